// round 6
// baseline (speedup 1.0000x reference)
#include <cuda_runtime.h>
#include <cuda_bf16.h>
#include <cstdint>
#include <cstddef>

#define DIM   4096
#define H3    12288
#define FFN_D 16384
#define NT    2048      // total tokens = 2*1024
#define LR    16        // lora rank
#define SEQ   1024
#define NH    32
#define HD    128

// ---------------- scratch (device globals; no allocations allowed) ----------
__device__ float g_ln1 [(size_t)NT * DIM];
__device__ float g_qkv [(size_t)NT * H3];
__device__ float g_attn[(size_t)NT * DIM];
__device__ float g_res2[(size_t)NT * DIM];
__device__ float g_ln2 [(size_t)NT * DIM];
__device__ float g_h1  [(size_t)NT * FFN_D];
__device__ float g_u   [(size_t)NT * LR];

// int8 two-level planes
#define WOFF_QKV 0
#define WOFF_OUT 50331648u
#define WOFF_FC1 67108864u
#define WOFF_FC2 134217728u
#define W_TOTAL  201326592u
__device__ int8_t g_Wq1[W_TOTAL];
__device__ int8_t g_Wq2[W_TOTAL];
__device__ int8_t g_Aq1[(size_t)NT * FFN_D];
__device__ int8_t g_Aq2[(size_t)NT * FFN_D];
// weight row scales: qkv[0,12288) out[12288,16384) fc1[16384,32768) fc2[32768,36864)
#define SQKV 0
#define SOUT 12288
#define SFC1 16384
#define SFC2 32768
__device__ float g_sW[36864];
__device__ float g_sA[NT];

// ================= helpers ===================================================
__device__ __forceinline__ uint32_t smem_u32(const void* p) {
    uint32_t a;
    asm("{ .reg .u64 t; cvta.to.shared.u64 t, %1; cvt.u32.u64 %0, t; }"
        : "=r"(a) : "l"(p));
    return a;
}
__device__ __forceinline__ void ldmx4(uint32_t* r, uint32_t addr) {
    asm volatile("ldmatrix.sync.aligned.m8n8.x4.shared.b16 {%0,%1,%2,%3}, [%4];"
                 : "=r"(r[0]), "=r"(r[1]), "=r"(r[2]), "=r"(r[3]) : "r"(addr));
}
__device__ __forceinline__ uint32_t lds32(uint32_t addr) {
    uint32_t v;
    asm volatile("ld.shared.b32 %0, [%1];" : "=r"(v) : "r"(addr));
    return v;
}
__device__ __forceinline__ void imma16832(int* d, const uint32_t* a,
                                          uint32_t b0, uint32_t b1) {
    asm volatile("mma.sync.aligned.m16n8k32.row.col.s32.s8.s8.s32 "
                 "{%0,%1,%2,%3}, {%4,%5,%6,%7}, {%8,%9}, {%0,%1,%2,%3};"
                 : "+r"(d[0]), "+r"(d[1]), "+r"(d[2]), "+r"(d[3])
                 : "r"(a[0]), "r"(a[1]), "r"(a[2]), "r"(a[3]),
                   "r"(b0), "r"(b1));
}
__device__ __forceinline__ void cpa16(uint32_t d, const void* s) {
    asm volatile("cp.async.ca.shared.global [%0], [%1], 16;"
                 :: "r"(d), "l"(s) : "memory");
}
__device__ __forceinline__ void cpa_commit() {
    asm volatile("cp.async.commit_group;" ::: "memory");
}

// ================= per-row two-level int8 quantization ========================
// x ~= s*(q1 + q2/128),  s = rowmax/127,  |q2| <= 64, residual <= s/256.
__global__ void quant_rows(const float* __restrict__ src,
                           int8_t* __restrict__ q1, int8_t* __restrict__ q2,
                           float* __restrict__ sc, int K) {
    int row = blockIdx.x;
    const float4* xr = (const float4*)(src + (size_t)row * K);
    int tid = threadIdx.x;
    int n4 = K >> 2;
    float mx = 0.f;
    for (int i = tid; i < n4; i += 256) {
        float4 v = xr[i];
        mx = fmaxf(mx, fmaxf(fmaxf(fabsf(v.x), fabsf(v.y)),
                             fmaxf(fabsf(v.z), fabsf(v.w))));
    }
    __shared__ float red[8];
    #pragma unroll
    for (int o = 16; o; o >>= 1) mx = fmaxf(mx, __shfl_xor_sync(0xffffffffu, mx, o));
    if (!(tid & 31)) red[tid >> 5] = mx;
    __syncthreads();
    mx = 0.f;
    #pragma unroll
    for (int w = 0; w < 8; w++) mx = fmaxf(mx, red[w]);
    float s1, inv1, inv2;
    if (mx > 1e-30f) { s1 = mx * (1.f / 127.f); inv1 = 127.f / mx; inv2 = inv1 * 128.f; }
    else             { s1 = 0.f; inv1 = 0.f; inv2 = 0.f; }
    if (tid == 0) sc[row] = s1;
    char4* o1 = (char4*)(q1 + (size_t)row * K);
    char4* o2 = (char4*)(q2 + (size_t)row * K);
    for (int i = tid; i < n4; i += 256) {
        float4 v = xr[i];
        float a0 = rintf(v.x * inv1), a1 = rintf(v.y * inv1);
        float a2 = rintf(v.z * inv1), a3 = rintf(v.w * inv1);
        float r0 = (v.x - a0 * s1) * inv2, r1 = (v.y - a1 * s1) * inv2;
        float r2 = (v.z - a2 * s1) * inv2, r3 = (v.w - a3 * s1) * inv2;
        char4 c1, c2;
        c1.x = (char)(int)a0; c1.y = (char)(int)a1;
        c1.z = (char)(int)a2; c1.w = (char)(int)a3;
        c2.x = (char)(int)rintf(r0); c2.y = (char)(int)rintf(r1);
        c2.z = (char)(int)rintf(r2); c2.w = (char)(int)rintf(r3);
        o1[i] = c1;
        o2[i] = c2;
    }
}

// ================= int8 tensor-core GEMM (two-level, 3-term) ==================
// C[m,n] = sA[m]*sW[n]*(main + cross/128) + bias[n]
//          + sum_r u[m,r]*Bl[map[m],n,r] (+ resid) (relu?)
// Block 128x128, k-chunk 32, 8 warps (2m x 4n), warp tile 64x32, mma m16n8k32.
#define BM 128
#define BN 128
#define RB 48                          // smem row stride bytes (32 data + 16 pad)
#define PLANE_I (128 * RB)             // 6144 B per plane
#define STAGE_I (4 * PLANE_I)          // Aq1 | Aq2 | Wq1 | Wq2 = 24576
#define SOFF_BIAS  128                 // 128 floats
#define SOFF_SW    640                 // 128 floats (weight row scales)
#define SOFF_STAGE 1280
#define SMEM_G (SOFF_STAGE + 65536)    // lora-B slice (64KB) dominates stages (48KB)

__device__ __forceinline__ float dot16(const float* u, const float* b) {
    float s = 0.f;
    #pragma unroll
    for (int r = 0; r < 16; r++) s = fmaf(u[r], b[r], s);
    return s;
}

__device__ __forceinline__ void issue_chunk(
        const int8_t* __restrict__ Aq1, const int8_t* __restrict__ Aq2,
        const int8_t* __restrict__ Wq1, const int8_t* __restrict__ Wq2,
        int m0, int n0, int K, int c, uint32_t sdst, int tid) {
    int k0 = c * 32;
    int row = tid >> 1, seg = tid & 1;
    uint32_t d = sdst + row * RB + seg * 16;
    size_t ao = (size_t)(m0 + row) * K + k0 + seg * 16;
    size_t wo = (size_t)(n0 + row) * K + k0 + seg * 16;
    cpa16(d,               Aq1 + ao);
    cpa16(d + PLANE_I,     Aq2 + ao);
    cpa16(d + 2 * PLANE_I, Wq1 + wo);
    cpa16(d + 3 * PLANE_I, Wq2 + wo);
    cpa_commit();
}

__global__ void __launch_bounds__(256, 1)
tc_gemm(const int8_t* __restrict__ Aq1, const int8_t* __restrict__ Aq2,
        const int8_t* __restrict__ Wq1, const int8_t* __restrict__ Wq2,
        const float* __restrict__ sA, const float* __restrict__ sW,
        const float* __restrict__ bias, const float* __restrict__ u,
        const float* __restrict__ Bl, const int* __restrict__ map,
        const float* __restrict__ resid, float* __restrict__ C,
        int N, int K, int relu) {
    extern __shared__ __align__(1024) char smem[];
    uint32_t sbase = smem_u32(smem);
    int tid = threadIdx.x;
    int lane = tid & 31, warp = tid >> 5;
    int wm = warp >> 2, wn = warp & 3;
    int n0 = blockIdx.x * BN;
    int m0 = blockIdx.y * BM;

    if (tid < BN) {
        ((float*)(smem + SOFF_BIAS))[tid] = bias[n0 + tid];
        ((float*)(smem + SOFF_SW))[tid]   = sW[n0 + tid];
    }

    int mainA[4][4][4], crossA[4][4][4];
    #pragma unroll
    for (int f = 0; f < 4; f++)
        #pragma unroll
        for (int g = 0; g < 4; g++)
            #pragma unroll
            for (int e = 0; e < 4; e++) { mainA[f][g][e] = 0; crossA[f][g][e] = 0; }

    int nCh = K >> 5;
    issue_chunk(Aq1, Aq2, Wq1, Wq2, m0, n0, K, 0, sbase + SOFF_STAGE, tid);
    issue_chunk(Aq1, Aq2, Wq1, Wq2, m0, n0, K, 1, sbase + SOFF_STAGE + STAGE_I, tid);

    // ldmatrix lane addressing: tile=lane>>3 (0..3), row-in-tile=lane&7
    uint32_t aoffL = (uint32_t)((((lane >> 3) & 1) * 8 + (lane & 7)) * RB
                               + (lane >> 4) * 16);
    int grp = lane >> 2, tig = lane & 3;
    uint32_t boffL = (uint32_t)(grp * RB + tig * 4);

    for (int c = 0; c < nCh; c++) {
        int cur = c & 1;
        if (c + 1 < nCh)
            asm volatile("cp.async.wait_group 1;" ::: "memory");
        else
            asm volatile("cp.async.wait_group 0;" ::: "memory");
        __syncthreads();

        uint32_t base = sbase + SOFF_STAGE + cur * STAGE_I;
        uint32_t aq1[4][4], aq2[4][4];
        #pragma unroll
        for (int f = 0; f < 4; f++) {
            uint32_t ad = base + (wm * 64 + f * 16) * RB + aoffL;
            ldmx4(aq1[f], ad);
            ldmx4(aq2[f], ad + PLANE_I);
        }
        #pragma unroll
        for (int g = 0; g < 4; g++) {
            uint32_t bd = base + 2 * PLANE_I + (wn * 32 + g * 8) * RB + boffL;
            uint32_t b10 = lds32(bd),            b11 = lds32(bd + 16);
            uint32_t b20 = lds32(bd + PLANE_I),  b21 = lds32(bd + PLANE_I + 16);
            #pragma unroll
            for (int f = 0; f < 4; f++) {
                imma16832(mainA[f][g],  aq1[f], b10, b11);
                imma16832(crossA[f][g], aq1[f], b20, b21);
                imma16832(crossA[f][g], aq2[f], b10, b11);
            }
        }
        __syncthreads();
        if (c + 2 < nCh)
            issue_chunk(Aq1, Aq2, Wq1, Wq2, m0, n0, K, c + 2,
                        sbase + SOFF_STAGE + cur * STAGE_I, tid);
    }

    // ---- stage lora-B slice into SMEM (reuses stage area) ----
    float* Bs = (float*)(smem + SOFF_STAGE);
    for (int i = tid; i < 4096; i += 256) {   // 8 adapters * 128 n * 4 float4
        int a   = i >> 9;
        int rem = i & 511;
        int nl  = rem >> 2;
        int sg  = rem & 3;
        float4 v = *(const float4*)(Bl + ((size_t)a * N + n0 + nl) * LR + sg * 4);
        *(float4*)(Bs + ((size_t)((a << 7) + nl)) * LR + sg * 4) = v;
    }
    __syncthreads();

    const float* biasS = (const float*)(smem + SOFF_BIAS);
    const float* sWS   = (const float*)(smem + SOFF_SW);
    #pragma unroll
    for (int f = 0; f < 4; f++) {
        int r0 = m0 + wm * 64 + f * 16 + grp;
        int r1 = r0 + 8;
        int a0 = map[r0], a1 = map[r1];
        float sa0 = sA[r0], sa1 = sA[r1];
        float u0[16], u1[16];
        {
            const float4* p0 = (const float4*)(u + (size_t)r0 * LR);
            const float4* p1 = (const float4*)(u + (size_t)r1 * LR);
            #pragma unroll
            for (int q = 0; q < 4; q++) {
                float4 v0 = p0[q], v1 = p1[q];
                u0[q*4+0]=v0.x; u0[q*4+1]=v0.y; u0[q*4+2]=v0.z; u0[q*4+3]=v0.w;
                u1[q*4+0]=v1.x; u1[q*4+1]=v1.y; u1[q*4+2]=v1.z; u1[q*4+3]=v1.w;
            }
        }
        #pragma unroll
        for (int g = 0; g < 4; g++) {
            int nl = wn * 32 + g * 8 + tig * 2;
            const float inv128 = 0.0078125f;
            float w0 = sWS[nl], w1 = sWS[nl + 1];
            float v00 = sa0 * w0 * ((float)mainA[f][g][0] + (float)crossA[f][g][0] * inv128)
                      + biasS[nl]     + dot16(u0, Bs + ((size_t)((a0 << 7) + nl)) * LR);
            float v01 = sa0 * w1 * ((float)mainA[f][g][1] + (float)crossA[f][g][1] * inv128)
                      + biasS[nl + 1] + dot16(u0, Bs + ((size_t)((a0 << 7) + nl + 1)) * LR);
            float v10 = sa1 * w0 * ((float)mainA[f][g][2] + (float)crossA[f][g][2] * inv128)
                      + biasS[nl]     + dot16(u1, Bs + ((size_t)((a1 << 7) + nl)) * LR);
            float v11 = sa1 * w1 * ((float)mainA[f][g][3] + (float)crossA[f][g][3] * inv128)
                      + biasS[nl + 1] + dot16(u1, Bs + ((size_t)((a1 << 7) + nl + 1)) * LR);
            size_t o0 = (size_t)r0 * N + n0 + nl;
            size_t o1 = (size_t)r1 * N + n0 + nl;
            if (resid) {
                float2 q0 = *(const float2*)(resid + o0);
                float2 q1 = *(const float2*)(resid + o1);
                v00 += q0.x; v01 += q0.y; v10 += q1.x; v11 += q1.y;
            }
            if (relu) {
                v00 = fmaxf(v00, 0.f); v01 = fmaxf(v01, 0.f);
                v10 = fmaxf(v10, 0.f); v11 = fmaxf(v11, 0.f);
            }
            *(float2*)(C + o0) = make_float2(v00, v01);
            *(float2*)(C + o1) = make_float2(v10, v11);
        }
    }
}

// ---------------- LayerNorm: one block per row --------------------------------
__global__ void ln_kernel(const float* __restrict__ x, const float* __restrict__ g,
                          const float* __restrict__ b, float* __restrict__ out) {
    int row = blockIdx.x;
    const float* xr = x + (size_t)row * DIM;
    float* orow = out + (size_t)row * DIM;
    int tid = threadIdx.x;
    float s = 0.f, s2 = 0.f;
    for (int i = tid; i < DIM; i += 256) { float v = xr[i]; s += v; s2 += v * v; }
    __shared__ float rs[8], rs2[8];
    #pragma unroll
    for (int o = 16; o; o >>= 1) {
        s  += __shfl_xor_sync(0xffffffffu, s,  o);
        s2 += __shfl_xor_sync(0xffffffffu, s2, o);
    }
    int warp = tid >> 5, lane = tid & 31;
    if (!lane) { rs[warp] = s; rs2[warp] = s2; }
    __syncthreads();
    s = 0.f; s2 = 0.f;
    #pragma unroll
    for (int w = 0; w < 8; w++) { s += rs[w]; s2 += rs2[w]; }
    float mean = s * (1.f / DIM);
    float var  = s2 * (1.f / DIM) - mean * mean;
    float rstd = rsqrtf(var + 1e-5f);
    for (int i = tid; i < DIM; i += 256) {
        float v = xr[i];
        orow[i] = (v - mean) * rstd * g[i] + b[i];
    }
}

// ---------------- LoRA "u" = x @ A^T  (per-token adapter) ---------------------
__global__ void lora_u_kernel(const float* __restrict__ x, const float* __restrict__ A,
                              const int* __restrict__ map, float* __restrict__ u, int K) {
    int t = blockIdx.x;
    int a = map[t];
    const float* xr = x + (size_t)t * K;
    int warp = threadIdx.x >> 5, lane = threadIdx.x & 31;
    #pragma unroll
    for (int rr = 0; rr < 2; rr++) {
        int r = warp * 2 + rr;
        const float* ar = A + ((size_t)a * LR + r) * K;
        float s = 0.f;
        for (int i = lane; i < K; i += 32) s += xr[i] * ar[i];
        #pragma unroll
        for (int o = 16; o; o >>= 1) s += __shfl_xor_sync(0xffffffffu, s, o);
        if (!lane) u[t * LR + r] = s;
    }
}

// ---------------- causal attention: q-tiled (TQ=8), scores in SMEM ------------
#define TQ 8
__global__ void attn2_kernel(const float* __restrict__ qkv, float* __restrict__ out) {
    int qt = blockIdx.x, h = blockIdx.y, bb = blockIdx.z;
    __shared__ float qs[TQ][HD];
    __shared__ float sc[TQ][SEQ];
    __shared__ float sinv[TQ];
    const size_t base = (size_t)bb * SEQ * H3;
    int tid = threadIdx.x, lane = tid & 31, warp = tid >> 5;
    int q0 = qt * TQ;

    for (int i = tid; i < TQ * HD; i += 256) {
        int r = i >> 7, d = i & 127;
        qs[r][d] = qkv[base + (size_t)(q0 + r) * H3 + h * HD + d];
    }
    __syncthreads();

    int nkmax = q0 + TQ;
    const float scale = 0.08838834764831845f;   // 128^-0.5
    for (int j = warp; j < nkmax; j += 8) {
        const float4 kv = *(const float4*)(qkv + base + (size_t)j * H3 + DIM
                                           + h * HD + lane * 4);
        float part[TQ];
        #pragma unroll
        for (int i = 0; i < TQ; i++) {
            float4 qv = *(const float4*)&qs[i][lane * 4];
            part[i] = qv.x * kv.x + qv.y * kv.y + qv.z * kv.z + qv.w * kv.w;
        }
        #pragma unroll
        for (int o = 16; o; o >>= 1)
            #pragma unroll
            for (int i = 0; i < TQ; i++)
                part[i] += __shfl_xor_sync(0xffffffffu, part[i], o);
        #pragma unroll
        for (int i = 0; i < TQ; i++)
            if (lane == i)
                sc[i][j] = (j <= q0 + i) ? part[i] * scale : -1e30f;
    }
    __syncthreads();

    {
        int i = warp;
        int nk = q0 + i + 1;
        float mx = -1e30f;
        for (int j = lane; j < nk; j += 32) mx = fmaxf(mx, sc[i][j]);
        #pragma unroll
        for (int o = 16; o; o >>= 1)
            mx = fmaxf(mx, __shfl_xor_sync(0xffffffffu, mx, o));
        float sum = 0.f;
        for (int j = lane; j < nk; j += 32) {
            float e = __expf(sc[i][j] - mx);
            sc[i][j] = e;
            sum += e;
        }
        #pragma unroll
        for (int o = 16; o; o >>= 1) sum += __shfl_xor_sync(0xffffffffu, sum, o);
        if (!lane) sinv[i] = 1.f / sum;
    }
    __syncthreads();

    {
        int i = warp;
        int nk = q0 + i + 1;
        float4 acc = make_float4(0.f, 0.f, 0.f, 0.f);
        const float* vb = qkv + base + 2 * DIM + h * HD + lane * 4;
        int j = 0;
        for (; j + 2 <= nk; j += 2) {
            float p0 = sc[i][j], p1 = sc[i][j + 1];
            float4 v0 = *(const float4*)(vb + (size_t)j * H3);
            float4 v1 = *(const float4*)(vb + (size_t)(j + 1) * H3);
            acc.x += p0 * v0.x + p1 * v1.x;
            acc.y += p0 * v0.y + p1 * v1.y;
            acc.z += p0 * v0.z + p1 * v1.z;
            acc.w += p0 * v0.w + p1 * v1.w;
        }
        if (j < nk) {
            float p0 = sc[i][j];
            float4 v0 = *(const float4*)(vb + (size_t)j * H3);
            acc.x += p0 * v0.x; acc.y += p0 * v0.y;
            acc.z += p0 * v0.z; acc.w += p0 * v0.w;
        }
        float inv = sinv[i];
        acc.x *= inv; acc.y *= inv; acc.z *= inv; acc.w *= inv;
        *(float4*)(out + ((size_t)bb * SEQ + q0 + i) * DIM + h * HD + lane * 4) = acc;
    }
}

// ---------------- launch ------------------------------------------------------
extern "C" void kernel_launch(void* const* d_in, const int* in_sizes, int n_in,
                              void* d_out, int out_size) {
    const float* x    = (const float*)d_in[0];
    const int*   map  = (const int*)  d_in[1];
    const float* Wqkv = (const float*)d_in[2];
    const float* bqkv = (const float*)d_in[3];
    const float* Wout = (const float*)d_in[4];
    const float* bout = (const float*)d_in[5];
    const float* Wfc1 = (const float*)d_in[6];
    const float* bfc1 = (const float*)d_in[7];
    const float* Wfc2 = (const float*)d_in[8];
    const float* bfc2 = (const float*)d_in[9];
    const float* ln1g = (const float*)d_in[10];
    const float* ln1b = (const float*)d_in[11];
    const float* ln2g = (const float*)d_in[12];
    const float* ln2b = (const float*)d_in[13];
    const float* Aqkv = (const float*)d_in[14];
    const float* Bqkv = (const float*)d_in[15];
    const float* Aout = (const float*)d_in[16];
    const float* Bout = (const float*)d_in[17];
    const float* Afc1 = (const float*)d_in[18];
    const float* Bfc1 = (const float*)d_in[19];
    const float* Afc2 = (const float*)d_in[20];
    const float* Bfc2 = (const float*)d_in[21];
    float* out = (float*)d_out;

    float *p_ln1, *p_qkv, *p_attn, *p_res2, *p_ln2, *p_h1, *p_u, *p_sW, *p_sA;
    int8_t *p_Wq1, *p_Wq2, *p_Aq1, *p_Aq2;
    cudaGetSymbolAddress((void**)&p_ln1,  g_ln1);
    cudaGetSymbolAddress((void**)&p_qkv,  g_qkv);
    cudaGetSymbolAddress((void**)&p_attn, g_attn);
    cudaGetSymbolAddress((void**)&p_res2, g_res2);
    cudaGetSymbolAddress((void**)&p_ln2,  g_ln2);
    cudaGetSymbolAddress((void**)&p_h1,   g_h1);
    cudaGetSymbolAddress((void**)&p_u,    g_u);
    cudaGetSymbolAddress((void**)&p_Wq1,  g_Wq1);
    cudaGetSymbolAddress((void**)&p_Wq2,  g_Wq2);
    cudaGetSymbolAddress((void**)&p_Aq1,  g_Aq1);
    cudaGetSymbolAddress((void**)&p_Aq2,  g_Aq2);
    cudaGetSymbolAddress((void**)&p_sW,   g_sW);
    cudaGetSymbolAddress((void**)&p_sA,   g_sA);

    cudaFuncSetAttribute(tc_gemm, cudaFuncAttributeMaxDynamicSharedMemorySize,
                         SMEM_G);

    // ---- quantize all weights (per-row, two-level int8) ----
    quant_rows<<<H3,    256>>>(Wqkv, p_Wq1 + WOFF_QKV, p_Wq2 + WOFF_QKV, p_sW + SQKV, DIM);
    quant_rows<<<DIM,   256>>>(Wout, p_Wq1 + WOFF_OUT, p_Wq2 + WOFF_OUT, p_sW + SOUT, DIM);
    quant_rows<<<FFN_D, 256>>>(Wfc1, p_Wq1 + WOFF_FC1, p_Wq2 + WOFF_FC1, p_sW + SFC1, DIM);
    quant_rows<<<DIM,   256>>>(Wfc2, p_Wq1 + WOFF_FC2, p_Wq2 + WOFF_FC2, p_sW + SFC2, FFN_D);

    // ---- attention block ----
    ln_kernel<<<NT, 256>>>(x, ln1g, ln1b, p_ln1);
    lora_u_kernel<<<NT, 256>>>(p_ln1, Aqkv, map, p_u, DIM);
    quant_rows<<<NT, 256>>>(p_ln1, p_Aq1, p_Aq2, p_sA, DIM);
    tc_gemm<<<dim3(H3 / BN, NT / BM), 256, SMEM_G>>>(
        p_Aq1, p_Aq2, p_Wq1 + WOFF_QKV, p_Wq2 + WOFF_QKV, p_sA, p_sW + SQKV,
        bqkv, p_u, Bqkv, map, nullptr, p_qkv, H3, DIM, 0);
    attn2_kernel<<<dim3(SEQ / TQ, NH, 2), 256>>>(p_qkv, p_attn);
    lora_u_kernel<<<NT, 256>>>(p_attn, Aout, map, p_u, DIM);
    quant_rows<<<NT, 256>>>(p_attn, p_Aq1, p_Aq2, p_sA, DIM);
    tc_gemm<<<dim3(DIM / BN, NT / BM), 256, SMEM_G>>>(
        p_Aq1, p_Aq2, p_Wq1 + WOFF_OUT, p_Wq2 + WOFF_OUT, p_sA, p_sW + SOUT,
        bout, p_u, Bout, map, x, p_res2, DIM, DIM, 0);
    // ---- FFN block ----
    ln_kernel<<<NT, 256>>>(p_res2, ln2g, ln2b, p_ln2);
    lora_u_kernel<<<NT, 256>>>(p_ln2, Afc1, map, p_u, DIM);
    quant_rows<<<NT, 256>>>(p_ln2, p_Aq1, p_Aq2, p_sA, DIM);
    tc_gemm<<<dim3(FFN_D / BN, NT / BM), 256, SMEM_G>>>(
        p_Aq1, p_Aq2, p_Wq1 + WOFF_FC1, p_Wq2 + WOFF_FC1, p_sA, p_sW + SFC1,
        bfc1, p_u, Bfc1, map, nullptr, p_h1, FFN_D, DIM, 1);
    lora_u_kernel<<<NT, 256>>>(p_h1, Afc2, map, p_u, FFN_D);
    quant_rows<<<NT, 256>>>(p_h1, p_Aq1, p_Aq2, p_sA, FFN_D);
    tc_gemm<<<dim3(DIM / BN, NT / BM), 256, SMEM_G>>>(
        p_Aq1, p_Aq2, p_Wq1 + WOFF_FC2, p_Wq2 + WOFF_FC2, p_sA, p_sW + SFC2,
        bfc2, p_u, Bfc2, map, p_res2, out, DIM, FFN_D, 0);
}

// round 8
// speedup vs baseline: 2.2964x; 2.2964x over previous
#include <cuda_runtime.h>
#include <cuda_bf16.h>
#include <cstdint>
#include <cstddef>

#define DIM   4096
#define H3    12288
#define FFN_D 16384
#define NT    2048      // total tokens = 2*1024
#define LR    16        // lora rank
#define SEQ   1024
#define NH    32
#define HD    128

// ---------------- scratch (device globals; no allocations allowed) ----------
__device__ float g_qkv [(size_t)NT * H3];
__device__ float g_attn[(size_t)NT * DIM];
__device__ float g_res2[(size_t)NT * DIM];
__device__ float g_h1  [(size_t)NT * FFN_D];
__device__ float g_u   [(size_t)NT * LR];

// split-bf16 weight planes
#define WOFF_QKV 0
#define WOFF_OUT 50331648u
#define WOFF_FC1 67108864u
#define WOFF_FC2 134217728u
#define W_TOTAL  201326592u
__device__ __nv_bfloat16 g_Whi[W_TOTAL];
__device__ __nv_bfloat16 g_Wlo[W_TOTAL];
// activation planes: S = [NT,4096] rows, L = [NT,16384] rows
__device__ __nv_bfloat16 g_AhiS[(size_t)NT * DIM];
__device__ __nv_bfloat16 g_AloS[(size_t)NT * DIM];
__device__ __nv_bfloat16 g_AhiL[(size_t)NT * FFN_D];
__device__ __nv_bfloat16 g_AloL[(size_t)NT * FFN_D];

// ================= helpers ===================================================
__device__ __forceinline__ uint32_t smem_u32(const void* p) {
    uint32_t a;
    asm("{ .reg .u64 t; cvta.to.shared.u64 t, %1; cvt.u32.u64 %0, t; }"
        : "=r"(a) : "l"(p));
    return a;
}
__device__ __forceinline__ void ldmx4(uint32_t* r, uint32_t addr) {
    asm volatile("ldmatrix.sync.aligned.m8n8.x4.shared.b16 {%0,%1,%2,%3}, [%4];"
                 : "=r"(r[0]), "=r"(r[1]), "=r"(r[2]), "=r"(r[3]) : "r"(addr));
}
__device__ __forceinline__ uint32_t lds32(uint32_t addr) {
    uint32_t v;
    asm volatile("ld.shared.b32 %0, [%1];" : "=r"(v) : "r"(addr));
    return v;
}
__device__ __forceinline__ void mma16816(float* d, const uint32_t* a,
                                         uint32_t b0, uint32_t b1) {
    asm volatile("mma.sync.aligned.m16n8k16.row.col.f32.bf16.bf16.f32 "
                 "{%0,%1,%2,%3}, {%4,%5,%6,%7}, {%8,%9}, {%0,%1,%2,%3};"
                 : "+f"(d[0]), "+f"(d[1]), "+f"(d[2]), "+f"(d[3])
                 : "r"(a[0]), "r"(a[1]), "r"(a[2]), "r"(a[3]),
                   "r"(b0), "r"(b1));
}
__device__ __forceinline__ void cpa16(uint32_t d, const void* s) {
    asm volatile("cp.async.ca.shared.global [%0], [%1], 16;"
                 :: "r"(d), "l"(s) : "memory");
}
__device__ __forceinline__ void cpa_commit() {
    asm volatile("cp.async.commit_group;" ::: "memory");
}
// pack two floats into (hi,lo) bf16 planes
__device__ __forceinline__ void split2(float a, float b, __nv_bfloat16* hi,
                                       __nv_bfloat16* lo) {
    __nv_bfloat16 h0 = __float2bfloat16(a), h1 = __float2bfloat16(b);
    float l0 = a - __bfloat162float(h0), l1 = b - __bfloat162float(h1);
    __nv_bfloat162 hv(h0, h1);
    __nv_bfloat162 lv(__float2bfloat16(l0), __float2bfloat16(l1));
    *(__nv_bfloat162*)hi = hv;
    *(__nv_bfloat162*)lo = lv;
}

// ================= fp32 -> (hi, lo) bf16 split (weights) ======================
__global__ void cvt_split(const float* __restrict__ src,
                          __nv_bfloat16* __restrict__ hi,
                          __nv_bfloat16* __restrict__ lo, size_t n4) {
    size_t i = (size_t)blockIdx.x * blockDim.x + threadIdx.x;
    size_t stride = (size_t)gridDim.x * blockDim.x;
    for (; i < n4; i += stride) {
        float4 v = ((const float4*)src)[i];
        split2(v.x, v.y, hi + i * 4, lo + i * 4);
        split2(v.z, v.w, hi + i * 4 + 2, lo + i * 4 + 2);
    }
}

// ================= fused LayerNorm + plane split + lora-u =====================
__global__ void ln_fused(const float* __restrict__ x, const float* __restrict__ g,
                         const float* __restrict__ b, const float* __restrict__ A,
                         const int* __restrict__ map,
                         __nv_bfloat16* __restrict__ hi, __nv_bfloat16* __restrict__ lo,
                         float* __restrict__ u) {
    __shared__ float row[DIM];
    __shared__ float rs[8], rs2[8];
    int t = blockIdx.x;
    int tid = threadIdx.x, lane = tid & 31, warp = tid >> 5;
    const float4* x4 = (const float4*)(x + (size_t)t * DIM);
    float4* row4 = (float4*)row;
    float s = 0.f, s2 = 0.f;
    #pragma unroll
    for (int p = 0; p < 4; p++) {
        int i = tid + p * 256;
        float4 v = x4[i];
        row4[i] = v;
        s += v.x + v.y + v.z + v.w;
        s2 += v.x * v.x + v.y * v.y + v.z * v.z + v.w * v.w;
    }
    #pragma unroll
    for (int o = 16; o; o >>= 1) {
        s  += __shfl_xor_sync(0xffffffffu, s,  o);
        s2 += __shfl_xor_sync(0xffffffffu, s2, o);
    }
    if (!lane) { rs[warp] = s; rs2[warp] = s2; }
    __syncthreads();
    s = 0.f; s2 = 0.f;
    #pragma unroll
    for (int w = 0; w < 8; w++) { s += rs[w]; s2 += rs2[w]; }
    float mean = s * (1.f / DIM);
    float var  = s2 * (1.f / DIM) - mean * mean;
    float rstd = rsqrtf(var + 1e-5f);
    __nv_bfloat16* hr = hi + (size_t)t * DIM;
    __nv_bfloat16* lr = lo + (size_t)t * DIM;
    const float4* g4 = (const float4*)g;
    const float4* b4 = (const float4*)b;
    #pragma unroll
    for (int p = 0; p < 4; p++) {
        int i = tid + p * 256;
        float4 v = row4[i], gv = g4[i], bv = b4[i];
        float4 nv;
        nv.x = (v.x - mean) * rstd * gv.x + bv.x;
        nv.y = (v.y - mean) * rstd * gv.y + bv.y;
        nv.z = (v.z - mean) * rstd * gv.z + bv.z;
        nv.w = (v.w - mean) * rstd * gv.w + bv.w;
        split2(nv.x, nv.y, hr + i * 4, lr + i * 4);
        split2(nv.z, nv.w, hr + i * 4 + 2, lr + i * 4 + 2);
        row4[i] = nv;
    }
    __syncthreads();
    // lora-u: warp w does ranks 2w, 2w+1
    int a = map[t];
    #pragma unroll
    for (int rr = 0; rr < 2; rr++) {
        int r = warp * 2 + rr;
        const float4* ar = (const float4*)(A + ((size_t)a * LR + r) * DIM);
        float acc = 0.f;
        #pragma unroll
        for (int p = 0; p < 32; p++) {
            int i = lane + p * 32;
            float4 av = ar[i], xv = row4[i];
            acc += av.x * xv.x + av.y * xv.y + av.z * xv.z + av.w * xv.w;
        }
        #pragma unroll
        for (int o = 16; o; o >>= 1) acc += __shfl_xor_sync(0xffffffffu, acc, o);
        if (!lane) u[t * LR + r] = acc;
    }
}

// ================= lora-u with smem-staged row ================================
__global__ void lora_u_smem(const float* __restrict__ x, const float* __restrict__ A,
                            const int* __restrict__ map, float* __restrict__ u, int K) {
    extern __shared__ float srow[];
    int t = blockIdx.x;
    int tid = threadIdx.x, lane = tid & 31, warp = tid >> 5;
    const float4* x4 = (const float4*)(x + (size_t)t * K);
    float4* s4 = (float4*)srow;
    int n4 = K >> 2;
    for (int i = tid; i < n4; i += 256) s4[i] = x4[i];
    __syncthreads();
    int a = map[t];
    #pragma unroll
    for (int rr = 0; rr < 2; rr++) {
        int r = warp * 2 + rr;
        const float4* ar = (const float4*)(A + ((size_t)a * LR + r) * K);
        float acc = 0.f;
        for (int i = lane; i < n4; i += 32) {
            float4 av = ar[i], xv = s4[i];
            acc += av.x * xv.x + av.y * xv.y + av.z * xv.z + av.w * xv.w;
        }
        #pragma unroll
        for (int o = 16; o; o >>= 1) acc += __shfl_xor_sync(0xffffffffu, acc, o);
        if (!lane) u[t * LR + r] = acc;
    }
}

// ================= tensor-core GEMM (pre-split bf16, 3-term) ==================
#define BM 128
#define BN 128
#define RSTR 40
#define PLANE (128 * RSTR * 2)
#define STAGE_B (4 * PLANE)
#define SOFF_BIAS  128
#define SOFF_STAGE 1024
#define SMEM_G (SOFF_STAGE + 2 * STAGE_B)

__device__ __forceinline__ float dot16(const float* u, const float* b) {
    float s = 0.f;
    #pragma unroll
    for (int r = 0; r < 16; r++) s = fmaf(u[r], b[r], s);
    return s;
}

__device__ __forceinline__ void issue_chunk(
        const __nv_bfloat16* __restrict__ Ahi, const __nv_bfloat16* __restrict__ Alo,
        const __nv_bfloat16* __restrict__ Whi, const __nv_bfloat16* __restrict__ Wlo,
        int m0, int n0, int K, int c, uint32_t sdst, int tid) {
    int k0 = c * 32;
    #pragma unroll
    for (int p = 0; p < 2; p++) {
        int idx = tid + p * 256;
        int row = idx >> 2, seg = idx & 3;
        uint32_t d = sdst + row * (RSTR * 2) + seg * 16;
        size_t ao = (size_t)(m0 + row) * K + k0 + seg * 8;
        size_t wo = (size_t)(n0 + row) * K + k0 + seg * 8;
        cpa16(d,             Ahi + ao);
        cpa16(d + PLANE,     Alo + ao);
        cpa16(d + 2 * PLANE, Whi + wo);
        cpa16(d + 3 * PLANE, Wlo + wo);
    }
    cpa_commit();
}

__global__ void __launch_bounds__(256, 2)
tc_gemm(const __nv_bfloat16* __restrict__ Ahi, const __nv_bfloat16* __restrict__ Alo,
        const __nv_bfloat16* __restrict__ Whi, const __nv_bfloat16* __restrict__ Wlo,
        const float* __restrict__ bias, const float* __restrict__ u,
        const float* __restrict__ Bl, const int* __restrict__ map,
        const float* __restrict__ resid, float* __restrict__ C,
        __nv_bfloat16* __restrict__ hiO, __nv_bfloat16* __restrict__ loO,
        int N, int K, int relu) {
    extern __shared__ __align__(1024) char smem[];
    uint32_t sbase = smem_u32(smem);
    int tid = threadIdx.x;
    int lane = tid & 31, warp = tid >> 5;
    int wm = warp >> 2, wn = warp & 3;
    int n0 = blockIdx.x * BN;
    int m0 = blockIdx.y * BM;

    if (tid < BN) ((float*)(smem + SOFF_BIAS))[tid] = bias[n0 + tid];

    float acc[4][4][4];
    #pragma unroll
    for (int f = 0; f < 4; f++)
        #pragma unroll
        for (int g = 0; g < 4; g++)
            #pragma unroll
            for (int e = 0; e < 4; e++) acc[f][g][e] = 0.f;

    int nCh = K >> 5;
    issue_chunk(Ahi, Alo, Whi, Wlo, m0, n0, K, 0, sbase + SOFF_STAGE, tid);
    issue_chunk(Ahi, Alo, Whi, Wlo, m0, n0, K, 1, sbase + SOFF_STAGE + STAGE_B, tid);

    int lane15 = lane & 15, laneHalf = lane >> 4;
    int grp = lane >> 2, tig = lane & 3;

    for (int c = 0; c < nCh; c++) {
        int cur = c & 1;
        if (c + 1 < nCh)
            asm volatile("cp.async.wait_group 1;" ::: "memory");
        else
            asm volatile("cp.async.wait_group 0;" ::: "memory");
        __syncthreads();

        uint32_t base = sbase + SOFF_STAGE + cur * STAGE_B;
        #pragma unroll
        for (int ks = 0; ks < 2; ks++) {
            uint32_t ahi[4][4], alo[4][4];
            int koffA = ks * 16 + laneHalf * 8;
            #pragma unroll
            for (int f = 0; f < 4; f++) {
                int row = wm * 64 + f * 16 + lane15;
                uint32_t ad = base + row * (RSTR * 2) + koffA * 2;
                ldmx4(ahi[f], ad);
                ldmx4(alo[f], ad + PLANE);
            }
            #pragma unroll
            for (int g = 0; g < 4; g++) {
                int n = wn * 32 + g * 8 + grp;
                uint32_t bd = base + 2 * PLANE + n * (RSTR * 2)
                            + (ks * 16 + tig * 2) * 2;
                uint32_t bh0 = lds32(bd), bh1 = lds32(bd + 16);
                uint32_t bl0 = lds32(bd + PLANE), bl1 = lds32(bd + PLANE + 16);
                #pragma unroll
                for (int f = 0; f < 4; f++) {
                    mma16816(acc[f][g], ahi[f], bh0, bh1);
                    mma16816(acc[f][g], ahi[f], bl0, bl1);
                    mma16816(acc[f][g], alo[f], bh0, bh1);
                }
            }
        }
        __syncthreads();
        if (c + 2 < nCh)
            issue_chunk(Ahi, Alo, Whi, Wlo, m0, n0, K, c + 2,
                        sbase + SOFF_STAGE + cur * STAGE_B, tid);
    }

    // ---- stage lora-B slice into SMEM ----
    float* Bs = (float*)(smem + SOFF_STAGE);
    for (int i = tid; i < 4096; i += 256) {
        int a   = i >> 9;
        int rem = i & 511;
        int nl  = rem >> 2;
        int sg  = rem & 3;
        float4 v = *(const float4*)(Bl + ((size_t)a * N + n0 + nl) * LR + sg * 4);
        *(float4*)(Bs + ((size_t)((a << 7) + nl)) * LR + sg * 4) = v;
    }
    __syncthreads();

    const float* biasS = (const float*)(smem + SOFF_BIAS);
    #pragma unroll
    for (int f = 0; f < 4; f++) {
        int r0 = m0 + wm * 64 + f * 16 + grp;
        int r1 = r0 + 8;
        int a0 = map[r0], a1 = map[r1];
        float u0[16], u1[16];
        {
            const float4* p0 = (const float4*)(u + (size_t)r0 * LR);
            const float4* p1 = (const float4*)(u + (size_t)r1 * LR);
            #pragma unroll
            for (int q = 0; q < 4; q++) {
                float4 v0 = p0[q], v1 = p1[q];
                u0[q*4+0]=v0.x; u0[q*4+1]=v0.y; u0[q*4+2]=v0.z; u0[q*4+3]=v0.w;
                u1[q*4+0]=v1.x; u1[q*4+1]=v1.y; u1[q*4+2]=v1.z; u1[q*4+3]=v1.w;
            }
        }
        #pragma unroll
        for (int g = 0; g < 4; g++) {
            int nl = wn * 32 + g * 8 + tig * 2;
            float v00 = acc[f][g][0] + biasS[nl]
                      + dot16(u0, Bs + ((size_t)((a0 << 7) + nl)) * LR);
            float v01 = acc[f][g][1] + biasS[nl + 1]
                      + dot16(u0, Bs + ((size_t)((a0 << 7) + nl + 1)) * LR);
            float v10 = acc[f][g][2] + biasS[nl]
                      + dot16(u1, Bs + ((size_t)((a1 << 7) + nl)) * LR);
            float v11 = acc[f][g][3] + biasS[nl + 1]
                      + dot16(u1, Bs + ((size_t)((a1 << 7) + nl + 1)) * LR);
            size_t o0 = (size_t)r0 * N + n0 + nl;
            size_t o1 = (size_t)r1 * N + n0 + nl;
            if (resid) {
                float2 q0 = *(const float2*)(resid + o0);
                float2 q1 = *(const float2*)(resid + o1);
                v00 += q0.x; v01 += q0.y; v10 += q1.x; v11 += q1.y;
            }
            if (relu) {
                v00 = fmaxf(v00, 0.f); v01 = fmaxf(v01, 0.f);
                v10 = fmaxf(v10, 0.f); v11 = fmaxf(v11, 0.f);
            }
            *(float2*)(C + o0) = make_float2(v00, v01);
            *(float2*)(C + o1) = make_float2(v10, v11);
            if (hiO) {
                split2(v00, v01, hiO + o0, loO + o0);
                split2(v10, v11, hiO + o1, loO + o1);
            }
        }
    }
}

// ================= attention: TQ=16, K-chunked smem, fused plane-out ==========
#define TQ 16
#define KCH 64
#define KSTR 33                       // k-chunk row stride in float4 (conflict-free)
// dyn smem layout (floats): qs[16*128] | sc[16*1024] | kch[64*132] | sinv[16]
#define AQ_OFF  0
#define ASC_OFF (16 * 128)
#define AK_OFF  (ASC_OFF + 16 * 1024)
#define ASV_OFF (AK_OFF + KCH * KSTR * 4)
#define ATTN_SMEM ((ASV_OFF + 16) * 4)

__global__ void __launch_bounds__(256, 1)
attn3_kernel(const float* __restrict__ qkv, float* __restrict__ out,
             __nv_bfloat16* __restrict__ hi, __nv_bfloat16* __restrict__ lo) {
    extern __shared__ float sm[];
    float4* qs4 = (float4*)(sm + AQ_OFF);
    float*  sc  = sm + ASC_OFF;
    float4* kc4 = (float4*)(sm + AK_OFF);
    float*  sinv = sm + ASV_OFF;
    int qt = blockIdx.x, h = blockIdx.y, bb = blockIdx.z;
    int q0 = qt * TQ;
    int tid = threadIdx.x, lane = tid & 31, warp = tid >> 5;
    const size_t base = (size_t)bb * SEQ * H3;
    const float scale = 0.08838834764831845f;

    // load q tile: 16 rows x 32 float4
    #pragma unroll
    for (int p = 0; p < 2; p++) {
        int i = tid + p * 256;
        int r = i >> 5, d4 = i & 31;
        qs4[r * 32 + d4] = *(const float4*)(qkv + base + (size_t)(q0 + r) * H3
                                            + h * HD + d4 * 4);
    }
    __syncthreads();

    int nkmax = q0 + TQ;
    int nch = (nkmax + KCH - 1) / KCH;
    int kkL = tid & 63, rbase = tid >> 6;
    for (int ch = 0; ch < nch; ch++) {
        int kb = ch * KCH;
        // cooperative K-chunk load (64 rows x 32 float4)
        #pragma unroll
        for (int p = 0; p < 8; p++) {
            int i = tid + p * 256;
            int r = i >> 5, d4 = i & 31;
            if (kb + r < nkmax)
                kc4[r * KSTR + d4] = *(const float4*)(qkv + base
                    + (size_t)(kb + r) * H3 + DIM + h * HD + d4 * 4);
        }
        __syncthreads();
        int kk = kb + kkL;
        if (kk < nkmax) {
            float part[4] = {0.f, 0.f, 0.f, 0.f};
            #pragma unroll 8
            for (int d4 = 0; d4 < 32; d4++) {
                float4 kv = kc4[kkL * KSTR + d4];
                #pragma unroll
                for (int rr = 0; rr < 4; rr++) {
                    float4 qv = qs4[(rbase * 4 + rr) * 32 + d4];
                    part[rr] += qv.x * kv.x + qv.y * kv.y + qv.z * kv.z + qv.w * kv.w;
                }
            }
            #pragma unroll
            for (int rr = 0; rr < 4; rr++)
                sc[(rbase * 4 + rr) * SEQ + kk] = part[rr] * scale;
        }
        __syncthreads();
    }

    // softmax: warp w handles rows w and w+8
    #pragma unroll
    for (int rr = 0; rr < 2; rr++) {
        int row = warp + rr * 8;
        int nk = q0 + row + 1;
        float* sr = sc + row * SEQ;
        float mx = -1e30f;
        for (int j = lane; j < nk; j += 32) mx = fmaxf(mx, sr[j]);
        #pragma unroll
        for (int o = 16; o; o >>= 1)
            mx = fmaxf(mx, __shfl_xor_sync(0xffffffffu, mx, o));
        float sum = 0.f;
        for (int j = lane; j < nk; j += 32) {
            float e = __expf(sr[j] - mx);
            sr[j] = e;
            sum += e;
        }
        #pragma unroll
        for (int o = 16; o; o >>= 1) sum += __shfl_xor_sync(0xffffffffu, sum, o);
        if (!lane) sinv[row] = 1.f / sum;
    }
    __syncthreads();

    // PV: warp rp owns rows rp and rp+8; lane owns 4 dims. V lines read
    // coalesced per warp; cross-warp re-reads hit L1.
    {
        int d4 = lane, rp = warp;
        const float* vb = qkv + base + 2 * DIM + h * HD + d4 * 4;
        #pragma unroll
        for (int rr = 0; rr < 2; rr++) {
            int row = rp + rr * 8;
            int nk = q0 + row + 1;
            const float* sr = sc + row * SEQ;
            float4 acc = make_float4(0.f, 0.f, 0.f, 0.f);
            int j = 0;
            for (; j + 2 <= nk; j += 2) {
                float p0 = sr[j], p1 = sr[j + 1];
                float4 v0 = *(const float4*)(vb + (size_t)j * H3);
                float4 v1 = *(const float4*)(vb + (size_t)(j + 1) * H3);
                acc.x += p0 * v0.x + p1 * v1.x;
                acc.y += p0 * v0.y + p1 * v1.y;
                acc.z += p0 * v0.z + p1 * v1.z;
                acc.w += p0 * v0.w + p1 * v1.w;
            }
            if (j < nk) {
                float p0 = sr[j];
                float4 v0 = *(const float4*)(vb + (size_t)j * H3);
                acc.x += p0 * v0.x; acc.y += p0 * v0.y;
                acc.z += p0 * v0.z; acc.w += p0 * v0.w;
            }
            float iv = sinv[row];
            acc.x *= iv; acc.y *= iv; acc.z *= iv; acc.w *= iv;
            size_t o = ((size_t)bb * SEQ + q0 + row) * DIM + h * HD + d4 * 4;
            *(float4*)(out + o) = acc;
            split2(acc.x, acc.y, hi + o, lo + o);
            split2(acc.z, acc.w, hi + o + 2, lo + o + 2);
        }
    }
}

// ---------------- launch ------------------------------------------------------
extern "C" void kernel_launch(void* const* d_in, const int* in_sizes, int n_in,
                              void* d_out, int out_size) {
    const float* x    = (const float*)d_in[0];
    const int*   map  = (const int*)  d_in[1];
    const float* Wqkv = (const float*)d_in[2];
    const float* bqkv = (const float*)d_in[3];
    const float* Wout = (const float*)d_in[4];
    const float* bout = (const float*)d_in[5];
    const float* Wfc1 = (const float*)d_in[6];
    const float* bfc1 = (const float*)d_in[7];
    const float* Wfc2 = (const float*)d_in[8];
    const float* bfc2 = (const float*)d_in[9];
    const float* ln1g = (const float*)d_in[10];
    const float* ln1b = (const float*)d_in[11];
    const float* ln2g = (const float*)d_in[12];
    const float* ln2b = (const float*)d_in[13];
    const float* Aqkv = (const float*)d_in[14];
    const float* Bqkv = (const float*)d_in[15];
    const float* Aout = (const float*)d_in[16];
    const float* Bout = (const float*)d_in[17];
    const float* Afc1 = (const float*)d_in[18];
    const float* Bfc1 = (const float*)d_in[19];
    const float* Afc2 = (const float*)d_in[20];
    const float* Bfc2 = (const float*)d_in[21];
    float* out = (float*)d_out;

    float *p_qkv, *p_attn, *p_res2, *p_h1, *p_u;
    __nv_bfloat16 *p_Whi, *p_Wlo, *p_AhiS, *p_AloS, *p_AhiL, *p_AloL;
    cudaGetSymbolAddress((void**)&p_qkv,  g_qkv);
    cudaGetSymbolAddress((void**)&p_attn, g_attn);
    cudaGetSymbolAddress((void**)&p_res2, g_res2);
    cudaGetSymbolAddress((void**)&p_h1,   g_h1);
    cudaGetSymbolAddress((void**)&p_u,    g_u);
    cudaGetSymbolAddress((void**)&p_Whi,  g_Whi);
    cudaGetSymbolAddress((void**)&p_Wlo,  g_Wlo);
    cudaGetSymbolAddress((void**)&p_AhiS, g_AhiS);
    cudaGetSymbolAddress((void**)&p_AloS, g_AloS);
    cudaGetSymbolAddress((void**)&p_AhiL, g_AhiL);
    cudaGetSymbolAddress((void**)&p_AloL, g_AloL);

    cudaFuncSetAttribute(tc_gemm, cudaFuncAttributeMaxDynamicSharedMemorySize, SMEM_G);
    cudaFuncSetAttribute(attn3_kernel, cudaFuncAttributeMaxDynamicSharedMemorySize,
                         ATTN_SMEM);
    cudaFuncSetAttribute(lora_u_smem, cudaFuncAttributeMaxDynamicSharedMemorySize,
                         FFN_D * 4);

    // ---- weights -> split planes ----
    cvt_split<<<4096, 256>>>(Wqkv, p_Whi + WOFF_QKV, p_Wlo + WOFF_QKV,
                             (size_t)H3 * DIM / 4);
    cvt_split<<<4096, 256>>>(Wout, p_Whi + WOFF_OUT, p_Wlo + WOFF_OUT,
                             (size_t)DIM * DIM / 4);
    cvt_split<<<4096, 256>>>(Wfc1, p_Whi + WOFF_FC1, p_Wlo + WOFF_FC1,
                             (size_t)FFN_D * DIM / 4);
    cvt_split<<<4096, 256>>>(Wfc2, p_Whi + WOFF_FC2, p_Wlo + WOFF_FC2,
                             (size_t)DIM * FFN_D / 4);

    // ---- attention block ----
    ln_fused<<<NT, 256>>>(x, ln1g, ln1b, Aqkv, map, p_AhiS, p_AloS, p_u);
    tc_gemm<<<dim3(H3 / BN, NT / BM), 256, SMEM_G>>>(
        p_AhiS, p_AloS, p_Whi + WOFF_QKV, p_Wlo + WOFF_QKV,
        bqkv, p_u, Bqkv, map, nullptr, p_qkv, nullptr, nullptr, H3, DIM, 0);
    attn3_kernel<<<dim3(SEQ / TQ, NH, 2), 256, ATTN_SMEM>>>(p_qkv, p_attn,
                                                            p_AhiS, p_AloS);
    lora_u_smem<<<NT, 256, DIM * 4>>>(p_attn, Aout, map, p_u, DIM);
    tc_gemm<<<dim3(DIM / BN, NT / BM), 256, SMEM_G>>>(
        p_AhiS, p_AloS, p_Whi + WOFF_OUT, p_Wlo + WOFF_OUT,
        bout, p_u, Bout, map, x, p_res2, nullptr, nullptr, DIM, DIM, 0);
    // ---- FFN block ----
    ln_fused<<<NT, 256>>>(p_res2, ln2g, ln2b, Afc1, map, p_AhiS, p_AloS, p_u);
    tc_gemm<<<dim3(FFN_D / BN, NT / BM), 256, SMEM_G>>>(
        p_AhiS, p_AloS, p_Whi + WOFF_FC1, p_Wlo + WOFF_FC1,
        bfc1, p_u, Bfc1, map, nullptr, p_h1, p_AhiL, p_AloL, FFN_D, DIM, 1);
    lora_u_smem<<<NT, 256, FFN_D * 4>>>(p_h1, Afc2, map, p_u, FFN_D);
    tc_gemm<<<dim3(DIM / BN, NT / BM), 256, SMEM_G>>>(
        p_AhiL, p_AloL, p_Whi + WOFF_FC2, p_Wlo + WOFF_FC2,
        bfc2, p_u, Bfc2, map, p_res2, out, nullptr, nullptr, DIM, FFN_D, 0);
}

// round 9
// speedup vs baseline: 2.9541x; 1.2864x over previous
#include <cuda_runtime.h>
#include <cuda_fp16.h>
#include <cstdint>
#include <cstddef>

#define DIM   4096
#define H3    12288
#define FFN_D 16384
#define NT    2048      // total tokens = 2*1024
#define LR    16        // lora rank
#define SEQ   1024
#define NH    32
#define HD    128

// ---------------- scratch (device globals; no allocations allowed) ----------
__device__ float g_qkv [(size_t)NT * H3];
__device__ float g_attn[(size_t)NT * DIM];
__device__ float g_res2[(size_t)NT * DIM];
__device__ float g_h1  [(size_t)NT * FFN_D];
__device__ float g_u   [(size_t)NT * LR];

// fp16 weight plane (single) + fp16 activation planes (hi/lo)
#define WOFF_QKV 0
#define WOFF_OUT 50331648u
#define WOFF_FC1 67108864u
#define WOFF_FC2 134217728u
#define W_TOTAL  201326592u
__device__ __half g_Wh [W_TOTAL];
__device__ __half g_AhiS[(size_t)NT * DIM];
__device__ __half g_AloS[(size_t)NT * DIM];
__device__ __half g_AhiL[(size_t)NT * FFN_D];
__device__ __half g_AloL[(size_t)NT * FFN_D];

// ================= helpers ===================================================
__device__ __forceinline__ uint32_t smem_u32(const void* p) {
    uint32_t a;
    asm("{ .reg .u64 t; cvta.to.shared.u64 t, %1; cvt.u32.u64 %0, t; }"
        : "=r"(a) : "l"(p));
    return a;
}
__device__ __forceinline__ void ldmx4(uint32_t* r, uint32_t addr) {
    asm volatile("ldmatrix.sync.aligned.m8n8.x4.shared.b16 {%0,%1,%2,%3}, [%4];"
                 : "=r"(r[0]), "=r"(r[1]), "=r"(r[2]), "=r"(r[3]) : "r"(addr));
}
__device__ __forceinline__ uint32_t lds32(uint32_t addr) {
    uint32_t v;
    asm volatile("ld.shared.b32 %0, [%1];" : "=r"(v) : "r"(addr));
    return v;
}
__device__ __forceinline__ void mmaf16(float* d, const uint32_t* a,
                                       uint32_t b0, uint32_t b1) {
    asm volatile("mma.sync.aligned.m16n8k16.row.col.f32.f16.f16.f32 "
                 "{%0,%1,%2,%3}, {%4,%5,%6,%7}, {%8,%9}, {%0,%1,%2,%3};"
                 : "+f"(d[0]), "+f"(d[1]), "+f"(d[2]), "+f"(d[3])
                 : "r"(a[0]), "r"(a[1]), "r"(a[2]), "r"(a[3]),
                   "r"(b0), "r"(b1));
}
__device__ __forceinline__ void cpa16(uint32_t d, const void* s) {
    asm volatile("cp.async.ca.shared.global [%0], [%1], 16;"
                 :: "r"(d), "l"(s) : "memory");
}
__device__ __forceinline__ void cpa_commit() {
    asm volatile("cp.async.commit_group;" ::: "memory");
}
// pack two floats into (hi,lo) fp16 planes
__device__ __forceinline__ void split2h(float a, float b, __half* hi, __half* lo) {
    __half h0 = __float2half_rn(a), h1 = __float2half_rn(b);
    float l0 = a - __half2float(h0), l1 = b - __half2float(h1);
    *(__half2*)hi = __halves2half2(h0, h1);
    *(__half2*)lo = __halves2half2(__float2half_rn(l0), __float2half_rn(l1));
}

// ================= fp32 -> fp16 (weights, single plane) =======================
__global__ void cvt_h(const float* __restrict__ src, __half* __restrict__ dst,
                      size_t n4) {
    size_t i = (size_t)blockIdx.x * blockDim.x + threadIdx.x;
    size_t stride = (size_t)gridDim.x * blockDim.x;
    for (; i < n4; i += stride) {
        float4 v = ((const float4*)src)[i];
        __half2 h0 = __halves2half2(__float2half_rn(v.x), __float2half_rn(v.y));
        __half2 h1 = __halves2half2(__float2half_rn(v.z), __float2half_rn(v.w));
        ((__half2*)dst)[i * 2]     = h0;
        ((__half2*)dst)[i * 2 + 1] = h1;
    }
}

// ================= fused LayerNorm + plane split + lora-u =====================
__global__ void ln_fused(const float* __restrict__ x, const float* __restrict__ g,
                         const float* __restrict__ b, const float* __restrict__ A,
                         const int* __restrict__ map,
                         __half* __restrict__ hi, __half* __restrict__ lo,
                         float* __restrict__ u) {
    __shared__ float row[DIM];
    __shared__ float rs[8], rs2[8];
    int t = blockIdx.x;
    int tid = threadIdx.x, lane = tid & 31, warp = tid >> 5;
    const float4* x4 = (const float4*)(x + (size_t)t * DIM);
    float4* row4 = (float4*)row;
    float s = 0.f, s2 = 0.f;
    #pragma unroll
    for (int p = 0; p < 4; p++) {
        int i = tid + p * 256;
        float4 v = x4[i];
        row4[i] = v;
        s += v.x + v.y + v.z + v.w;
        s2 += v.x * v.x + v.y * v.y + v.z * v.z + v.w * v.w;
    }
    #pragma unroll
    for (int o = 16; o; o >>= 1) {
        s  += __shfl_xor_sync(0xffffffffu, s,  o);
        s2 += __shfl_xor_sync(0xffffffffu, s2, o);
    }
    if (!lane) { rs[warp] = s; rs2[warp] = s2; }
    __syncthreads();
    s = 0.f; s2 = 0.f;
    #pragma unroll
    for (int w = 0; w < 8; w++) { s += rs[w]; s2 += rs2[w]; }
    float mean = s * (1.f / DIM);
    float var  = s2 * (1.f / DIM) - mean * mean;
    float rstd = rsqrtf(var + 1e-5f);
    __half* hr = hi + (size_t)t * DIM;
    __half* lr = lo + (size_t)t * DIM;
    const float4* g4 = (const float4*)g;
    const float4* b4 = (const float4*)b;
    #pragma unroll
    for (int p = 0; p < 4; p++) {
        int i = tid + p * 256;
        float4 v = row4[i], gv = g4[i], bv = b4[i];
        float4 nv;
        nv.x = (v.x - mean) * rstd * gv.x + bv.x;
        nv.y = (v.y - mean) * rstd * gv.y + bv.y;
        nv.z = (v.z - mean) * rstd * gv.z + bv.z;
        nv.w = (v.w - mean) * rstd * gv.w + bv.w;
        split2h(nv.x, nv.y, hr + i * 4, lr + i * 4);
        split2h(nv.z, nv.w, hr + i * 4 + 2, lr + i * 4 + 2);
        row4[i] = nv;
    }
    __syncthreads();
    // lora-u: warp w does ranks 2w, 2w+1
    int a = map[t];
    #pragma unroll
    for (int rr = 0; rr < 2; rr++) {
        int r = warp * 2 + rr;
        const float4* ar = (const float4*)(A + ((size_t)a * LR + r) * DIM);
        float acc = 0.f;
        #pragma unroll
        for (int p = 0; p < 32; p++) {
            int i = lane + p * 32;
            float4 av = ar[i], xv = row4[i];
            acc += av.x * xv.x + av.y * xv.y + av.z * xv.z + av.w * xv.w;
        }
        #pragma unroll
        for (int o = 16; o; o >>= 1) acc += __shfl_xor_sync(0xffffffffu, acc, o);
        if (!lane) u[t * LR + r] = acc;
    }
}

// ================= lora-u with smem-staged row ================================
__global__ void lora_u_smem(const float* __restrict__ x, const float* __restrict__ A,
                            const int* __restrict__ map, float* __restrict__ u, int K) {
    extern __shared__ float srow[];
    int t = blockIdx.x;
    int tid = threadIdx.x, lane = tid & 31, warp = tid >> 5;
    const float4* x4 = (const float4*)(x + (size_t)t * K);
    float4* s4 = (float4*)srow;
    int n4 = K >> 2;
    for (int i = tid; i < n4; i += 256) s4[i] = x4[i];
    __syncthreads();
    int a = map[t];
    #pragma unroll
    for (int rr = 0; rr < 2; rr++) {
        int r = warp * 2 + rr;
        const float4* ar = (const float4*)(A + ((size_t)a * LR + r) * K);
        float acc = 0.f;
        for (int i = lane; i < n4; i += 32) {
            float4 av = ar[i], xv = s4[i];
            acc += av.x * xv.x + av.y * xv.y + av.z * xv.z + av.w * xv.w;
        }
        #pragma unroll
        for (int o = 16; o; o >>= 1) acc += __shfl_xor_sync(0xffffffffu, acc, o);
        if (!lane) u[t * LR + r] = acc;
    }
}

// ================= tensor-core GEMM (fp16, A split 2-term, W single) ==========
// C[m,n] = sum_k A[m,k]*W[n,k] + bias[n] + sum_r u[m,r]*Bl[map[m],n,r]
//          (+ resid) (relu?)  plane-out optional.
#define BM 128
#define BN 128
#define RSTR 40                       // smem row stride in halves (80 B rows)
#define PLANE (128 * RSTR * 2)        // 10240 B per plane
#define STAGE_B (3 * PLANE)           // A_hi | A_lo | W
#define SOFF_BIAS  128
#define SOFF_STAGE 1024
#define SMEM_G (SOFF_STAGE + 65536)   // lora-B overlay (64KB) > 2 stages (60KB)

__device__ __forceinline__ float dot16(const float* u, const float* b) {
    float s = 0.f;
    #pragma unroll
    for (int r = 0; r < 16; r++) s = fmaf(u[r], b[r], s);
    return s;
}

__device__ __forceinline__ void issue_chunk(
        const __half* __restrict__ Ahi, const __half* __restrict__ Alo,
        const __half* __restrict__ W,
        int m0, int n0, int K, int c, uint32_t sdst, int tid) {
    int k0 = c * 32;
    #pragma unroll
    for (int p = 0; p < 2; p++) {
        int idx = tid + p * 256;
        int row = idx >> 2, seg = idx & 3;
        uint32_t d = sdst + row * (RSTR * 2) + seg * 16;
        size_t ao = (size_t)(m0 + row) * K + k0 + seg * 8;
        size_t wo = (size_t)(n0 + row) * K + k0 + seg * 8;
        cpa16(d,             Ahi + ao);
        cpa16(d + PLANE,     Alo + ao);
        cpa16(d + 2 * PLANE, W + wo);
    }
    cpa_commit();
}

__global__ void __launch_bounds__(256, 2)
tc_gemm(const __half* __restrict__ Ahi, const __half* __restrict__ Alo,
        const __half* __restrict__ W,
        const float* __restrict__ bias, const float* __restrict__ u,
        const float* __restrict__ Bl, const int* __restrict__ map,
        const float* __restrict__ resid, float* __restrict__ C,
        __half* __restrict__ hiO, __half* __restrict__ loO,
        int N, int K, int relu) {
    extern __shared__ __align__(1024) char smem[];
    uint32_t sbase = smem_u32(smem);
    int tid = threadIdx.x;
    int lane = tid & 31, warp = tid >> 5;
    int wm = warp >> 2, wn = warp & 3;
    int n0 = blockIdx.x * BN;
    int m0 = blockIdx.y * BM;

    if (tid < BN) ((float*)(smem + SOFF_BIAS))[tid] = bias[n0 + tid];

    float acc[4][4][4];
    #pragma unroll
    for (int f = 0; f < 4; f++)
        #pragma unroll
        for (int g = 0; g < 4; g++)
            #pragma unroll
            for (int e = 0; e < 4; e++) acc[f][g][e] = 0.f;

    int nCh = K >> 5;
    issue_chunk(Ahi, Alo, W, m0, n0, K, 0, sbase + SOFF_STAGE, tid);
    issue_chunk(Ahi, Alo, W, m0, n0, K, 1, sbase + SOFF_STAGE + STAGE_B, tid);

    int lane15 = lane & 15, laneHalf = lane >> 4;
    int grp = lane >> 2, tig = lane & 3;

    for (int c = 0; c < nCh; c++) {
        int cur = c & 1;
        if (c + 1 < nCh)
            asm volatile("cp.async.wait_group 1;" ::: "memory");
        else
            asm volatile("cp.async.wait_group 0;" ::: "memory");
        __syncthreads();

        uint32_t base = sbase + SOFF_STAGE + cur * STAGE_B;
        #pragma unroll
        for (int ks = 0; ks < 2; ks++) {
            uint32_t ahi[4][4], alo[4][4];
            int koffA = ks * 16 + laneHalf * 8;
            #pragma unroll
            for (int f = 0; f < 4; f++) {
                int row = wm * 64 + f * 16 + lane15;
                uint32_t ad = base + row * (RSTR * 2) + koffA * 2;
                ldmx4(ahi[f], ad);
                ldmx4(alo[f], ad + PLANE);
            }
            #pragma unroll
            for (int g = 0; g < 4; g++) {
                int n = wn * 32 + g * 8 + grp;
                uint32_t bd = base + 2 * PLANE + n * (RSTR * 2)
                            + (ks * 16 + tig * 2) * 2;
                uint32_t w0 = lds32(bd), w1 = lds32(bd + 16);
                #pragma unroll
                for (int f = 0; f < 4; f++) {
                    mmaf16(acc[f][g], ahi[f], w0, w1);
                    mmaf16(acc[f][g], alo[f], w0, w1);
                }
            }
        }
        __syncthreads();
        if (c + 2 < nCh)
            issue_chunk(Ahi, Alo, W, m0, n0, K, c + 2,
                        sbase + SOFF_STAGE + cur * STAGE_B, tid);
    }

    // ---- stage lora-B slice into SMEM ----
    float* Bs = (float*)(smem + SOFF_STAGE);
    for (int i = tid; i < 4096; i += 256) {
        int a   = i >> 9;
        int rem = i & 511;
        int nl  = rem >> 2;
        int sg  = rem & 3;
        float4 v = *(const float4*)(Bl + ((size_t)a * N + n0 + nl) * LR + sg * 4);
        *(float4*)(Bs + ((size_t)((a << 7) + nl)) * LR + sg * 4) = v;
    }
    __syncthreads();

    const float* biasS = (const float*)(smem + SOFF_BIAS);
    #pragma unroll
    for (int f = 0; f < 4; f++) {
        int r0 = m0 + wm * 64 + f * 16 + grp;
        int r1 = r0 + 8;
        int a0 = map[r0], a1 = map[r1];
        float u0[16], u1[16];
        {
            const float4* p0 = (const float4*)(u + (size_t)r0 * LR);
            const float4* p1 = (const float4*)(u + (size_t)r1 * LR);
            #pragma unroll
            for (int q = 0; q < 4; q++) {
                float4 v0 = p0[q], v1 = p1[q];
                u0[q*4+0]=v0.x; u0[q*4+1]=v0.y; u0[q*4+2]=v0.z; u0[q*4+3]=v0.w;
                u1[q*4+0]=v1.x; u1[q*4+1]=v1.y; u1[q*4+2]=v1.z; u1[q*4+3]=v1.w;
            }
        }
        #pragma unroll
        for (int g = 0; g < 4; g++) {
            int nl = wn * 32 + g * 8 + tig * 2;
            float v00 = acc[f][g][0] + biasS[nl]
                      + dot16(u0, Bs + ((size_t)((a0 << 7) + nl)) * LR);
            float v01 = acc[f][g][1] + biasS[nl + 1]
                      + dot16(u0, Bs + ((size_t)((a0 << 7) + nl + 1)) * LR);
            float v10 = acc[f][g][2] + biasS[nl]
                      + dot16(u1, Bs + ((size_t)((a1 << 7) + nl)) * LR);
            float v11 = acc[f][g][3] + biasS[nl + 1]
                      + dot16(u1, Bs + ((size_t)((a1 << 7) + nl + 1)) * LR);
            size_t o0 = (size_t)r0 * N + n0 + nl;
            size_t o1 = (size_t)r1 * N + n0 + nl;
            if (resid) {
                float2 q0 = *(const float2*)(resid + o0);
                float2 q1 = *(const float2*)(resid + o1);
                v00 += q0.x; v01 += q0.y; v10 += q1.x; v11 += q1.y;
            }
            if (relu) {
                v00 = fmaxf(v00, 0.f); v01 = fmaxf(v01, 0.f);
                v10 = fmaxf(v10, 0.f); v11 = fmaxf(v11, 0.f);
            }
            *(float2*)(C + o0) = make_float2(v00, v01);
            *(float2*)(C + o1) = make_float2(v10, v11);
            if (hiO) {
                split2h(v00, v01, hiO + o0, loO + o0);
                split2h(v10, v11, hiO + o1, loO + o1);
            }
        }
    }
}

// ================= attention: TQ=16, K-chunked smem, fused plane-out ==========
#define TQ 16
#define KCH 64
#define KSTR 33                       // k-chunk row stride in float4
#define AQ_OFF  0
#define ASC_OFF (16 * 128)
#define AK_OFF  (ASC_OFF + 16 * 1024)
#define ASV_OFF (AK_OFF + KCH * KSTR * 4)
#define ATTN_SMEM ((ASV_OFF + 16) * 4)

__global__ void __launch_bounds__(256, 1)
attn3_kernel(const float* __restrict__ qkv, float* __restrict__ out,
             __half* __restrict__ hi, __half* __restrict__ lo) {
    extern __shared__ float sm[];
    float4* qs4 = (float4*)(sm + AQ_OFF);
    float*  sc  = sm + ASC_OFF;
    float4* kc4 = (float4*)(sm + AK_OFF);
    float*  sinv = sm + ASV_OFF;
    int qt = blockIdx.x, h = blockIdx.y, bb = blockIdx.z;
    int q0 = qt * TQ;
    int tid = threadIdx.x, lane = tid & 31, warp = tid >> 5;
    const size_t base = (size_t)bb * SEQ * H3;
    const float scale = 0.08838834764831845f;

    #pragma unroll
    for (int p = 0; p < 2; p++) {
        int i = tid + p * 256;
        int r = i >> 5, d4 = i & 31;
        qs4[r * 32 + d4] = *(const float4*)(qkv + base + (size_t)(q0 + r) * H3
                                            + h * HD + d4 * 4);
    }
    __syncthreads();

    int nkmax = q0 + TQ;
    int nch = (nkmax + KCH - 1) / KCH;
    int kkL = tid & 63, rbase = tid >> 6;
    for (int ch = 0; ch < nch; ch++) {
        int kb = ch * KCH;
        #pragma unroll
        for (int p = 0; p < 8; p++) {
            int i = tid + p * 256;
            int r = i >> 5, d4 = i & 31;
            if (kb + r < nkmax)
                kc4[r * KSTR + d4] = *(const float4*)(qkv + base
                    + (size_t)(kb + r) * H3 + DIM + h * HD + d4 * 4);
        }
        __syncthreads();
        int kk = kb + kkL;
        if (kk < nkmax) {
            float part[4] = {0.f, 0.f, 0.f, 0.f};
            #pragma unroll 8
            for (int d4 = 0; d4 < 32; d4++) {
                float4 kv = kc4[kkL * KSTR + d4];
                #pragma unroll
                for (int rr = 0; rr < 4; rr++) {
                    float4 qv = qs4[(rbase * 4 + rr) * 32 + d4];
                    part[rr] += qv.x * kv.x + qv.y * kv.y + qv.z * kv.z + qv.w * kv.w;
                }
            }
            #pragma unroll
            for (int rr = 0; rr < 4; rr++)
                sc[(rbase * 4 + rr) * SEQ + kk] = part[rr] * scale;
        }
        __syncthreads();
    }

    #pragma unroll
    for (int rr = 0; rr < 2; rr++) {
        int row = warp + rr * 8;
        int nk = q0 + row + 1;
        float* sr = sc + row * SEQ;
        float mx = -1e30f;
        for (int j = lane; j < nk; j += 32) mx = fmaxf(mx, sr[j]);
        #pragma unroll
        for (int o = 16; o; o >>= 1)
            mx = fmaxf(mx, __shfl_xor_sync(0xffffffffu, mx, o));
        float sum = 0.f;
        for (int j = lane; j < nk; j += 32) {
            float e = __expf(sr[j] - mx);
            sr[j] = e;
            sum += e;
        }
        #pragma unroll
        for (int o = 16; o; o >>= 1) sum += __shfl_xor_sync(0xffffffffu, sum, o);
        if (!lane) sinv[row] = 1.f / sum;
    }
    __syncthreads();

    {
        int d4 = lane, rp = warp;
        const float* vb = qkv + base + 2 * DIM + h * HD + d4 * 4;
        #pragma unroll
        for (int rr = 0; rr < 2; rr++) {
            int row = rp + rr * 8;
            int nk = q0 + row + 1;
            const float* sr = sc + row * SEQ;
            float4 acc = make_float4(0.f, 0.f, 0.f, 0.f);
            int j = 0;
            for (; j + 2 <= nk; j += 2) {
                float p0 = sr[j], p1 = sr[j + 1];
                float4 v0 = *(const float4*)(vb + (size_t)j * H3);
                float4 v1 = *(const float4*)(vb + (size_t)(j + 1) * H3);
                acc.x += p0 * v0.x + p1 * v1.x;
                acc.y += p0 * v0.y + p1 * v1.y;
                acc.z += p0 * v0.z + p1 * v1.z;
                acc.w += p0 * v0.w + p1 * v1.w;
            }
            if (j < nk) {
                float p0 = sr[j];
                float4 v0 = *(const float4*)(vb + (size_t)j * H3);
                acc.x += p0 * v0.x; acc.y += p0 * v0.y;
                acc.z += p0 * v0.z; acc.w += p0 * v0.w;
            }
            float iv = sinv[row];
            acc.x *= iv; acc.y *= iv; acc.z *= iv; acc.w *= iv;
            size_t o = ((size_t)bb * SEQ + q0 + row) * DIM + h * HD + d4 * 4;
            *(float4*)(out + o) = acc;
            split2h(acc.x, acc.y, hi + o, lo + o);
            split2h(acc.z, acc.w, hi + o + 2, lo + o + 2);
        }
    }
}

// ---------------- launch ------------------------------------------------------
extern "C" void kernel_launch(void* const* d_in, const int* in_sizes, int n_in,
                              void* d_out, int out_size) {
    const float* x    = (const float*)d_in[0];
    const int*   map  = (const int*)  d_in[1];
    const float* Wqkv = (const float*)d_in[2];
    const float* bqkv = (const float*)d_in[3];
    const float* Wout = (const float*)d_in[4];
    const float* bout = (const float*)d_in[5];
    const float* Wfc1 = (const float*)d_in[6];
    const float* bfc1 = (const float*)d_in[7];
    const float* Wfc2 = (const float*)d_in[8];
    const float* bfc2 = (const float*)d_in[9];
    const float* ln1g = (const float*)d_in[10];
    const float* ln1b = (const float*)d_in[11];
    const float* ln2g = (const float*)d_in[12];
    const float* ln2b = (const float*)d_in[13];
    const float* Aqkv = (const float*)d_in[14];
    const float* Bqkv = (const float*)d_in[15];
    const float* Aout = (const float*)d_in[16];
    const float* Bout = (const float*)d_in[17];
    const float* Afc1 = (const float*)d_in[18];
    const float* Bfc1 = (const float*)d_in[19];
    const float* Afc2 = (const float*)d_in[20];
    const float* Bfc2 = (const float*)d_in[21];
    float* out = (float*)d_out;

    float *p_qkv, *p_attn, *p_res2, *p_h1, *p_u;
    __half *p_Wh, *p_AhiS, *p_AloS, *p_AhiL, *p_AloL;
    cudaGetSymbolAddress((void**)&p_qkv,  g_qkv);
    cudaGetSymbolAddress((void**)&p_attn, g_attn);
    cudaGetSymbolAddress((void**)&p_res2, g_res2);
    cudaGetSymbolAddress((void**)&p_h1,   g_h1);
    cudaGetSymbolAddress((void**)&p_u,    g_u);
    cudaGetSymbolAddress((void**)&p_Wh,   g_Wh);
    cudaGetSymbolAddress((void**)&p_AhiS, g_AhiS);
    cudaGetSymbolAddress((void**)&p_AloS, g_AloS);
    cudaGetSymbolAddress((void**)&p_AhiL, g_AhiL);
    cudaGetSymbolAddress((void**)&p_AloL, g_AloL);

    cudaFuncSetAttribute(tc_gemm, cudaFuncAttributeMaxDynamicSharedMemorySize, SMEM_G);
    cudaFuncSetAttribute(attn3_kernel, cudaFuncAttributeMaxDynamicSharedMemorySize,
                         ATTN_SMEM);
    cudaFuncSetAttribute(lora_u_smem, cudaFuncAttributeMaxDynamicSharedMemorySize,
                         FFN_D * 4);

    // ---- weights -> fp16 single plane ----
    cvt_h<<<4096, 256>>>(Wqkv, p_Wh + WOFF_QKV, (size_t)H3 * DIM / 4);
    cvt_h<<<4096, 256>>>(Wout, p_Wh + WOFF_OUT, (size_t)DIM * DIM / 4);
    cvt_h<<<4096, 256>>>(Wfc1, p_Wh + WOFF_FC1, (size_t)FFN_D * DIM / 4);
    cvt_h<<<4096, 256>>>(Wfc2, p_Wh + WOFF_FC2, (size_t)DIM * FFN_D / 4);

    // ---- attention block ----
    ln_fused<<<NT, 256>>>(x, ln1g, ln1b, Aqkv, map, p_AhiS, p_AloS, p_u);
    tc_gemm<<<dim3(H3 / BN, NT / BM), 256, SMEM_G>>>(
        p_AhiS, p_AloS, p_Wh + WOFF_QKV,
        bqkv, p_u, Bqkv, map, nullptr, p_qkv, nullptr, nullptr, H3, DIM, 0);
    attn3_kernel<<<dim3(SEQ / TQ, NH, 2), 256, ATTN_SMEM>>>(p_qkv, p_attn,
                                                            p_AhiS, p_AloS);
    lora_u_smem<<<NT, 256, DIM * 4>>>(p_attn, Aout, map, p_u, DIM);
    tc_gemm<<<dim3(DIM / BN, NT / BM), 256, SMEM_G>>>(
        p_AhiS, p_AloS, p_Wh + WOFF_OUT,
        bout, p_u, Bout, map, x, p_res2, nullptr, nullptr, DIM, DIM, 0);
    // ---- FFN block ----
    ln_fused<<<NT, 256>>>(p_res2, ln2g, ln2b, Afc1, map, p_AhiS, p_AloS, p_u);
    tc_gemm<<<dim3(FFN_D / BN, NT / BM), 256, SMEM_G>>>(
        p_AhiS, p_AloS, p_Wh + WOFF_FC1,
        bfc1, p_u, Bfc1, map, nullptr, p_h1, p_AhiL, p_AloL, FFN_D, DIM, 1);
    lora_u_smem<<<NT, 256, FFN_D * 4>>>(p_h1, Afc2, map, p_u, FFN_D);
    tc_gemm<<<dim3(DIM / BN, NT / BM), 256, SMEM_G>>>(
        p_AhiL, p_AloL, p_Wh + WOFF_FC2,
        bfc2, p_u, Bfc2, map, p_res2, out, nullptr, nullptr, DIM, FFN_D, 0);
}

// round 10
// speedup vs baseline: 4.0548x; 1.3726x over previous
#include <cuda_runtime.h>
#include <cuda_fp16.h>
#include <cstdint>
#include <cstddef>

#define DIM   4096
#define H3    12288
#define FFN_D 16384
#define NT    2048      // total tokens = 2*1024
#define LR    16        // lora rank
#define SEQ   1024
#define NH    32
#define HD    128

// ---------------- scratch (device globals; no allocations allowed) ----------
__device__ float g_qkv [(size_t)NT * H3];
__device__ float g_attn[(size_t)NT * DIM];
__device__ float g_res2[(size_t)NT * DIM];
__device__ float g_h1  [(size_t)NT * FFN_D];
__device__ float g_u   [(size_t)NT * LR];

// fp16 weight plane + fp16 activation planes (single each)
#define WOFF_QKV 0
#define WOFF_OUT 50331648u
#define WOFF_FC1 67108864u
#define WOFF_FC2 134217728u
#define W_TOTAL  201326592u
__device__ __half g_Wh [W_TOTAL];
__device__ __half g_AS [(size_t)NT * DIM];
__device__ __half g_AL [(size_t)NT * FFN_D];

// ================= helpers ===================================================
__device__ __forceinline__ uint32_t smem_u32(const void* p) {
    uint32_t a;
    asm("{ .reg .u64 t; cvta.to.shared.u64 t, %1; cvt.u32.u64 %0, t; }"
        : "=r"(a) : "l"(p));
    return a;
}
__device__ __forceinline__ void ldmx4(uint32_t* r, uint32_t addr) {
    asm volatile("ldmatrix.sync.aligned.m8n8.x4.shared.b16 {%0,%1,%2,%3}, [%4];"
                 : "=r"(r[0]), "=r"(r[1]), "=r"(r[2]), "=r"(r[3]) : "r"(addr));
}
__device__ __forceinline__ uint32_t lds32(uint32_t addr) {
    uint32_t v;
    asm volatile("ld.shared.b32 %0, [%1];" : "=r"(v) : "r"(addr));
    return v;
}
__device__ __forceinline__ void mmaf16(float* d, const uint32_t* a,
                                       uint32_t b0, uint32_t b1) {
    asm volatile("mma.sync.aligned.m16n8k16.row.col.f32.f16.f16.f32 "
                 "{%0,%1,%2,%3}, {%4,%5,%6,%7}, {%8,%9}, {%0,%1,%2,%3};"
                 : "+f"(d[0]), "+f"(d[1]), "+f"(d[2]), "+f"(d[3])
                 : "r"(a[0]), "r"(a[1]), "r"(a[2]), "r"(a[3]),
                   "r"(b0), "r"(b1));
}
__device__ __forceinline__ void cpa16(uint32_t d, const void* s) {
    asm volatile("cp.async.ca.shared.global [%0], [%1], 16;"
                 :: "r"(d), "l"(s) : "memory");
}
__device__ __forceinline__ void cpa_commit() {
    asm volatile("cp.async.commit_group;" ::: "memory");
}
__device__ __forceinline__ void pack2h(float a, float b, __half* dst) {
    *(__half2*)dst = __halves2half2(__float2half_rn(a), __float2half_rn(b));
}

// ================= fp32 -> fp16 (weights, single plane) =======================
__global__ void cvt_h(const float* __restrict__ src, __half* __restrict__ dst,
                      size_t n4) {
    size_t i = (size_t)blockIdx.x * blockDim.x + threadIdx.x;
    size_t stride = (size_t)gridDim.x * blockDim.x;
    for (; i < n4; i += stride) {
        float4 v = ((const float4*)src)[i];
        ((__half2*)dst)[i * 2]     = __halves2half2(__float2half_rn(v.x),
                                                    __float2half_rn(v.y));
        ((__half2*)dst)[i * 2 + 1] = __halves2half2(__float2half_rn(v.z),
                                                    __float2half_rn(v.w));
    }
}

// ================= fused LayerNorm + fp16 plane + lora-u ======================
__global__ void ln_fused(const float* __restrict__ x, const float* __restrict__ g,
                         const float* __restrict__ b, const float* __restrict__ A,
                         const int* __restrict__ map,
                         __half* __restrict__ hp, float* __restrict__ u) {
    __shared__ float row[DIM];
    __shared__ float rs[8], rs2[8];
    int t = blockIdx.x;
    int tid = threadIdx.x, lane = tid & 31, warp = tid >> 5;
    const float4* x4 = (const float4*)(x + (size_t)t * DIM);
    float4* row4 = (float4*)row;
    float s = 0.f, s2 = 0.f;
    #pragma unroll
    for (int p = 0; p < 4; p++) {
        int i = tid + p * 256;
        float4 v = x4[i];
        row4[i] = v;
        s += v.x + v.y + v.z + v.w;
        s2 += v.x * v.x + v.y * v.y + v.z * v.z + v.w * v.w;
    }
    #pragma unroll
    for (int o = 16; o; o >>= 1) {
        s  += __shfl_xor_sync(0xffffffffu, s,  o);
        s2 += __shfl_xor_sync(0xffffffffu, s2, o);
    }
    if (!lane) { rs[warp] = s; rs2[warp] = s2; }
    __syncthreads();
    s = 0.f; s2 = 0.f;
    #pragma unroll
    for (int w = 0; w < 8; w++) { s += rs[w]; s2 += rs2[w]; }
    float mean = s * (1.f / DIM);
    float var  = s2 * (1.f / DIM) - mean * mean;
    float rstd = rsqrtf(var + 1e-5f);
    __half* hr = hp + (size_t)t * DIM;
    const float4* g4 = (const float4*)g;
    const float4* b4 = (const float4*)b;
    #pragma unroll
    for (int p = 0; p < 4; p++) {
        int i = tid + p * 256;
        float4 v = row4[i], gv = g4[i], bv = b4[i];
        float4 nv;
        nv.x = (v.x - mean) * rstd * gv.x + bv.x;
        nv.y = (v.y - mean) * rstd * gv.y + bv.y;
        nv.z = (v.z - mean) * rstd * gv.z + bv.z;
        nv.w = (v.w - mean) * rstd * gv.w + bv.w;
        pack2h(nv.x, nv.y, hr + i * 4);
        pack2h(nv.z, nv.w, hr + i * 4 + 2);
        row4[i] = nv;
    }
    __syncthreads();
    int a = map[t];
    #pragma unroll
    for (int rr = 0; rr < 2; rr++) {
        int r = warp * 2 + rr;
        const float4* ar = (const float4*)(A + ((size_t)a * LR + r) * DIM);
        float acc = 0.f;
        #pragma unroll
        for (int p = 0; p < 32; p++) {
            int i = lane + p * 32;
            float4 av = ar[i], xv = row4[i];
            acc += av.x * xv.x + av.y * xv.y + av.z * xv.z + av.w * xv.w;
        }
        #pragma unroll
        for (int o = 16; o; o >>= 1) acc += __shfl_xor_sync(0xffffffffu, acc, o);
        if (!lane) u[t * LR + r] = acc;
    }
}

// ================= lora-u with smem-staged row ================================
__global__ void lora_u_smem(const float* __restrict__ x, const float* __restrict__ A,
                            const int* __restrict__ map, float* __restrict__ u, int K) {
    extern __shared__ float srow[];
    int t = blockIdx.x;
    int tid = threadIdx.x, lane = tid & 31, warp = tid >> 5;
    const float4* x4 = (const float4*)(x + (size_t)t * K);
    float4* s4 = (float4*)srow;
    int n4 = K >> 2;
    for (int i = tid; i < n4; i += 256) s4[i] = x4[i];
    __syncthreads();
    int a = map[t];
    #pragma unroll
    for (int rr = 0; rr < 2; rr++) {
        int r = warp * 2 + rr;
        const float4* ar = (const float4*)(A + ((size_t)a * LR + r) * K);
        float acc = 0.f;
        for (int i = lane; i < n4; i += 32) {
            float4 av = ar[i], xv = s4[i];
            acc += av.x * xv.x + av.y * xv.y + av.z * xv.z + av.w * xv.w;
        }
        #pragma unroll
        for (int o = 16; o; o >>= 1) acc += __shfl_xor_sync(0xffffffffu, acc, o);
        if (!lane) u[t * LR + r] = acc;
    }
}

// ================= tensor-core GEMM (fp16 x fp16, 1-term) =====================
// C[m,n] = sum_k A[m,k]*W[n,k] + bias[n] + sum_r u[m,r]*Bl[map[m],n,r]
//          (+ resid) (relu?)  fp16 plane-out optional.
// 3-stage cp.async pipeline, block 128x128, k-chunk 32.
#define BM 128
#define BN 128
#define RSTR 40                       // smem row stride in halves (80 B)
#define PLANE (128 * RSTR * 2)        // 10240 B per plane
#define STAGE_B (2 * PLANE)           // A | W = 20480
#define NSTAGE 3
#define SOFF_BIAS  128
#define SOFF_STAGE 1024
#define SMEM_G (SOFF_STAGE + 65536)   // lora-B overlay (64KB) > 3 stages (60KB)

__device__ __forceinline__ float dot16(const float* u, const float* b) {
    float s = 0.f;
    #pragma unroll
    for (int r = 0; r < 16; r++) s = fmaf(u[r], b[r], s);
    return s;
}

__device__ __forceinline__ void issue_chunk(
        const __half* __restrict__ Ah, const __half* __restrict__ W,
        int m0, int n0, int K, int c, uint32_t sdst, int tid) {
    int k0 = c * 32;
    // A: 128 rows x 4 segs of 16B; W same. 2+2 cp.async per thread.
    #pragma unroll
    for (int p = 0; p < 2; p++) {
        int idx = tid + p * 256;
        int row = idx >> 2, seg = idx & 3;
        uint32_t d = sdst + row * (RSTR * 2) + seg * 16;
        cpa16(d,         Ah + (size_t)(m0 + row) * K + k0 + seg * 8);
        cpa16(d + PLANE, W  + (size_t)(n0 + row) * K + k0 + seg * 8);
    }
    cpa_commit();
}

__global__ void __launch_bounds__(256, 2)
tc_gemm(const __half* __restrict__ Ah, const __half* __restrict__ W,
        const float* __restrict__ bias, const float* __restrict__ u,
        const float* __restrict__ Bl, const int* __restrict__ map,
        const float* __restrict__ resid, float* __restrict__ C,
        __half* __restrict__ hOut, int N, int K, int relu) {
    extern __shared__ __align__(1024) char smem[];
    uint32_t sbase = smem_u32(smem);
    int tid = threadIdx.x;
    int lane = tid & 31, warp = tid >> 5;
    int wm = warp >> 2, wn = warp & 3;
    int n0 = blockIdx.x * BN;
    int m0 = blockIdx.y * BM;

    if (tid < BN) ((float*)(smem + SOFF_BIAS))[tid] = bias[n0 + tid];

    float acc[4][4][4];
    #pragma unroll
    for (int f = 0; f < 4; f++)
        #pragma unroll
        for (int g = 0; g < 4; g++)
            #pragma unroll
            for (int e = 0; e < 4; e++) acc[f][g][e] = 0.f;

    int nCh = K >> 5;
    #pragma unroll
    for (int c = 0; c < NSTAGE; c++)
        if (c < nCh)
            issue_chunk(Ah, W, m0, n0, K, c,
                        sbase + SOFF_STAGE + c * STAGE_B, tid);

    int lane15 = lane & 15, laneHalf = lane >> 4;
    int grp = lane >> 2, tig = lane & 3;

    int stage = 0;
    for (int c = 0; c < nCh; c++) {
        int allow = nCh - 1 - c;       // chunks still outstanding beyond c
        if (allow >= 2)
            asm volatile("cp.async.wait_group 2;" ::: "memory");
        else if (allow == 1)
            asm volatile("cp.async.wait_group 1;" ::: "memory");
        else
            asm volatile("cp.async.wait_group 0;" ::: "memory");
        __syncthreads();

        uint32_t base = sbase + SOFF_STAGE + stage * STAGE_B;
        #pragma unroll
        for (int ks = 0; ks < 2; ks++) {
            uint32_t af[4][4];
            int koffA = ks * 16 + laneHalf * 8;
            #pragma unroll
            for (int f = 0; f < 4; f++) {
                int row = wm * 64 + f * 16 + lane15;
                ldmx4(af[f], base + row * (RSTR * 2) + koffA * 2);
            }
            #pragma unroll
            for (int g = 0; g < 4; g++) {
                int n = wn * 32 + g * 8 + grp;
                uint32_t bd = base + PLANE + n * (RSTR * 2)
                            + (ks * 16 + tig * 2) * 2;
                uint32_t w0 = lds32(bd), w1 = lds32(bd + 16);
                #pragma unroll
                for (int f = 0; f < 4; f++)
                    mmaf16(acc[f][g], af[f], w0, w1);
            }
        }
        __syncthreads();
        if (c + NSTAGE < nCh)
            issue_chunk(Ah, W, m0, n0, K, c + NSTAGE,
                        sbase + SOFF_STAGE + stage * STAGE_B, tid);
        stage = (stage + 1 == NSTAGE) ? 0 : stage + 1;
    }

    // ---- stage lora-B slice into SMEM (overlays stages) ----
    float* Bs = (float*)(smem + SOFF_STAGE);
    for (int i = tid; i < 4096; i += 256) {
        int a   = i >> 9;
        int rem = i & 511;
        int nl  = rem >> 2;
        int sg  = rem & 3;
        float4 v = *(const float4*)(Bl + ((size_t)a * N + n0 + nl) * LR + sg * 4);
        *(float4*)(Bs + ((size_t)((a << 7) + nl)) * LR + sg * 4) = v;
    }
    __syncthreads();

    const float* biasS = (const float*)(smem + SOFF_BIAS);
    #pragma unroll
    for (int f = 0; f < 4; f++) {
        int r0 = m0 + wm * 64 + f * 16 + grp;
        int r1 = r0 + 8;
        int a0 = map[r0], a1 = map[r1];
        float u0[16], u1[16];
        {
            const float4* p0 = (const float4*)(u + (size_t)r0 * LR);
            const float4* p1 = (const float4*)(u + (size_t)r1 * LR);
            #pragma unroll
            for (int q = 0; q < 4; q++) {
                float4 v0 = p0[q], v1 = p1[q];
                u0[q*4+0]=v0.x; u0[q*4+1]=v0.y; u0[q*4+2]=v0.z; u0[q*4+3]=v0.w;
                u1[q*4+0]=v1.x; u1[q*4+1]=v1.y; u1[q*4+2]=v1.z; u1[q*4+3]=v1.w;
            }
        }
        #pragma unroll
        for (int g = 0; g < 4; g++) {
            int nl = wn * 32 + g * 8 + tig * 2;
            float v00 = acc[f][g][0] + biasS[nl]
                      + dot16(u0, Bs + ((size_t)((a0 << 7) + nl)) * LR);
            float v01 = acc[f][g][1] + biasS[nl + 1]
                      + dot16(u0, Bs + ((size_t)((a0 << 7) + nl + 1)) * LR);
            float v10 = acc[f][g][2] + biasS[nl]
                      + dot16(u1, Bs + ((size_t)((a1 << 7) + nl)) * LR);
            float v11 = acc[f][g][3] + biasS[nl + 1]
                      + dot16(u1, Bs + ((size_t)((a1 << 7) + nl + 1)) * LR);
            size_t o0 = (size_t)r0 * N + n0 + nl;
            size_t o1 = (size_t)r1 * N + n0 + nl;
            if (resid) {
                float2 q0 = *(const float2*)(resid + o0);
                float2 q1 = *(const float2*)(resid + o1);
                v00 += q0.x; v01 += q0.y; v10 += q1.x; v11 += q1.y;
            }
            if (relu) {
                v00 = fmaxf(v00, 0.f); v01 = fmaxf(v01, 0.f);
                v10 = fmaxf(v10, 0.f); v11 = fmaxf(v11, 0.f);
            }
            *(float2*)(C + o0) = make_float2(v00, v01);
            *(float2*)(C + o1) = make_float2(v10, v11);
            if (hOut) {
                pack2h(v00, v01, hOut + o0);
                pack2h(v10, v11, hOut + o1);
            }
        }
    }
}

// ================= attention: TQ=16, K-chunked smem, fp16 plane-out ===========
#define TQ 16
#define KCH 64
#define KSTR 33
#define AQ_OFF  0
#define ASC_OFF (16 * 128)
#define AK_OFF  (ASC_OFF + 16 * 1024)
#define ASV_OFF (AK_OFF + KCH * KSTR * 4)
#define ATTN_SMEM ((ASV_OFF + 16) * 4)

__global__ void __launch_bounds__(256, 1)
attn3_kernel(const float* __restrict__ qkv, float* __restrict__ out,
             __half* __restrict__ hp) {
    extern __shared__ float sm[];
    float4* qs4 = (float4*)(sm + AQ_OFF);
    float*  sc  = sm + ASC_OFF;
    float4* kc4 = (float4*)(sm + AK_OFF);
    float*  sinv = sm + ASV_OFF;
    int qt = blockIdx.x, h = blockIdx.y, bb = blockIdx.z;
    int q0 = qt * TQ;
    int tid = threadIdx.x, lane = tid & 31, warp = tid >> 5;
    const size_t base = (size_t)bb * SEQ * H3;
    const float scale = 0.08838834764831845f;

    #pragma unroll
    for (int p = 0; p < 2; p++) {
        int i = tid + p * 256;
        int r = i >> 5, d4 = i & 31;
        qs4[r * 32 + d4] = *(const float4*)(qkv + base + (size_t)(q0 + r) * H3
                                            + h * HD + d4 * 4);
    }
    __syncthreads();

    int nkmax = q0 + TQ;
    int nch = (nkmax + KCH - 1) / KCH;
    int kkL = tid & 63, rbase = tid >> 6;
    for (int ch = 0; ch < nch; ch++) {
        int kb = ch * KCH;
        #pragma unroll
        for (int p = 0; p < 8; p++) {
            int i = tid + p * 256;
            int r = i >> 5, d4 = i & 31;
            if (kb + r < nkmax)
                kc4[r * KSTR + d4] = *(const float4*)(qkv + base
                    + (size_t)(kb + r) * H3 + DIM + h * HD + d4 * 4);
        }
        __syncthreads();
        int kk = kb + kkL;
        if (kk < nkmax) {
            float part[4] = {0.f, 0.f, 0.f, 0.f};
            #pragma unroll 8
            for (int d4 = 0; d4 < 32; d4++) {
                float4 kv = kc4[kkL * KSTR + d4];
                #pragma unroll
                for (int rr = 0; rr < 4; rr++) {
                    float4 qv = qs4[(rbase * 4 + rr) * 32 + d4];
                    part[rr] += qv.x * kv.x + qv.y * kv.y + qv.z * kv.z + qv.w * kv.w;
                }
            }
            #pragma unroll
            for (int rr = 0; rr < 4; rr++)
                sc[(rbase * 4 + rr) * SEQ + kk] = part[rr] * scale;
        }
        __syncthreads();
    }

    #pragma unroll
    for (int rr = 0; rr < 2; rr++) {
        int row = warp + rr * 8;
        int nk = q0 + row + 1;
        float* sr = sc + row * SEQ;
        float mx = -1e30f;
        for (int j = lane; j < nk; j += 32) mx = fmaxf(mx, sr[j]);
        #pragma unroll
        for (int o = 16; o; o >>= 1)
            mx = fmaxf(mx, __shfl_xor_sync(0xffffffffu, mx, o));
        float sum = 0.f;
        for (int j = lane; j < nk; j += 32) {
            float e = __expf(sr[j] - mx);
            sr[j] = e;
            sum += e;
        }
        #pragma unroll
        for (int o = 16; o; o >>= 1) sum += __shfl_xor_sync(0xffffffffu, sum, o);
        if (!lane) sinv[row] = 1.f / sum;
    }
    __syncthreads();

    {
        int d4 = lane, rp = warp;
        const float* vb = qkv + base + 2 * DIM + h * HD + d4 * 4;
        #pragma unroll
        for (int rr = 0; rr < 2; rr++) {
            int row = rp + rr * 8;
            int nk = q0 + row + 1;
            const float* sr = sc + row * SEQ;
            float4 acc = make_float4(0.f, 0.f, 0.f, 0.f);
            int j = 0;
            for (; j + 2 <= nk; j += 2) {
                float p0 = sr[j], p1 = sr[j + 1];
                float4 v0 = *(const float4*)(vb + (size_t)j * H3);
                float4 v1 = *(const float4*)(vb + (size_t)(j + 1) * H3);
                acc.x += p0 * v0.x + p1 * v1.x;
                acc.y += p0 * v0.y + p1 * v1.y;
                acc.z += p0 * v0.z + p1 * v1.z;
                acc.w += p0 * v0.w + p1 * v1.w;
            }
            if (j < nk) {
                float p0 = sr[j];
                float4 v0 = *(const float4*)(vb + (size_t)j * H3);
                acc.x += p0 * v0.x; acc.y += p0 * v0.y;
                acc.z += p0 * v0.z; acc.w += p0 * v0.w;
            }
            float iv = sinv[row];
            acc.x *= iv; acc.y *= iv; acc.z *= iv; acc.w *= iv;
            size_t o = ((size_t)bb * SEQ + q0 + row) * DIM + h * HD + d4 * 4;
            *(float4*)(out + o) = acc;
            pack2h(acc.x, acc.y, hp + o);
            pack2h(acc.z, acc.w, hp + o + 2);
        }
    }
}

// ---------------- launch ------------------------------------------------------
extern "C" void kernel_launch(void* const* d_in, const int* in_sizes, int n_in,
                              void* d_out, int out_size) {
    const float* x    = (const float*)d_in[0];
    const int*   map  = (const int*)  d_in[1];
    const float* Wqkv = (const float*)d_in[2];
    const float* bqkv = (const float*)d_in[3];
    const float* Wout = (const float*)d_in[4];
    const float* bout = (const float*)d_in[5];
    const float* Wfc1 = (const float*)d_in[6];
    const float* bfc1 = (const float*)d_in[7];
    const float* Wfc2 = (const float*)d_in[8];
    const float* bfc2 = (const float*)d_in[9];
    const float* ln1g = (const float*)d_in[10];
    const float* ln1b = (const float*)d_in[11];
    const float* ln2g = (const float*)d_in[12];
    const float* ln2b = (const float*)d_in[13];
    const float* Aqkv = (const float*)d_in[14];
    const float* Bqkv = (const float*)d_in[15];
    const float* Aout = (const float*)d_in[16];
    const float* Bout = (const float*)d_in[17];
    const float* Afc1 = (const float*)d_in[18];
    const float* Bfc1 = (const float*)d_in[19];
    const float* Afc2 = (const float*)d_in[20];
    const float* Bfc2 = (const float*)d_in[21];
    float* out = (float*)d_out;

    float *p_qkv, *p_attn, *p_res2, *p_h1, *p_u;
    __half *p_Wh, *p_AS, *p_AL;
    cudaGetSymbolAddress((void**)&p_qkv,  g_qkv);
    cudaGetSymbolAddress((void**)&p_attn, g_attn);
    cudaGetSymbolAddress((void**)&p_res2, g_res2);
    cudaGetSymbolAddress((void**)&p_h1,   g_h1);
    cudaGetSymbolAddress((void**)&p_u,    g_u);
    cudaGetSymbolAddress((void**)&p_Wh,   g_Wh);
    cudaGetSymbolAddress((void**)&p_AS,   g_AS);
    cudaGetSymbolAddress((void**)&p_AL,   g_AL);

    cudaFuncSetAttribute(tc_gemm, cudaFuncAttributeMaxDynamicSharedMemorySize, SMEM_G);
    cudaFuncSetAttribute(attn3_kernel, cudaFuncAttributeMaxDynamicSharedMemorySize,
                         ATTN_SMEM);
    cudaFuncSetAttribute(lora_u_smem, cudaFuncAttributeMaxDynamicSharedMemorySize,
                         FFN_D * 4);

    // ---- weights -> fp16 ----
    cvt_h<<<4096, 256>>>(Wqkv, p_Wh + WOFF_QKV, (size_t)H3 * DIM / 4);
    cvt_h<<<4096, 256>>>(Wout, p_Wh + WOFF_OUT, (size_t)DIM * DIM / 4);
    cvt_h<<<4096, 256>>>(Wfc1, p_Wh + WOFF_FC1, (size_t)FFN_D * DIM / 4);
    cvt_h<<<4096, 256>>>(Wfc2, p_Wh + WOFF_FC2, (size_t)DIM * FFN_D / 4);

    // ---- attention block ----
    ln_fused<<<NT, 256>>>(x, ln1g, ln1b, Aqkv, map, p_AS, p_u);
    tc_gemm<<<dim3(H3 / BN, NT / BM), 256, SMEM_G>>>(
        p_AS, p_Wh + WOFF_QKV, bqkv, p_u, Bqkv, map,
        nullptr, p_qkv, nullptr, H3, DIM, 0);
    attn3_kernel<<<dim3(SEQ / TQ, NH, 2), 256, ATTN_SMEM>>>(p_qkv, p_attn, p_AS);
    lora_u_smem<<<NT, 256, DIM * 4>>>(p_attn, Aout, map, p_u, DIM);
    tc_gemm<<<dim3(DIM / BN, NT / BM), 256, SMEM_G>>>(
        p_AS, p_Wh + WOFF_OUT, bout, p_u, Bout, map,
        x, p_res2, nullptr, DIM, DIM, 0);
    // ---- FFN block ----
    ln_fused<<<NT, 256>>>(p_res2, ln2g, ln2b, Afc1, map, p_AS, p_u);
    tc_gemm<<<dim3(FFN_D / BN, NT / BM), 256, SMEM_G>>>(
        p_AS, p_Wh + WOFF_FC1, bfc1, p_u, Bfc1, map,
        nullptr, p_h1, p_AL, FFN_D, DIM, 1);
    lora_u_smem<<<NT, 256, FFN_D * 4>>>(p_h1, Afc2, map, p_u, FFN_D);
    tc_gemm<<<dim3(DIM / BN, NT / BM), 256, SMEM_G>>>(
        p_AL, p_Wh + WOFF_FC2, bfc2, p_u, Bfc2, map,
        p_res2, out, nullptr, DIM, FFN_D, 0);
}

// round 11
// speedup vs baseline: 4.7971x; 1.1831x over previous
#include <cuda_runtime.h>
#include <cuda_fp16.h>
#include <cstdint>
#include <cstddef>

#define DIM   4096
#define H3    12288
#define FFN_D 16384
#define NT    2048      // total tokens = 2*1024
#define LR    16        // lora rank
#define SEQ   1024
#define NH    32
#define HD    128

// ---------------- scratch (device globals; no allocations allowed) ----------
__device__ float g_qkv [(size_t)NT * H3];
__device__ float g_res2[(size_t)NT * DIM];
__device__ float g_u   [(size_t)NT * LR];

// fp16 weight plane + fp16 activation planes
#define WOFF_QKV 0
#define WOFF_OUT 50331648u
#define WOFF_FC1 67108864u
#define WOFF_FC2 134217728u
#define W_TOTAL  201326592u
__device__ __half g_Wh [W_TOTAL];
__device__ __half g_AS [(size_t)NT * DIM];
__device__ __half g_AL [(size_t)NT * FFN_D];

// ================= helpers ===================================================
__device__ __forceinline__ uint32_t smem_u32(const void* p) {
    uint32_t a;
    asm("{ .reg .u64 t; cvta.to.shared.u64 t, %1; cvt.u32.u64 %0, t; }"
        : "=r"(a) : "l"(p));
    return a;
}
__device__ __forceinline__ void ldmx4(uint32_t* r, uint32_t addr) {
    asm volatile("ldmatrix.sync.aligned.m8n8.x4.shared.b16 {%0,%1,%2,%3}, [%4];"
                 : "=r"(r[0]), "=r"(r[1]), "=r"(r[2]), "=r"(r[3]) : "r"(addr));
}
__device__ __forceinline__ uint32_t lds32(uint32_t addr) {
    uint32_t v;
    asm volatile("ld.shared.b32 %0, [%1];" : "=r"(v) : "r"(addr));
    return v;
}
__device__ __forceinline__ void mmaf16(float* d, const uint32_t* a,
                                       uint32_t b0, uint32_t b1) {
    asm volatile("mma.sync.aligned.m16n8k16.row.col.f32.f16.f16.f32 "
                 "{%0,%1,%2,%3}, {%4,%5,%6,%7}, {%8,%9}, {%0,%1,%2,%3};"
                 : "+f"(d[0]), "+f"(d[1]), "+f"(d[2]), "+f"(d[3])
                 : "r"(a[0]), "r"(a[1]), "r"(a[2]), "r"(a[3]),
                   "r"(b0), "r"(b1));
}
__device__ __forceinline__ void cpa16(uint32_t d, const void* s) {
    asm volatile("cp.async.ca.shared.global [%0], [%1], 16;"
                 :: "r"(d), "l"(s) : "memory");
}
__device__ __forceinline__ void cpa_commit() {
    asm volatile("cp.async.commit_group;" ::: "memory");
}
__device__ __forceinline__ void pack2h(float a, float b, __half* dst) {
    *(__half2*)dst = __halves2half2(__float2half_rn(a), __float2half_rn(b));
}

// ================= fused weight fp32 -> fp16 (all 4 mats, 1 launch) ===========
__global__ void cvt_all(const float* __restrict__ s0, const float* __restrict__ s1,
                        const float* __restrict__ s2, const float* __restrict__ s3,
                        __half* __restrict__ dst) {
    const size_t e0 = 12582912, e1 = 16777216, e2 = 33554432, e3 = 50331648;
    size_t i = (size_t)blockIdx.x * blockDim.x + threadIdx.x;
    size_t stride = (size_t)gridDim.x * blockDim.x;
    for (; i < e3; i += stride) {
        const float* src; size_t j;
        if (i < e0)      { src = s0; j = i; }
        else if (i < e1) { src = s1; j = i - e0; }
        else if (i < e2) { src = s2; j = i - e1; }
        else             { src = s3; j = i - e2; }
        float4 v = ((const float4*)src)[j];
        ((__half2*)dst)[i * 2]     = __halves2half2(__float2half_rn(v.x),
                                                    __float2half_rn(v.y));
        ((__half2*)dst)[i * 2 + 1] = __halves2half2(__float2half_rn(v.z),
                                                    __float2half_rn(v.w));
    }
}

// ================= fused LayerNorm + fp16 plane + lora-u ======================
__global__ void ln_fused(const float* __restrict__ x, const float* __restrict__ g,
                         const float* __restrict__ b, const float* __restrict__ A,
                         const int* __restrict__ map,
                         __half* __restrict__ hp, float* __restrict__ u) {
    __shared__ float row[DIM];
    __shared__ float rs[8], rs2[8];
    int t = blockIdx.x;
    int tid = threadIdx.x, lane = tid & 31, warp = tid >> 5;
    const float4* x4 = (const float4*)(x + (size_t)t * DIM);
    float4* row4 = (float4*)row;
    float s = 0.f, s2 = 0.f;
    #pragma unroll
    for (int p = 0; p < 4; p++) {
        int i = tid + p * 256;
        float4 v = x4[i];
        row4[i] = v;
        s += v.x + v.y + v.z + v.w;
        s2 += v.x * v.x + v.y * v.y + v.z * v.z + v.w * v.w;
    }
    #pragma unroll
    for (int o = 16; o; o >>= 1) {
        s  += __shfl_xor_sync(0xffffffffu, s,  o);
        s2 += __shfl_xor_sync(0xffffffffu, s2, o);
    }
    if (!lane) { rs[warp] = s; rs2[warp] = s2; }
    __syncthreads();
    s = 0.f; s2 = 0.f;
    #pragma unroll
    for (int w = 0; w < 8; w++) { s += rs[w]; s2 += rs2[w]; }
    float mean = s * (1.f / DIM);
    float var  = s2 * (1.f / DIM) - mean * mean;
    float rstd = rsqrtf(var + 1e-5f);
    __half* hr = hp + (size_t)t * DIM;
    const float4* g4 = (const float4*)g;
    const float4* b4 = (const float4*)b;
    #pragma unroll
    for (int p = 0; p < 4; p++) {
        int i = tid + p * 256;
        float4 v = row4[i], gv = g4[i], bv = b4[i];
        float4 nv;
        nv.x = (v.x - mean) * rstd * gv.x + bv.x;
        nv.y = (v.y - mean) * rstd * gv.y + bv.y;
        nv.z = (v.z - mean) * rstd * gv.z + bv.z;
        nv.w = (v.w - mean) * rstd * gv.w + bv.w;
        pack2h(nv.x, nv.y, hr + i * 4);
        pack2h(nv.z, nv.w, hr + i * 4 + 2);
        row4[i] = nv;
    }
    __syncthreads();
    int a = map[t];
    #pragma unroll
    for (int rr = 0; rr < 2; rr++) {
        int r = warp * 2 + rr;
        const float4* ar = (const float4*)(A + ((size_t)a * LR + r) * DIM);
        float acc = 0.f;
        #pragma unroll
        for (int p = 0; p < 32; p++) {
            int i = lane + p * 32;
            float4 av = ar[i], xv = row4[i];
            acc += av.x * xv.x + av.y * xv.y + av.z * xv.z + av.w * xv.w;
        }
        #pragma unroll
        for (int o = 16; o; o >>= 1) acc += __shfl_xor_sync(0xffffffffu, acc, o);
        if (!lane) u[t * LR + r] = acc;
    }
}

// ================= lora-u from fp16 plane, smem-staged ========================
__global__ void lora_u_smem_h(const __half* __restrict__ x,
                              const float* __restrict__ A,
                              const int* __restrict__ map,
                              float* __restrict__ u, int K) {
    extern __shared__ float srow[];
    int t = blockIdx.x;
    int tid = threadIdx.x, lane = tid & 31, warp = tid >> 5;
    const __half2* x2 = (const __half2*)(x + (size_t)t * K);
    int n2 = K >> 1;
    for (int i = tid; i < n2; i += 256)
        ((float2*)srow)[i] = __half22float2(x2[i]);
    __syncthreads();
    int a = map[t];
    const float4* s4 = (const float4*)srow;
    int n4 = K >> 2;
    #pragma unroll
    for (int rr = 0; rr < 2; rr++) {
        int r = warp * 2 + rr;
        const float4* ar = (const float4*)(A + ((size_t)a * LR + r) * K);
        float acc = 0.f;
        for (int i = lane; i < n4; i += 32) {
            float4 av = ar[i], xv = s4[i];
            acc += av.x * xv.x + av.y * xv.y + av.z * xv.z + av.w * xv.w;
        }
        #pragma unroll
        for (int o = 16; o; o >>= 1) acc += __shfl_xor_sync(0xffffffffu, acc, o);
        if (!lane) u[t * LR + r] = acc;
    }
}

// ================= tensor-core GEMM (fp16 x fp16, k-chunk 64, 2-stage) ========
#define BM 128
#define BN 128
#define RSTR 72                       // smem row stride in halves (144 B)
#define PLANE (128 * RSTR * 2)        // 18432 B per plane
#define STAGE_B (2 * PLANE)           // A | W = 36864
#define SOFF_BIAS  128
#define SOFF_STAGE 1024
#define SMEM_G (SOFF_STAGE + 2 * STAGE_B)   // 74752 (lora 64KB overlay fits)

__device__ __forceinline__ float dot16(const float* u, const float* b) {
    float s = 0.f;
    #pragma unroll
    for (int r = 0; r < 16; r++) s = fmaf(u[r], b[r], s);
    return s;
}

__device__ __forceinline__ void issue_chunk(
        const __half* __restrict__ Ah, const __half* __restrict__ W,
        int m0, int n0, int K, int c, uint32_t sdst, int tid) {
    int k0 = c * 64;
    #pragma unroll
    for (int p = 0; p < 4; p++) {
        int idx = tid + p * 256;
        int row = idx >> 3, seg = idx & 7;
        uint32_t d = sdst + row * (RSTR * 2) + seg * 16;
        cpa16(d,         Ah + (size_t)(m0 + row) * K + k0 + seg * 8);
        cpa16(d + PLANE, W  + (size_t)(n0 + row) * K + k0 + seg * 8);
    }
    cpa_commit();
}

__global__ void __launch_bounds__(256, 2)
tc_gemm(const __half* __restrict__ Ah, const __half* __restrict__ W,
        const float* __restrict__ bias, const float* __restrict__ u,
        const float* __restrict__ Bl, const int* __restrict__ map,
        const float* __restrict__ resid, float* __restrict__ C,
        __half* __restrict__ hOut, int N, int K, int relu) {
    extern __shared__ __align__(1024) char smem[];
    uint32_t sbase = smem_u32(smem);
    int tid = threadIdx.x;
    int lane = tid & 31, warp = tid >> 5;
    int wm = warp >> 2, wn = warp & 3;
    int n0 = blockIdx.x * BN;
    int m0 = blockIdx.y * BM;

    if (tid < BN) ((float*)(smem + SOFF_BIAS))[tid] = bias[n0 + tid];

    float acc[4][4][4];
    #pragma unroll
    for (int f = 0; f < 4; f++)
        #pragma unroll
        for (int g = 0; g < 4; g++)
            #pragma unroll
            for (int e = 0; e < 4; e++) acc[f][g][e] = 0.f;

    int nCh = K >> 6;
    issue_chunk(Ah, W, m0, n0, K, 0, sbase + SOFF_STAGE, tid);
    if (nCh > 1)
        issue_chunk(Ah, W, m0, n0, K, 1, sbase + SOFF_STAGE + STAGE_B, tid);

    int lane15 = lane & 15, laneHalf = lane >> 4;
    int grp = lane >> 2, tig = lane & 3;

    int stage = 0;
    for (int c = 0; c < nCh; c++) {
        if (c + 1 < nCh)
            asm volatile("cp.async.wait_group 1;" ::: "memory");
        else
            asm volatile("cp.async.wait_group 0;" ::: "memory");
        __syncthreads();

        uint32_t base = sbase + SOFF_STAGE + stage * STAGE_B;
        #pragma unroll
        for (int ks = 0; ks < 4; ks++) {
            uint32_t af[4][4];
            int koffA = ks * 16 + laneHalf * 8;
            #pragma unroll
            for (int f = 0; f < 4; f++) {
                int row = wm * 64 + f * 16 + lane15;
                ldmx4(af[f], base + row * (RSTR * 2) + koffA * 2);
            }
            #pragma unroll
            for (int g = 0; g < 4; g++) {
                int n = wn * 32 + g * 8 + grp;
                uint32_t bd = base + PLANE + n * (RSTR * 2)
                            + (ks * 16 + tig * 2) * 2;
                uint32_t w0 = lds32(bd), w1 = lds32(bd + 16);
                #pragma unroll
                for (int f = 0; f < 4; f++)
                    mmaf16(acc[f][g], af[f], w0, w1);
            }
        }
        __syncthreads();
        if (c + 2 < nCh)
            issue_chunk(Ah, W, m0, n0, K, c + 2,
                        sbase + SOFF_STAGE + stage * STAGE_B, tid);
        stage ^= 1;
    }

    // ---- stage lora-B slice into SMEM (overlays stages) ----
    float* Bs = (float*)(smem + SOFF_STAGE);
    for (int i = tid; i < 4096; i += 256) {
        int a   = i >> 9;
        int rem = i & 511;
        int nl  = rem >> 2;
        int sg  = rem & 3;
        float4 v = *(const float4*)(Bl + ((size_t)a * N + n0 + nl) * LR + sg * 4);
        *(float4*)(Bs + ((size_t)((a << 7) + nl)) * LR + sg * 4) = v;
    }
    __syncthreads();

    const float* biasS = (const float*)(smem + SOFF_BIAS);
    #pragma unroll
    for (int f = 0; f < 4; f++) {
        int r0 = m0 + wm * 64 + f * 16 + grp;
        int r1 = r0 + 8;
        int a0 = map[r0], a1 = map[r1];
        float u0[16], u1[16];
        {
            const float4* p0 = (const float4*)(u + (size_t)r0 * LR);
            const float4* p1 = (const float4*)(u + (size_t)r1 * LR);
            #pragma unroll
            for (int q = 0; q < 4; q++) {
                float4 v0 = p0[q], v1 = p1[q];
                u0[q*4+0]=v0.x; u0[q*4+1]=v0.y; u0[q*4+2]=v0.z; u0[q*4+3]=v0.w;
                u1[q*4+0]=v1.x; u1[q*4+1]=v1.y; u1[q*4+2]=v1.z; u1[q*4+3]=v1.w;
            }
        }
        #pragma unroll
        for (int g = 0; g < 4; g++) {
            int nl = wn * 32 + g * 8 + tig * 2;
            float v00 = acc[f][g][0] + biasS[nl]
                      + dot16(u0, Bs + ((size_t)((a0 << 7) + nl)) * LR);
            float v01 = acc[f][g][1] + biasS[nl + 1]
                      + dot16(u0, Bs + ((size_t)((a0 << 7) + nl + 1)) * LR);
            float v10 = acc[f][g][2] + biasS[nl]
                      + dot16(u1, Bs + ((size_t)((a1 << 7) + nl)) * LR);
            float v11 = acc[f][g][3] + biasS[nl + 1]
                      + dot16(u1, Bs + ((size_t)((a1 << 7) + nl + 1)) * LR);
            size_t o0 = (size_t)r0 * N + n0 + nl;
            size_t o1 = (size_t)r1 * N + n0 + nl;
            if (resid) {
                float2 q0 = *(const float2*)(resid + o0);
                float2 q1 = *(const float2*)(resid + o1);
                v00 += q0.x; v01 += q0.y; v10 += q1.x; v11 += q1.y;
            }
            if (relu) {
                v00 = fmaxf(v00, 0.f); v01 = fmaxf(v01, 0.f);
                v10 = fmaxf(v10, 0.f); v11 = fmaxf(v11, 0.f);
            }
            if (C) {
                *(float2*)(C + o0) = make_float2(v00, v01);
                *(float2*)(C + o1) = make_float2(v10, v11);
            }
            if (hOut) {
                pack2h(v00, v01, hOut + o0);
                pack2h(v10, v11, hOut + o1);
            }
        }
    }
}

// ================= attention: fp16-MMA scores, fp32 softmax/PV ================
#define TQ 16
// smem bytes: sc fp32 16x1024 | qh 16x136 h | kh 64x136 h | sinv 16 f
#define ATT_SC 0
#define ATT_QH 65536
#define ATT_KH 69888
#define ATT_SV 87296
#define ATTN_SMEM 87360

__global__ void __launch_bounds__(256, 2)
attn4_kernel(const float* __restrict__ qkv, __half* __restrict__ hp) {
    extern __shared__ __align__(1024) char smemA[];
    float*  sc   = (float*)(smemA + ATT_SC);
    __half* qh   = (__half*)(smemA + ATT_QH);
    __half* kh   = (__half*)(smemA + ATT_KH);
    float*  sinv = (float*)(smemA + ATT_SV);
    int qt = blockIdx.x, h = blockIdx.y, bb = blockIdx.z;
    int q0 = qt * TQ;
    int tid = threadIdx.x, lane = tid & 31, warp = tid >> 5;
    int lane15 = lane & 15, laneHalf = lane >> 4;
    int grp = lane >> 2, tig = lane & 3;
    const size_t base = (size_t)bb * SEQ * H3;
    const float scale = 0.08838834764831845f;

    // stage Q tile fp16: 16 rows x 128 dims
    #pragma unroll
    for (int p = 0; p < 2; p++) {
        int i = tid + p * 256;
        int r = i >> 5, d4 = i & 31;
        float4 v = *(const float4*)(qkv + base + (size_t)(q0 + r) * H3
                                    + h * HD + d4 * 4);
        __half* dst = qh + r * 136 + d4 * 4;
        pack2h(v.x, v.y, dst);
        pack2h(v.z, v.w, dst + 2);
    }
    __syncthreads();
    uint32_t qaddr = smem_u32(qh);
    uint32_t qf[8][4];
    #pragma unroll
    for (int ks = 0; ks < 8; ks++)
        ldmx4(qf[ks], qaddr + lane15 * 272 + (ks * 16 + laneHalf * 8) * 2);

    uint32_t kaddr = smem_u32(kh);
    int nkmax = q0 + TQ;
    for (int kb = 0; kb < nkmax; kb += 64) {
        __syncthreads();    // kh reuse: prior chunk's MMAs complete
        #pragma unroll
        for (int p = 0; p < 8; p++) {
            int i = tid + p * 256;
            int r = i >> 5, d4 = i & 31;
            if (kb + r < nkmax) {
                float4 v = *(const float4*)(qkv + base + (size_t)(kb + r) * H3
                                            + DIM + h * HD + d4 * 4);
                __half* dst = kh + r * 136 + d4 * 4;
                pack2h(v.x, v.y, dst);
                pack2h(v.z, v.w, dst + 2);
            }
        }
        __syncthreads();
        float sacc[4] = {0.f, 0.f, 0.f, 0.f};
        #pragma unroll
        for (int ks = 0; ks < 8; ks++) {
            uint32_t bd = kaddr + (warp * 8 + grp) * 272
                        + (ks * 16 + tig * 2) * 2;
            uint32_t w0 = lds32(bd), w1 = lds32(bd + 16);
            mmaf16(sacc, qf[ks], w0, w1);
        }
        int kcol = kb + warp * 8 + tig * 2;
        sc[grp * SEQ + kcol]           = sacc[0] * scale;
        sc[grp * SEQ + kcol + 1]       = sacc[1] * scale;
        sc[(grp + 8) * SEQ + kcol]     = sacc[2] * scale;
        sc[(grp + 8) * SEQ + kcol + 1] = sacc[3] * scale;
    }
    __syncthreads();

    // softmax: warp w handles rows w and w+8
    #pragma unroll
    for (int rr = 0; rr < 2; rr++) {
        int row = warp + rr * 8;
        int nk = q0 + row + 1;
        float* sr = sc + row * SEQ;
        float mx = -1e30f;
        for (int j = lane; j < nk; j += 32) mx = fmaxf(mx, sr[j]);
        #pragma unroll
        for (int o = 16; o; o >>= 1)
            mx = fmaxf(mx, __shfl_xor_sync(0xffffffffu, mx, o));
        float sum = 0.f;
        for (int j = lane; j < nk; j += 32) {
            float e = __expf(sr[j] - mx);
            sr[j] = e;
            sum += e;
        }
        #pragma unroll
        for (int o = 16; o; o >>= 1) sum += __shfl_xor_sync(0xffffffffu, sum, o);
        if (!lane) sinv[row] = 1.f / sum;
    }
    __syncthreads();

    // PV: warp rp owns rows rp, rp+8; lane owns 4 dims; fp16 plane out only
    {
        int d4 = lane, rp = warp;
        const float* vb = qkv + base + 2 * DIM + h * HD + d4 * 4;
        #pragma unroll
        for (int rr = 0; rr < 2; rr++) {
            int row = rp + rr * 8;
            int nk = q0 + row + 1;
            const float* sr = sc + row * SEQ;
            float4 acc = make_float4(0.f, 0.f, 0.f, 0.f);
            int j = 0;
            for (; j + 2 <= nk; j += 2) {
                float p0 = sr[j], p1 = sr[j + 1];
                float4 v0 = *(const float4*)(vb + (size_t)j * H3);
                float4 v1 = *(const float4*)(vb + (size_t)(j + 1) * H3);
                acc.x += p0 * v0.x + p1 * v1.x;
                acc.y += p0 * v0.y + p1 * v1.y;
                acc.z += p0 * v0.z + p1 * v1.z;
                acc.w += p0 * v0.w + p1 * v1.w;
            }
            if (j < nk) {
                float p0 = sr[j];
                float4 v0 = *(const float4*)(vb + (size_t)j * H3);
                acc.x += p0 * v0.x; acc.y += p0 * v0.y;
                acc.z += p0 * v0.z; acc.w += p0 * v0.w;
            }
            float iv = sinv[row];
            acc.x *= iv; acc.y *= iv; acc.z *= iv; acc.w *= iv;
            size_t o = ((size_t)bb * SEQ + q0 + row) * DIM + h * HD + d4 * 4;
            pack2h(acc.x, acc.y, hp + o);
            pack2h(acc.z, acc.w, hp + o + 2);
        }
    }
}

// ---------------- launch ------------------------------------------------------
extern "C" void kernel_launch(void* const* d_in, const int* in_sizes, int n_in,
                              void* d_out, int out_size) {
    const float* x    = (const float*)d_in[0];
    const int*   map  = (const int*)  d_in[1];
    const float* Wqkv = (const float*)d_in[2];
    const float* bqkv = (const float*)d_in[3];
    const float* Wout = (const float*)d_in[4];
    const float* bout = (const float*)d_in[5];
    const float* Wfc1 = (const float*)d_in[6];
    const float* bfc1 = (const float*)d_in[7];
    const float* Wfc2 = (const float*)d_in[8];
    const float* bfc2 = (const float*)d_in[9];
    const float* ln1g = (const float*)d_in[10];
    const float* ln1b = (const float*)d_in[11];
    const float* ln2g = (const float*)d_in[12];
    const float* ln2b = (const float*)d_in[13];
    const float* Aqkv = (const float*)d_in[14];
    const float* Bqkv = (const float*)d_in[15];
    const float* Aout = (const float*)d_in[16];
    const float* Bout = (const float*)d_in[17];
    const float* Afc1 = (const float*)d_in[18];
    const float* Bfc1 = (const float*)d_in[19];
    const float* Afc2 = (const float*)d_in[20];
    const float* Bfc2 = (const float*)d_in[21];
    float* out = (float*)d_out;

    float *p_qkv, *p_res2, *p_u;
    __half *p_Wh, *p_AS, *p_AL;
    cudaGetSymbolAddress((void**)&p_qkv,  g_qkv);
    cudaGetSymbolAddress((void**)&p_res2, g_res2);
    cudaGetSymbolAddress((void**)&p_u,    g_u);
    cudaGetSymbolAddress((void**)&p_Wh,   g_Wh);
    cudaGetSymbolAddress((void**)&p_AS,   g_AS);
    cudaGetSymbolAddress((void**)&p_AL,   g_AL);

    cudaFuncSetAttribute(tc_gemm, cudaFuncAttributeMaxDynamicSharedMemorySize, SMEM_G);
    cudaFuncSetAttribute(attn4_kernel, cudaFuncAttributeMaxDynamicSharedMemorySize,
                         ATTN_SMEM);
    cudaFuncSetAttribute(lora_u_smem_h, cudaFuncAttributeMaxDynamicSharedMemorySize,
                         FFN_D * 4);

    // ---- all weights -> fp16 (one launch) ----
    cvt_all<<<8192, 256>>>(Wqkv, Wout, Wfc1, Wfc2, p_Wh);

    // ---- attention block ----
    ln_fused<<<NT, 256>>>(x, ln1g, ln1b, Aqkv, map, p_AS, p_u);
    tc_gemm<<<dim3(H3 / BN, NT / BM), 256, SMEM_G>>>(
        p_AS, p_Wh + WOFF_QKV, bqkv, p_u, Bqkv, map,
        nullptr, p_qkv, nullptr, H3, DIM, 0);
    attn4_kernel<<<dim3(SEQ / TQ, NH, 2), 256, ATTN_SMEM>>>(p_qkv, p_AS);
    lora_u_smem_h<<<NT, 256, DIM * 4>>>(p_AS, Aout, map, p_u, DIM);
    tc_gemm<<<dim3(DIM / BN, NT / BM), 256, SMEM_G>>>(
        p_AS, p_Wh + WOFF_OUT, bout, p_u, Bout, map,
        x, p_res2, nullptr, DIM, DIM, 0);
    // ---- FFN block ----
    ln_fused<<<NT, 256>>>(p_res2, ln2g, ln2b, Afc1, map, p_AS, p_u);
    tc_gemm<<<dim3(FFN_D / BN, NT / BM), 256, SMEM_G>>>(
        p_AS, p_Wh + WOFF_FC1, bfc1, p_u, Bfc1, map,
        nullptr, nullptr, p_AL, FFN_D, DIM, 1);
    lora_u_smem_h<<<NT, 256, FFN_D * 4>>>(p_AL, Afc2, map, p_u, FFN_D);
    tc_gemm<<<dim3(DIM / BN, NT / BM), 256, SMEM_G>>>(
        p_AL, p_Wh + WOFF_FC2, bfc2, p_u, Bfc2, map,
        p_res2, out, nullptr, DIM, FFN_D, 0);
}

// round 12
// speedup vs baseline: 5.1090x; 1.0650x over previous
#include <cuda_runtime.h>
#include <cuda_fp16.h>
#include <cstdint>
#include <cstddef>

#define DIM   4096
#define H3    12288
#define FFN_D 16384
#define NT    2048      // total tokens = 2*1024
#define LR    16        // lora rank
#define SEQ   1024
#define NH    32
#define HD    128

// ---------------- scratch (device globals; no allocations allowed) ----------
__device__ float g_qkv [(size_t)NT * H3];
__device__ float g_res2[(size_t)NT * DIM];
__device__ float g_u   [(size_t)NT * LR];

// fp16 weight plane + fp16 activation planes
#define WOFF_QKV 0
#define WOFF_OUT 50331648u
#define WOFF_FC1 67108864u
#define WOFF_FC2 134217728u
#define W_TOTAL  201326592u
__device__ __half g_Wh [W_TOTAL];
__device__ __half g_AS [(size_t)NT * DIM];
__device__ __half g_AL [(size_t)NT * FFN_D];

// ================= helpers ===================================================
__device__ __forceinline__ uint32_t smem_u32(const void* p) {
    uint32_t a;
    asm("{ .reg .u64 t; cvta.to.shared.u64 t, %1; cvt.u32.u64 %0, t; }"
        : "=r"(a) : "l"(p));
    return a;
}
__device__ __forceinline__ void ldmx4(uint32_t* r, uint32_t addr) {
    asm volatile("ldmatrix.sync.aligned.m8n8.x4.shared.b16 {%0,%1,%2,%3}, [%4];"
                 : "=r"(r[0]), "=r"(r[1]), "=r"(r[2]), "=r"(r[3]) : "r"(addr));
}
__device__ __forceinline__ void ldmx4t(uint32_t* r, uint32_t addr) {
    asm volatile("ldmatrix.sync.aligned.m8n8.x4.trans.shared.b16 {%0,%1,%2,%3}, [%4];"
                 : "=r"(r[0]), "=r"(r[1]), "=r"(r[2]), "=r"(r[3]) : "r"(addr));
}
__device__ __forceinline__ uint32_t lds32(uint32_t addr) {
    uint32_t v;
    asm volatile("ld.shared.b32 %0, [%1];" : "=r"(v) : "r"(addr));
    return v;
}
__device__ __forceinline__ void mmaf16(float* d, const uint32_t* a,
                                       uint32_t b0, uint32_t b1) {
    asm volatile("mma.sync.aligned.m16n8k16.row.col.f32.f16.f16.f32 "
                 "{%0,%1,%2,%3}, {%4,%5,%6,%7}, {%8,%9}, {%0,%1,%2,%3};"
                 : "+f"(d[0]), "+f"(d[1]), "+f"(d[2]), "+f"(d[3])
                 : "r"(a[0]), "r"(a[1]), "r"(a[2]), "r"(a[3]),
                   "r"(b0), "r"(b1));
}
__device__ __forceinline__ void cpa16(uint32_t d, const void* s) {
    asm volatile("cp.async.ca.shared.global [%0], [%1], 16;"
                 :: "r"(d), "l"(s) : "memory");
}
__device__ __forceinline__ void cpa_commit() {
    asm volatile("cp.async.commit_group;" ::: "memory");
}
__device__ __forceinline__ void pack2h(float a, float b, __half* dst) {
    *(__half2*)dst = __halves2half2(__float2half_rn(a), __float2half_rn(b));
}

// ================= fused weight fp32 -> fp16 (all 4 mats, 1 launch) ===========
__global__ void cvt_all(const float* __restrict__ s0, const float* __restrict__ s1,
                        const float* __restrict__ s2, const float* __restrict__ s3,
                        __half* __restrict__ dst) {
    const size_t e0 = 12582912, e1 = 16777216, e2 = 33554432, e3 = 50331648;
    size_t i = (size_t)blockIdx.x * blockDim.x + threadIdx.x;
    size_t stride = (size_t)gridDim.x * blockDim.x;
    for (; i < e3; i += stride) {
        const float* src; size_t j;
        if (i < e0)      { src = s0; j = i; }
        else if (i < e1) { src = s1; j = i - e0; }
        else if (i < e2) { src = s2; j = i - e1; }
        else             { src = s3; j = i - e2; }
        float4 v = ((const float4*)src)[j];
        ((__half2*)dst)[i * 2]     = __halves2half2(__float2half_rn(v.x),
                                                    __float2half_rn(v.y));
        ((__half2*)dst)[i * 2 + 1] = __halves2half2(__float2half_rn(v.z),
                                                    __float2half_rn(v.w));
    }
}

// ================= fused LayerNorm + fp16 plane + lora-u ======================
__global__ void ln_fused(const float* __restrict__ x, const float* __restrict__ g,
                         const float* __restrict__ b, const float* __restrict__ A,
                         const int* __restrict__ map,
                         __half* __restrict__ hp, float* __restrict__ u) {
    __shared__ float row[DIM];
    __shared__ float rs[8], rs2[8];
    int t = blockIdx.x;
    int tid = threadIdx.x, lane = tid & 31, warp = tid >> 5;
    const float4* x4 = (const float4*)(x + (size_t)t * DIM);
    float4* row4 = (float4*)row;
    float s = 0.f, s2 = 0.f;
    #pragma unroll
    for (int p = 0; p < 4; p++) {
        int i = tid + p * 256;
        float4 v = x4[i];
        row4[i] = v;
        s += v.x + v.y + v.z + v.w;
        s2 += v.x * v.x + v.y * v.y + v.z * v.z + v.w * v.w;
    }
    #pragma unroll
    for (int o = 16; o; o >>= 1) {
        s  += __shfl_xor_sync(0xffffffffu, s,  o);
        s2 += __shfl_xor_sync(0xffffffffu, s2, o);
    }
    if (!lane) { rs[warp] = s; rs2[warp] = s2; }
    __syncthreads();
    s = 0.f; s2 = 0.f;
    #pragma unroll
    for (int w = 0; w < 8; w++) { s += rs[w]; s2 += rs2[w]; }
    float mean = s * (1.f / DIM);
    float var  = s2 * (1.f / DIM) - mean * mean;
    float rstd = rsqrtf(var + 1e-5f);
    __half* hr = hp + (size_t)t * DIM;
    const float4* g4 = (const float4*)g;
    const float4* b4 = (const float4*)b;
    #pragma unroll
    for (int p = 0; p < 4; p++) {
        int i = tid + p * 256;
        float4 v = row4[i], gv = g4[i], bv = b4[i];
        float4 nv;
        nv.x = (v.x - mean) * rstd * gv.x + bv.x;
        nv.y = (v.y - mean) * rstd * gv.y + bv.y;
        nv.z = (v.z - mean) * rstd * gv.z + bv.z;
        nv.w = (v.w - mean) * rstd * gv.w + bv.w;
        pack2h(nv.x, nv.y, hr + i * 4);
        pack2h(nv.z, nv.w, hr + i * 4 + 2);
        row4[i] = nv;
    }
    __syncthreads();
    int a = map[t];
    #pragma unroll
    for (int rr = 0; rr < 2; rr++) {
        int r = warp * 2 + rr;
        const float4* ar = (const float4*)(A + ((size_t)a * LR + r) * DIM);
        float acc = 0.f;
        #pragma unroll
        for (int p = 0; p < 32; p++) {
            int i = lane + p * 32;
            float4 av = ar[i], xv = row4[i];
            acc += av.x * xv.x + av.y * xv.y + av.z * xv.z + av.w * xv.w;
        }
        #pragma unroll
        for (int o = 16; o; o >>= 1) acc += __shfl_xor_sync(0xffffffffu, acc, o);
        if (!lane) u[t * LR + r] = acc;
    }
}

// ================= lora-u from fp16 plane, smem-staged ========================
__global__ void lora_u_smem_h(const __half* __restrict__ x,
                              const float* __restrict__ A,
                              const int* __restrict__ map,
                              float* __restrict__ u, int K) {
    extern __shared__ float srow[];
    int t = blockIdx.x;
    int tid = threadIdx.x, lane = tid & 31, warp = tid >> 5;
    const __half2* x2 = (const __half2*)(x + (size_t)t * K);
    int n2 = K >> 1;
    for (int i = tid; i < n2; i += 256)
        ((float2*)srow)[i] = __half22float2(x2[i]);
    __syncthreads();
    int a = map[t];
    const float4* s4 = (const float4*)srow;
    int n4 = K >> 2;
    #pragma unroll
    for (int rr = 0; rr < 2; rr++) {
        int r = warp * 2 + rr;
        const float4* ar = (const float4*)(A + ((size_t)a * LR + r) * K);
        float acc = 0.f;
        for (int i = lane; i < n4; i += 32) {
            float4 av = ar[i], xv = s4[i];
            acc += av.x * xv.x + av.y * xv.y + av.z * xv.z + av.w * xv.w;
        }
        #pragma unroll
        for (int o = 16; o; o >>= 1) acc += __shfl_xor_sync(0xffffffffu, acc, o);
        if (!lane) u[t * LR + r] = acc;
    }
}

// ================= tensor-core GEMM (fp16 x fp16, k-chunk 64, 2-stage) ========
#define BM 128
#define BN 128
#define RSTR 72                       // smem row stride in halves (144 B)
#define PLANE (128 * RSTR * 2)        // 18432 B per plane
#define STAGE_B (2 * PLANE)           // A | W = 36864
#define SOFF_BIAS  128
#define SOFF_STAGE 1024
#define SMEM_G (SOFF_STAGE + 2 * STAGE_B)   // 74752

__device__ __forceinline__ float dot16(const float* u, const float* b) {
    float s = 0.f;
    #pragma unroll
    for (int r = 0; r < 16; r++) s = fmaf(u[r], b[r], s);
    return s;
}

__device__ __forceinline__ void issue_chunk(
        const __half* __restrict__ Ah, const __half* __restrict__ W,
        int m0, int n0, int K, int c, uint32_t sdst, int tid) {
    int k0 = c * 64;
    #pragma unroll
    for (int p = 0; p < 4; p++) {
        int idx = tid + p * 256;
        int row = idx >> 3, seg = idx & 7;
        uint32_t d = sdst + row * (RSTR * 2) + seg * 16;
        cpa16(d,         Ah + (size_t)(m0 + row) * K + k0 + seg * 8);
        cpa16(d + PLANE, W  + (size_t)(n0 + row) * K + k0 + seg * 8);
    }
    cpa_commit();
}

__global__ void __launch_bounds__(256, 2)
tc_gemm(const __half* __restrict__ Ah, const __half* __restrict__ W,
        const float* __restrict__ bias, const float* __restrict__ u,
        const float* __restrict__ Bl, const int* __restrict__ map,
        const float* __restrict__ resid, float* __restrict__ C,
        __half* __restrict__ hOut, int N, int K, int relu) {
    extern __shared__ __align__(1024) char smem[];
    uint32_t sbase = smem_u32(smem);
    int tid = threadIdx.x;
    int lane = tid & 31, warp = tid >> 5;
    int wm = warp >> 2, wn = warp & 3;
    int n0 = blockIdx.x * BN;
    int m0 = blockIdx.y * BM;

    if (tid < BN) ((float*)(smem + SOFF_BIAS))[tid] = bias[n0 + tid];

    float acc[4][4][4];
    #pragma unroll
    for (int f = 0; f < 4; f++)
        #pragma unroll
        for (int g = 0; g < 4; g++)
            #pragma unroll
            for (int e = 0; e < 4; e++) acc[f][g][e] = 0.f;

    int nCh = K >> 6;
    issue_chunk(Ah, W, m0, n0, K, 0, sbase + SOFF_STAGE, tid);
    if (nCh > 1)
        issue_chunk(Ah, W, m0, n0, K, 1, sbase + SOFF_STAGE + STAGE_B, tid);

    int lane15 = lane & 15, laneHalf = lane >> 4;
    int grp = lane >> 2, tig = lane & 3;

    int stage = 0;
    for (int c = 0; c < nCh; c++) {
        if (c + 1 < nCh)
            asm volatile("cp.async.wait_group 1;" ::: "memory");
        else
            asm volatile("cp.async.wait_group 0;" ::: "memory");
        __syncthreads();

        uint32_t base = sbase + SOFF_STAGE + stage * STAGE_B;
        #pragma unroll
        for (int ks = 0; ks < 4; ks++) {
            uint32_t af[4][4];
            int koffA = ks * 16 + laneHalf * 8;
            #pragma unroll
            for (int f = 0; f < 4; f++) {
                int row = wm * 64 + f * 16 + lane15;
                ldmx4(af[f], base + row * (RSTR * 2) + koffA * 2);
            }
            #pragma unroll
            for (int g = 0; g < 4; g++) {
                int n = wn * 32 + g * 8 + grp;
                uint32_t bd = base + PLANE + n * (RSTR * 2)
                            + (ks * 16 + tig * 2) * 2;
                uint32_t w0 = lds32(bd), w1 = lds32(bd + 16);
                #pragma unroll
                for (int f = 0; f < 4; f++)
                    mmaf16(acc[f][g], af[f], w0, w1);
            }
        }
        __syncthreads();
        if (c + 2 < nCh)
            issue_chunk(Ah, W, m0, n0, K, c + 2,
                        sbase + SOFF_STAGE + stage * STAGE_B, tid);
        stage ^= 1;
    }

    // ---- stage lora-B slice into SMEM (overlays stages) ----
    float* Bs = (float*)(smem + SOFF_STAGE);
    for (int i = tid; i < 4096; i += 256) {
        int a   = i >> 9;
        int rem = i & 511;
        int nl  = rem >> 2;
        int sg  = rem & 3;
        float4 v = *(const float4*)(Bl + ((size_t)a * N + n0 + nl) * LR + sg * 4);
        *(float4*)(Bs + ((size_t)((a << 7) + nl)) * LR + sg * 4) = v;
    }
    __syncthreads();

    const float* biasS = (const float*)(smem + SOFF_BIAS);
    #pragma unroll
    for (int f = 0; f < 4; f++) {
        int r0 = m0 + wm * 64 + f * 16 + grp;
        int r1 = r0 + 8;
        int a0 = map[r0], a1 = map[r1];
        float u0[16], u1[16];
        {
            const float4* p0 = (const float4*)(u + (size_t)r0 * LR);
            const float4* p1 = (const float4*)(u + (size_t)r1 * LR);
            #pragma unroll
            for (int q = 0; q < 4; q++) {
                float4 v0 = p0[q], v1 = p1[q];
                u0[q*4+0]=v0.x; u0[q*4+1]=v0.y; u0[q*4+2]=v0.z; u0[q*4+3]=v0.w;
                u1[q*4+0]=v1.x; u1[q*4+1]=v1.y; u1[q*4+2]=v1.z; u1[q*4+3]=v1.w;
            }
        }
        #pragma unroll
        for (int g = 0; g < 4; g++) {
            int nl = wn * 32 + g * 8 + tig * 2;
            float v00 = acc[f][g][0] + biasS[nl]
                      + dot16(u0, Bs + ((size_t)((a0 << 7) + nl)) * LR);
            float v01 = acc[f][g][1] + biasS[nl + 1]
                      + dot16(u0, Bs + ((size_t)((a0 << 7) + nl + 1)) * LR);
            float v10 = acc[f][g][2] + biasS[nl]
                      + dot16(u1, Bs + ((size_t)((a1 << 7) + nl)) * LR);
            float v11 = acc[f][g][3] + biasS[nl + 1]
                      + dot16(u1, Bs + ((size_t)((a1 << 7) + nl + 1)) * LR);
            size_t o0 = (size_t)r0 * N + n0 + nl;
            size_t o1 = (size_t)r1 * N + n0 + nl;
            if (resid) {
                float2 q0 = *(const float2*)(resid + o0);
                float2 q1 = *(const float2*)(resid + o1);
                v00 += q0.x; v01 += q0.y; v10 += q1.x; v11 += q1.y;
            }
            if (relu) {
                v00 = fmaxf(v00, 0.f); v01 = fmaxf(v01, 0.f);
                v10 = fmaxf(v10, 0.f); v11 = fmaxf(v11, 0.f);
            }
            if (C) {
                *(float2*)(C + o0) = make_float2(v00, v01);
                *(float2*)(C + o1) = make_float2(v10, v11);
            }
            if (hOut) {
                pack2h(v00, v01, hOut + o0);
                pack2h(v10, v11, hOut + o1);
            }
        }
    }
}

// ================= attention: fp16-MMA scores AND PV ==========================
#define TQ 16
// smem: sc fp32 16x1024 (64K) | pT fp16 1024x16 (32K) | kv fp16 64x136 (17.4K)
//       | qh fp16 16x136 (4.35K) | sinv 16 f
#define ATT_SC 0
#define ATT_PT 65536
#define ATT_KV 98304
#define ATT_QH 115712
#define ATT_SV 120064
#define ATTN_SMEM 120192

__global__ void __launch_bounds__(256, 1)
attn5_kernel(const float* __restrict__ qkv, __half* __restrict__ hp) {
    extern __shared__ __align__(1024) char smemA[];
    float*  sc   = (float*)(smemA + ATT_SC);
    __half* pT   = (__half*)(smemA + ATT_PT);
    __half* kv   = (__half*)(smemA + ATT_KV);
    __half* qh   = (__half*)(smemA + ATT_QH);
    float*  sinv = (float*)(smemA + ATT_SV);
    int qt = blockIdx.x, h = blockIdx.y, bb = blockIdx.z;
    int q0 = qt * TQ;
    int tid = threadIdx.x, lane = tid & 31, warp = tid >> 5;
    int lane15 = lane & 15, laneHalf = lane >> 4;
    int grp = lane >> 2, tig = lane & 3;
    const size_t base = (size_t)bb * SEQ * H3;
    const float scale = 0.08838834764831845f;

    // stage Q tile fp16: 16 rows x 128 dims
    #pragma unroll
    for (int p = 0; p < 2; p++) {
        int i = tid + p * 256;
        int r = i >> 5, d4 = i & 31;
        float4 v = *(const float4*)(qkv + base + (size_t)(q0 + r) * H3
                                    + h * HD + d4 * 4);
        __half* dst = qh + r * 136 + d4 * 4;
        pack2h(v.x, v.y, dst);
        pack2h(v.z, v.w, dst + 2);
    }
    __syncthreads();
    uint32_t qaddr = smem_u32(qh);
    uint32_t qf[8][4];
    #pragma unroll
    for (int ks = 0; ks < 8; ks++)
        ldmx4(qf[ks], qaddr + lane15 * 272 + (ks * 16 + laneHalf * 8) * 2);

    uint32_t kvaddr = smem_u32(kv);
    int nkmax = q0 + TQ;
    // ---- score phase: K chunks of 64, warp owns 8 keys ----
    for (int kb = 0; kb < nkmax; kb += 64) {
        __syncthreads();
        #pragma unroll
        for (int p = 0; p < 8; p++) {
            int i = tid + p * 256;
            int r = i >> 5, d4 = i & 31;
            if (kb + r < nkmax) {
                float4 v = *(const float4*)(qkv + base + (size_t)(kb + r) * H3
                                            + DIM + h * HD + d4 * 4);
                __half* dst = kv + r * 136 + d4 * 4;
                pack2h(v.x, v.y, dst);
                pack2h(v.z, v.w, dst + 2);
            }
        }
        __syncthreads();
        float sacc[4] = {0.f, 0.f, 0.f, 0.f};
        #pragma unroll
        for (int ks = 0; ks < 8; ks++) {
            uint32_t bd = kvaddr + (warp * 8 + grp) * 272
                        + (ks * 16 + tig * 2) * 2;
            uint32_t w0 = lds32(bd), w1 = lds32(bd + 16);
            mmaf16(sacc, qf[ks], w0, w1);
        }
        int kcol = kb + warp * 8 + tig * 2;
        sc[grp * SEQ + kcol]           = sacc[0] * scale;
        sc[grp * SEQ + kcol + 1]       = sacc[1] * scale;
        sc[(grp + 8) * SEQ + kcol]     = sacc[2] * scale;
        sc[(grp + 8) * SEQ + kcol + 1] = sacc[3] * scale;
    }
    __syncthreads();

    int nkceil = (nkmax + 63) & ~63;
    // ---- softmax: warp w rows w, w+8; write fp16 P transposed into pT ----
    #pragma unroll
    for (int rr = 0; rr < 2; rr++) {
        int row = warp + rr * 8;
        int nk = q0 + row + 1;
        float* sr = sc + row * SEQ;
        float mx = -1e30f;
        for (int j = lane; j < nk; j += 32) mx = fmaxf(mx, sr[j]);
        #pragma unroll
        for (int o = 16; o; o >>= 1)
            mx = fmaxf(mx, __shfl_xor_sync(0xffffffffu, mx, o));
        float sum = 0.f;
        for (int j = lane; j < nkceil; j += 32) {
            __half ph;
            if (j < nk) {
                float e = __expf(sr[j] - mx);
                sum += e;
                ph = __float2half(e);
            } else ph = __float2half(0.f);
            pT[j * 16 + row] = ph;
        }
        #pragma unroll
        for (int o = 16; o; o >>= 1) sum += __shfl_xor_sync(0xffffffffu, sum, o);
        if (!lane) sinv[row] = 1.f / sum;
    }
    __syncthreads();

    // ---- PV phase: warp owns dims [warp*16, warp*16+16) ----
    uint32_t ptaddr = smem_u32(pT);
    float acc0[4] = {0.f, 0.f, 0.f, 0.f};
    float acc1[4] = {0.f, 0.f, 0.f, 0.f};
    for (int kb = 0; kb < nkceil; kb += 64) {
        __syncthreads();     // kv reuse: prior chunk MMAs complete
        #pragma unroll
        for (int p = 0; p < 8; p++) {
            int i = tid + p * 256;
            int r = i >> 5, d4 = i & 31;
            __half* dst = kv + r * 136 + d4 * 4;
            if (kb + r < nkmax) {
                float4 v = *(const float4*)(qkv + base + (size_t)(kb + r) * H3
                                            + 2 * DIM + h * HD + d4 * 4);
                pack2h(v.x, v.y, dst);
                pack2h(v.z, v.w, dst + 2);
            } else {
                pack2h(0.f, 0.f, dst);
                pack2h(0.f, 0.f, dst + 2);
            }
        }
        __syncthreads();
        #pragma unroll
        for (int ks = 0; ks < 4; ks++) {
            // A-frag from pT via ldmatrix.trans:
            // lanes 0-7: keys 0-7 q0-7 | 8-15: keys 8-15 q0-7
            // 16-23: keys 0-7 q8-15    | 24-31: keys 8-15 q8-15
            uint32_t tA[4];
            uint32_t arow = (uint32_t)(kb + ks * 16 + lane15);
            ldmx4t(tA, ptaddr + arow * 32 + (laneHalf ? 16u : 0u));
            uint32_t a[4] = { tA[0], tA[2], tA[1], tA[3] };
            // B-frag from kv via ldmatrix.trans:
            // lanes 0-15: dims warp*16..+7 (keys 0-15), 16-31: dims +8
            uint32_t tB[4];
            uint32_t brow = (uint32_t)(ks * 16 + lane15);
            ldmx4t(tB, kvaddr + brow * 272 + (warp * 16 + laneHalf * 8) * 2);
            mmaf16(acc0, a, tB[0], tB[1]);
            mmaf16(acc1, a, tB[2], tB[3]);
        }
    }

    // ---- epilogue: D[q][dim] scaled by sinv, fp16 out ----
    {
        float iv0 = sinv[grp], iv1 = sinv[grp + 8];
        int dbase = warp * 16 + tig * 2;
        size_t o00 = ((size_t)bb * SEQ + q0 + grp) * DIM + h * HD + dbase;
        size_t o10 = ((size_t)bb * SEQ + q0 + grp + 8) * DIM + h * HD + dbase;
        pack2h(acc0[0] * iv0, acc0[1] * iv0, hp + o00);
        pack2h(acc0[2] * iv1, acc0[3] * iv1, hp + o10);
        pack2h(acc1[0] * iv0, acc1[1] * iv0, hp + o00 + 8);
        pack2h(acc1[2] * iv1, acc1[3] * iv1, hp + o10 + 8);
    }
}

// ---------------- launch ------------------------------------------------------
extern "C" void kernel_launch(void* const* d_in, const int* in_sizes, int n_in,
                              void* d_out, int out_size) {
    const float* x    = (const float*)d_in[0];
    const int*   map  = (const int*)  d_in[1];
    const float* Wqkv = (const float*)d_in[2];
    const float* bqkv = (const float*)d_in[3];
    const float* Wout = (const float*)d_in[4];
    const float* bout = (const float*)d_in[5];
    const float* Wfc1 = (const float*)d_in[6];
    const float* bfc1 = (const float*)d_in[7];
    const float* Wfc2 = (const float*)d_in[8];
    const float* bfc2 = (const float*)d_in[9];
    const float* ln1g = (const float*)d_in[10];
    const float* ln1b = (const float*)d_in[11];
    const float* ln2g = (const float*)d_in[12];
    const float* ln2b = (const float*)d_in[13];
    const float* Aqkv = (const float*)d_in[14];
    const float* Bqkv = (const float*)d_in[15];
    const float* Aout = (const float*)d_in[16];
    const float* Bout = (const float*)d_in[17];
    const float* Afc1 = (const float*)d_in[18];
    const float* Bfc1 = (const float*)d_in[19];
    const float* Afc2 = (const float*)d_in[20];
    const float* Bfc2 = (const float*)d_in[21];
    float* out = (float*)d_out;

    float *p_qkv, *p_res2, *p_u;
    __half *p_Wh, *p_AS, *p_AL;
    cudaGetSymbolAddress((void**)&p_qkv,  g_qkv);
    cudaGetSymbolAddress((void**)&p_res2, g_res2);
    cudaGetSymbolAddress((void**)&p_u,    g_u);
    cudaGetSymbolAddress((void**)&p_Wh,   g_Wh);
    cudaGetSymbolAddress((void**)&p_AS,   g_AS);
    cudaGetSymbolAddress((void**)&p_AL,   g_AL);

    cudaFuncSetAttribute(tc_gemm, cudaFuncAttributeMaxDynamicSharedMemorySize, SMEM_G);
    cudaFuncSetAttribute(attn5_kernel, cudaFuncAttributeMaxDynamicSharedMemorySize,
                         ATTN_SMEM);
    cudaFuncSetAttribute(lora_u_smem_h, cudaFuncAttributeMaxDynamicSharedMemorySize,
                         FFN_D * 4);

    // ---- all weights -> fp16 (one launch) ----
    cvt_all<<<8192, 256>>>(Wqkv, Wout, Wfc1, Wfc2, p_Wh);

    // ---- attention block ----
    ln_fused<<<NT, 256>>>(x, ln1g, ln1b, Aqkv, map, p_AS, p_u);
    tc_gemm<<<dim3(H3 / BN, NT / BM), 256, SMEM_G>>>(
        p_AS, p_Wh + WOFF_QKV, bqkv, p_u, Bqkv, map,
        nullptr, p_qkv, nullptr, H3, DIM, 0);
    attn5_kernel<<<dim3(SEQ / TQ, NH, 2), 256, ATTN_SMEM>>>(p_qkv, p_AS);
    lora_u_smem_h<<<NT, 256, DIM * 4>>>(p_AS, Aout, map, p_u, DIM);
    tc_gemm<<<dim3(DIM / BN, NT / BM), 256, SMEM_G>>>(
        p_AS, p_Wh + WOFF_OUT, bout, p_u, Bout, map,
        x, p_res2, nullptr, DIM, DIM, 0);
    // ---- FFN block ----
    ln_fused<<<NT, 256>>>(p_res2, ln2g, ln2b, Afc1, map, p_AS, p_u);
    tc_gemm<<<dim3(FFN_D / BN, NT / BM), 256, SMEM_G>>>(
        p_AS, p_Wh + WOFF_FC1, bfc1, p_u, Bfc1, map,
        nullptr, nullptr, p_AL, FFN_D, DIM, 1);
    lora_u_smem_h<<<NT, 256, FFN_D * 4>>>(p_AL, Afc2, map, p_u, FFN_D);
    tc_gemm<<<dim3(DIM / BN, NT / BM), 256, SMEM_G>>>(
        p_AL, p_Wh + WOFF_FC2, bfc2, p_u, Bfc2, map,
        p_res2, out, nullptr, DIM, FFN_D, 0);
}

// round 13
// speedup vs baseline: 5.4319x; 1.0632x over previous
#include <cuda_runtime.h>
#include <cuda_fp16.h>
#include <cstdint>
#include <cstddef>

#define DIM   4096
#define H3    12288
#define FFN_D 16384
#define NT    2048      // total tokens = 2*1024
#define LR    16        // lora rank
#define SEQ   1024
#define NH    32
#define HD    128

// ---------------- scratch (device globals; no allocations allowed) ----------
__device__ float g_res2[(size_t)NT * DIM];
__device__ float g_u   [(size_t)NT * LR];

// fp16 weight plane + fp16 activation planes
#define WOFF_QKV 0
#define WOFF_OUT 50331648u
#define WOFF_FC1 67108864u
#define WOFF_FC2 134217728u
#define W_TOTAL  201326592u
__device__ __half g_Wh [W_TOTAL];
__device__ __half g_AS [(size_t)NT * DIM];
__device__ __half g_AL [(size_t)NT * FFN_D];   // doubles as fp16 qkv plane

// ================= helpers ===================================================
__device__ __forceinline__ uint32_t smem_u32(const void* p) {
    uint32_t a;
    asm("{ .reg .u64 t; cvta.to.shared.u64 t, %1; cvt.u32.u64 %0, t; }"
        : "=r"(a) : "l"(p));
    return a;
}
__device__ __forceinline__ void ldmx4(uint32_t* r, uint32_t addr) {
    asm volatile("ldmatrix.sync.aligned.m8n8.x4.shared.b16 {%0,%1,%2,%3}, [%4];"
                 : "=r"(r[0]), "=r"(r[1]), "=r"(r[2]), "=r"(r[3]) : "r"(addr));
}
__device__ __forceinline__ void ldmx4t(uint32_t* r, uint32_t addr) {
    asm volatile("ldmatrix.sync.aligned.m8n8.x4.trans.shared.b16 {%0,%1,%2,%3}, [%4];"
                 : "=r"(r[0]), "=r"(r[1]), "=r"(r[2]), "=r"(r[3]) : "r"(addr));
}
__device__ __forceinline__ uint32_t lds32(uint32_t addr) {
    uint32_t v;
    asm volatile("ld.shared.b32 %0, [%1];" : "=r"(v) : "r"(addr));
    return v;
}
__device__ __forceinline__ void mmaf16(float* d, const uint32_t* a,
                                       uint32_t b0, uint32_t b1) {
    asm volatile("mma.sync.aligned.m16n8k16.row.col.f32.f16.f16.f32 "
                 "{%0,%1,%2,%3}, {%4,%5,%6,%7}, {%8,%9}, {%0,%1,%2,%3};"
                 : "+f"(d[0]), "+f"(d[1]), "+f"(d[2]), "+f"(d[3])
                 : "r"(a[0]), "r"(a[1]), "r"(a[2]), "r"(a[3]),
                   "r"(b0), "r"(b1));
}
__device__ __forceinline__ void cpa16(uint32_t d, const void* s) {
    asm volatile("cp.async.ca.shared.global [%0], [%1], 16;"
                 :: "r"(d), "l"(s) : "memory");
}
__device__ __forceinline__ void cpa_commit() {
    asm volatile("cp.async.commit_group;" ::: "memory");
}
__device__ __forceinline__ void pack2h(float a, float b, __half* dst) {
    *(__half2*)dst = __halves2half2(__float2half_rn(a), __float2half_rn(b));
}

// ================= fused weight fp32 -> fp16 (all 4 mats, 1 launch) ===========
__global__ void cvt_all(const float* __restrict__ s0, const float* __restrict__ s1,
                        const float* __restrict__ s2, const float* __restrict__ s3,
                        __half* __restrict__ dst) {
    const size_t e0 = 12582912, e1 = 16777216, e2 = 33554432, e3 = 50331648;
    size_t i = (size_t)blockIdx.x * blockDim.x + threadIdx.x;
    size_t stride = (size_t)gridDim.x * blockDim.x;
    for (; i < e3; i += stride) {
        const float* src; size_t j;
        if (i < e0)      { src = s0; j = i; }
        else if (i < e1) { src = s1; j = i - e0; }
        else if (i < e2) { src = s2; j = i - e1; }
        else             { src = s3; j = i - e2; }
        float4 v = ((const float4*)src)[j];
        ((__half2*)dst)[i * 2]     = __halves2half2(__float2half_rn(v.x),
                                                    __float2half_rn(v.y));
        ((__half2*)dst)[i * 2 + 1] = __halves2half2(__float2half_rn(v.z),
                                                    __float2half_rn(v.w));
    }
}

// ================= fused LayerNorm + fp16 plane + lora-u ======================
__global__ void ln_fused(const float* __restrict__ x, const float* __restrict__ g,
                         const float* __restrict__ b, const float* __restrict__ A,
                         const int* __restrict__ map,
                         __half* __restrict__ hp, float* __restrict__ u) {
    __shared__ float row[DIM];
    __shared__ float rs[8], rs2[8];
    int t = blockIdx.x;
    int tid = threadIdx.x, lane = tid & 31, warp = tid >> 5;
    const float4* x4 = (const float4*)(x + (size_t)t * DIM);
    float4* row4 = (float4*)row;
    float s = 0.f, s2 = 0.f;
    #pragma unroll
    for (int p = 0; p < 4; p++) {
        int i = tid + p * 256;
        float4 v = x4[i];
        row4[i] = v;
        s += v.x + v.y + v.z + v.w;
        s2 += v.x * v.x + v.y * v.y + v.z * v.z + v.w * v.w;
    }
    #pragma unroll
    for (int o = 16; o; o >>= 1) {
        s  += __shfl_xor_sync(0xffffffffu, s,  o);
        s2 += __shfl_xor_sync(0xffffffffu, s2, o);
    }
    if (!lane) { rs[warp] = s; rs2[warp] = s2; }
    __syncthreads();
    s = 0.f; s2 = 0.f;
    #pragma unroll
    for (int w = 0; w < 8; w++) { s += rs[w]; s2 += rs2[w]; }
    float mean = s * (1.f / DIM);
    float var  = s2 * (1.f / DIM) - mean * mean;
    float rstd = rsqrtf(var + 1e-5f);
    __half* hr = hp + (size_t)t * DIM;
    const float4* g4 = (const float4*)g;
    const float4* b4 = (const float4*)b;
    #pragma unroll
    for (int p = 0; p < 4; p++) {
        int i = tid + p * 256;
        float4 v = row4[i], gv = g4[i], bv = b4[i];
        float4 nv;
        nv.x = (v.x - mean) * rstd * gv.x + bv.x;
        nv.y = (v.y - mean) * rstd * gv.y + bv.y;
        nv.z = (v.z - mean) * rstd * gv.z + bv.z;
        nv.w = (v.w - mean) * rstd * gv.w + bv.w;
        pack2h(nv.x, nv.y, hr + i * 4);
        pack2h(nv.z, nv.w, hr + i * 4 + 2);
        row4[i] = nv;
    }
    __syncthreads();
    int a = map[t];
    #pragma unroll
    for (int rr = 0; rr < 2; rr++) {
        int r = warp * 2 + rr;
        const float4* ar = (const float4*)(A + ((size_t)a * LR + r) * DIM);
        float acc = 0.f;
        #pragma unroll
        for (int p = 0; p < 32; p++) {
            int i = lane + p * 32;
            float4 av = ar[i], xv = row4[i];
            acc += av.x * xv.x + av.y * xv.y + av.z * xv.z + av.w * xv.w;
        }
        #pragma unroll
        for (int o = 16; o; o >>= 1) acc += __shfl_xor_sync(0xffffffffu, acc, o);
        if (!lane) u[t * LR + r] = acc;
    }
}

// ================= lora-u from fp16 plane, smem-staged ========================
__global__ void lora_u_smem_h(const __half* __restrict__ x,
                              const float* __restrict__ A,
                              const int* __restrict__ map,
                              float* __restrict__ u, int K) {
    extern __shared__ float srow[];
    int t = blockIdx.x;
    int tid = threadIdx.x, lane = tid & 31, warp = tid >> 5;
    const __half2* x2 = (const __half2*)(x + (size_t)t * K);
    int n2 = K >> 1;
    for (int i = tid; i < n2; i += 256)
        ((float2*)srow)[i] = __half22float2(x2[i]);
    __syncthreads();
    int a = map[t];
    const float4* s4 = (const float4*)srow;
    int n4 = K >> 2;
    #pragma unroll
    for (int rr = 0; rr < 2; rr++) {
        int r = warp * 2 + rr;
        const float4* ar = (const float4*)(A + ((size_t)a * LR + r) * K);
        float acc = 0.f;
        for (int i = lane; i < n4; i += 32) {
            float4 av = ar[i], xv = s4[i];
            acc += av.x * xv.x + av.y * xv.y + av.z * xv.z + av.w * xv.w;
        }
        #pragma unroll
        for (int o = 16; o; o >>= 1) acc += __shfl_xor_sync(0xffffffffu, acc, o);
        if (!lane) u[t * LR + r] = acc;
    }
}

// ================= tensor-core GEMM (fp16 x fp16, k-chunk 64, 2-stage) ========
#define BM 128
#define BN 128
#define RSTR 72                       // smem row stride in halves (144 B)
#define PLANE (128 * RSTR * 2)        // 18432 B per plane
#define STAGE_B (2 * PLANE)           // A | W = 36864
#define SOFF_BIAS  128
#define SOFF_STAGE 1024
#define SMEM_G (SOFF_STAGE + 2 * STAGE_B)   // 74752

__device__ __forceinline__ float dot16(const float* u, const float* b) {
    float s = 0.f;
    #pragma unroll
    for (int r = 0; r < 16; r++) s = fmaf(u[r], b[r], s);
    return s;
}

__device__ __forceinline__ void issue_chunk(
        const __half* __restrict__ Ah, const __half* __restrict__ W,
        int m0, int n0, int K, int c, uint32_t sdst, int tid) {
    int k0 = c * 64;
    #pragma unroll
    for (int p = 0; p < 4; p++) {
        int idx = tid + p * 256;
        int row = idx >> 3, seg = idx & 7;
        uint32_t d = sdst + row * (RSTR * 2) + seg * 16;
        cpa16(d,         Ah + (size_t)(m0 + row) * K + k0 + seg * 8);
        cpa16(d + PLANE, W  + (size_t)(n0 + row) * K + k0 + seg * 8);
    }
    cpa_commit();
}

__global__ void __launch_bounds__(256, 2)
tc_gemm(const __half* __restrict__ Ah, const __half* __restrict__ W,
        const float* __restrict__ bias, const float* __restrict__ u,
        const float* __restrict__ Bl, const int* __restrict__ map,
        const float* __restrict__ resid, float* __restrict__ C,
        __half* __restrict__ hOut, int N, int K, int relu) {
    extern __shared__ __align__(1024) char smem[];
    uint32_t sbase = smem_u32(smem);
    int tid = threadIdx.x;
    int lane = tid & 31, warp = tid >> 5;
    int wm = warp >> 2, wn = warp & 3;
    int n0 = blockIdx.x * BN;
    int m0 = blockIdx.y * BM;

    if (tid < BN) ((float*)(smem + SOFF_BIAS))[tid] = bias[n0 + tid];

    float acc[4][4][4];
    #pragma unroll
    for (int f = 0; f < 4; f++)
        #pragma unroll
        for (int g = 0; g < 4; g++)
            #pragma unroll
            for (int e = 0; e < 4; e++) acc[f][g][e] = 0.f;

    int nCh = K >> 6;
    issue_chunk(Ah, W, m0, n0, K, 0, sbase + SOFF_STAGE, tid);
    if (nCh > 1)
        issue_chunk(Ah, W, m0, n0, K, 1, sbase + SOFF_STAGE + STAGE_B, tid);

    int lane15 = lane & 15, laneHalf = lane >> 4;
    int grp = lane >> 2, tig = lane & 3;

    int stage = 0;
    for (int c = 0; c < nCh; c++) {
        if (c + 1 < nCh)
            asm volatile("cp.async.wait_group 1;" ::: "memory");
        else
            asm volatile("cp.async.wait_group 0;" ::: "memory");
        __syncthreads();

        uint32_t base = sbase + SOFF_STAGE + stage * STAGE_B;
        #pragma unroll
        for (int ks = 0; ks < 4; ks++) {
            uint32_t af[4][4];
            int koffA = ks * 16 + laneHalf * 8;
            #pragma unroll
            for (int f = 0; f < 4; f++) {
                int row = wm * 64 + f * 16 + lane15;
                ldmx4(af[f], base + row * (RSTR * 2) + koffA * 2);
            }
            #pragma unroll
            for (int g = 0; g < 4; g++) {
                int n = wn * 32 + g * 8 + grp;
                uint32_t bd = base + PLANE + n * (RSTR * 2)
                            + (ks * 16 + tig * 2) * 2;
                uint32_t w0 = lds32(bd), w1 = lds32(bd + 16);
                #pragma unroll
                for (int f = 0; f < 4; f++)
                    mmaf16(acc[f][g], af[f], w0, w1);
            }
        }
        __syncthreads();
        if (c + 2 < nCh)
            issue_chunk(Ah, W, m0, n0, K, c + 2,
                        sbase + SOFF_STAGE + stage * STAGE_B, tid);
        stage ^= 1;
    }

    // ---- stage lora-B slice into SMEM (overlays stages) ----
    float* Bs = (float*)(smem + SOFF_STAGE);
    for (int i = tid; i < 4096; i += 256) {
        int a   = i >> 9;
        int rem = i & 511;
        int nl  = rem >> 2;
        int sg  = rem & 3;
        float4 v = *(const float4*)(Bl + ((size_t)a * N + n0 + nl) * LR + sg * 4);
        *(float4*)(Bs + ((size_t)((a << 7) + nl)) * LR + sg * 4) = v;
    }
    __syncthreads();

    const float* biasS = (const float*)(smem + SOFF_BIAS);
    #pragma unroll
    for (int f = 0; f < 4; f++) {
        int r0 = m0 + wm * 64 + f * 16 + grp;
        int r1 = r0 + 8;
        int a0 = map[r0], a1 = map[r1];
        float u0[16], u1[16];
        {
            const float4* p0 = (const float4*)(u + (size_t)r0 * LR);
            const float4* p1 = (const float4*)(u + (size_t)r1 * LR);
            #pragma unroll
            for (int q = 0; q < 4; q++) {
                float4 v0 = p0[q], v1 = p1[q];
                u0[q*4+0]=v0.x; u0[q*4+1]=v0.y; u0[q*4+2]=v0.z; u0[q*4+3]=v0.w;
                u1[q*4+0]=v1.x; u1[q*4+1]=v1.y; u1[q*4+2]=v1.z; u1[q*4+3]=v1.w;
            }
        }
        #pragma unroll
        for (int g = 0; g < 4; g++) {
            int nl = wn * 32 + g * 8 + tig * 2;
            float v00 = acc[f][g][0] + biasS[nl]
                      + dot16(u0, Bs + ((size_t)((a0 << 7) + nl)) * LR);
            float v01 = acc[f][g][1] + biasS[nl + 1]
                      + dot16(u0, Bs + ((size_t)((a0 << 7) + nl + 1)) * LR);
            float v10 = acc[f][g][2] + biasS[nl]
                      + dot16(u1, Bs + ((size_t)((a1 << 7) + nl)) * LR);
            float v11 = acc[f][g][3] + biasS[nl + 1]
                      + dot16(u1, Bs + ((size_t)((a1 << 7) + nl + 1)) * LR);
            size_t o0 = (size_t)r0 * N + n0 + nl;
            size_t o1 = (size_t)r1 * N + n0 + nl;
            if (resid) {
                float2 q0 = *(const float2*)(resid + o0);
                float2 q1 = *(const float2*)(resid + o1);
                v00 += q0.x; v01 += q0.y; v10 += q1.x; v11 += q1.y;
            }
            if (relu) {
                v00 = fmaxf(v00, 0.f); v01 = fmaxf(v01, 0.f);
                v10 = fmaxf(v10, 0.f); v11 = fmaxf(v11, 0.f);
            }
            if (C) {
                *(float2*)(C + o0) = make_float2(v00, v01);
                *(float2*)(C + o1) = make_float2(v10, v11);
            }
            if (hOut) {
                pack2h(v00, v01, hOut + o0);
                pack2h(v10, v11, hOut + o1);
            }
        }
    }
}

// ================= attention: flash-style online softmax, all-MMA =============
#define TQ 16
// smem bytes: qh 16x136h (4352) | kc 64x136h (17408) | vc 64x136h (17408)
//             scb 16x64 f (4096) | pt 64x16h (2048) | m/l/f 3x16 f (192)
#define ATT_QH  0
#define ATT_KC  4352
#define ATT_VC  21760
#define ATT_SCB 39168
#define ATT_PT  43264
#define ATT_M   45312
#define ATT_L   45376
#define ATT_F   45440
#define ATTN_SMEM 45504

__global__ void __launch_bounds__(256, 2)
attn6_kernel(const __half* __restrict__ qkvh, __half* __restrict__ hp) {
    extern __shared__ __align__(1024) char smemA[];
    __half* qh  = (__half*)(smemA + ATT_QH);
    __half* kc  = (__half*)(smemA + ATT_KC);
    __half* vc  = (__half*)(smemA + ATT_VC);
    float*  scb = (float*)(smemA + ATT_SCB);
    __half* pt  = (__half*)(smemA + ATT_PT);
    float*  mrow = (float*)(smemA + ATT_M);
    float*  lrow = (float*)(smemA + ATT_L);
    float*  frow = (float*)(smemA + ATT_F);
    int qt = blockIdx.x, h = blockIdx.y, bb = blockIdx.z;
    int q0 = qt * TQ;
    int tid = threadIdx.x, lane = tid & 31, warp = tid >> 5;
    int lane15 = lane & 15, laneHalf = lane >> 4;
    int grp = lane >> 2, tig = lane & 3;
    const size_t base = (size_t)bb * SEQ * H3;
    const float scale = 0.08838834764831845f;
    uint32_t qaddr = smem_u32(qh), kcaddr = smem_u32(kc);
    uint32_t vcaddr = smem_u32(vc), ptaddr = smem_u32(pt);

    if (tid < TQ) { mrow[tid] = -1e30f; lrow[tid] = 0.f; }

    // stage Q tile via cp.async (16 rows x 16 segs)
    {
        int r = tid >> 4, seg = tid & 15;
        cpa16(qaddr + r * 272 + seg * 16,
              qkvh + base + (size_t)(q0 + r) * H3 + h * HD + seg * 8);
        cpa_commit();
        asm volatile("cp.async.wait_group 0;" ::: "memory");
    }
    __syncthreads();
    uint32_t qf[8][4];
    #pragma unroll
    for (int ks = 0; ks < 8; ks++)
        ldmx4(qf[ks], qaddr + lane15 * 272 + (ks * 16 + laneHalf * 8) * 2);

    float acc0[4] = {0.f, 0.f, 0.f, 0.f};
    float acc1[4] = {0.f, 0.f, 0.f, 0.f};
    int nkmax = q0 + TQ;

    for (int kb = 0; kb < nkmax; kb += 64) {
        __syncthreads();     // kc/vc/pt reuse: prior chunk's MMAs complete
        // stage K+V chunk via cp.async; zero-fill V tail rows
        #pragma unroll
        for (int p = 0; p < 4; p++) {
            int idx = tid + p * 256;
            int r = idx >> 4, seg = idx & 15;
            uint32_t off = (uint32_t)(r * 272 + seg * 16);
            if (kb + r < nkmax) {
                const __half* src = qkvh + base + (size_t)(kb + r) * H3
                                  + h * HD + seg * 8;
                cpa16(kcaddr + off, src + DIM);
                cpa16(vcaddr + off, src + 2 * DIM);
            } else {
                *(uint4*)((char*)vc + off) = make_uint4(0, 0, 0, 0);
            }
        }
        cpa_commit();
        asm volatile("cp.async.wait_group 0;" ::: "memory");
        __syncthreads();

        // scores: warp owns keys kb+warp*8 .. +8
        float sacc[4] = {0.f, 0.f, 0.f, 0.f};
        #pragma unroll
        for (int ks = 0; ks < 8; ks++) {
            uint32_t bd = kcaddr + (warp * 8 + grp) * 272
                        + (ks * 16 + tig * 2) * 2;
            uint32_t w0 = lds32(bd), w1 = lds32(bd + 16);
            mmaf16(sacc, qf[ks], w0, w1);
        }
        {
            int kcol = kb + warp * 8 + tig * 2;
            int kl = kcol - kb;
            scb[grp * 64 + kl]           = (kcol     <= q0 + grp) ? sacc[0] * scale : -1e30f;
            scb[grp * 64 + kl + 1]       = (kcol + 1 <= q0 + grp) ? sacc[1] * scale : -1e30f;
            scb[(grp + 8) * 64 + kl]     = (kcol     <= q0 + grp + 8) ? sacc[2] * scale : -1e30f;
            scb[(grp + 8) * 64 + kl + 1] = (kcol + 1 <= q0 + grp + 8) ? sacc[3] * scale : -1e30f;
        }
        __syncthreads();

        // online softmax update: warp w rows w, w+8
        #pragma unroll
        for (int rr = 0; rr < 2; rr++) {
            int r = warp + rr * 8;
            float s0 = scb[r * 64 + lane], s1 = scb[r * 64 + lane + 32];
            float mc = fmaxf(s0, s1);
            #pragma unroll
            for (int o = 16; o; o >>= 1)
                mc = fmaxf(mc, __shfl_xor_sync(0xffffffffu, mc, o));
            float mold = mrow[r];
            float newm = fmaxf(mold, mc);
            float p0 = __expf(s0 - newm), p1 = __expf(s1 - newm);
            pt[lane * 16 + r]        = __float2half(p0);
            pt[(lane + 32) * 16 + r] = __float2half(p1);
            float ls = p0 + p1;
            #pragma unroll
            for (int o = 16; o; o >>= 1) ls += __shfl_xor_sync(0xffffffffu, ls, o);
            if (!lane) {
                float f = __expf(mold - newm);
                lrow[r] = lrow[r] * f + ls;
                mrow[r] = newm;
                frow[r] = f;
            }
        }
        __syncthreads();

        // rescale + PV MMAs: warp owns dims [warp*16, +16)
        {
            float f0 = frow[grp], f1 = frow[grp + 8];
            acc0[0] *= f0; acc0[1] *= f0; acc0[2] *= f1; acc0[3] *= f1;
            acc1[0] *= f0; acc1[1] *= f0; acc1[2] *= f1; acc1[3] *= f1;
        }
        #pragma unroll
        for (int ks = 0; ks < 4; ks++) {
            uint32_t tA[4];
            ldmx4t(tA, ptaddr + (ks * 16 + lane15) * 32 + (laneHalf ? 16u : 0u));
            uint32_t a[4] = { tA[0], tA[2], tA[1], tA[3] };
            uint32_t tB[4];
            ldmx4t(tB, vcaddr + (ks * 16 + lane15) * 272
                       + (warp * 16 + laneHalf * 8) * 2);
            mmaf16(acc0, a, tB[0], tB[1]);
            mmaf16(acc1, a, tB[2], tB[3]);
        }
    }
    __syncthreads();

    // epilogue
    {
        float iv0 = 1.f / lrow[grp], iv1 = 1.f / lrow[grp + 8];
        int dbase = warp * 16 + tig * 2;
        size_t o00 = ((size_t)bb * SEQ + q0 + grp) * DIM + h * HD + dbase;
        size_t o10 = ((size_t)bb * SEQ + q0 + grp + 8) * DIM + h * HD + dbase;
        pack2h(acc0[0] * iv0, acc0[1] * iv0, hp + o00);
        pack2h(acc0[2] * iv1, acc0[3] * iv1, hp + o10);
        pack2h(acc1[0] * iv0, acc1[1] * iv0, hp + o00 + 8);
        pack2h(acc1[2] * iv1, acc1[3] * iv1, hp + o10 + 8);
    }
}

// ---------------- launch ------------------------------------------------------
extern "C" void kernel_launch(void* const* d_in, const int* in_sizes, int n_in,
                              void* d_out, int out_size) {
    const float* x    = (const float*)d_in[0];
    const int*   map  = (const int*)  d_in[1];
    const float* Wqkv = (const float*)d_in[2];
    const float* bqkv = (const float*)d_in[3];
    const float* Wout = (const float*)d_in[4];
    const float* bout = (const float*)d_in[5];
    const float* Wfc1 = (const float*)d_in[6];
    const float* bfc1 = (const float*)d_in[7];
    const float* Wfc2 = (const float*)d_in[8];
    const float* bfc2 = (const float*)d_in[9];
    const float* ln1g = (const float*)d_in[10];
    const float* ln1b = (const float*)d_in[11];
    const float* ln2g = (const float*)d_in[12];
    const float* ln2b = (const float*)d_in[13];
    const float* Aqkv = (const float*)d_in[14];
    const float* Bqkv = (const float*)d_in[15];
    const float* Aout = (const float*)d_in[16];
    const float* Bout = (const float*)d_in[17];
    const float* Afc1 = (const float*)d_in[18];
    const float* Bfc1 = (const float*)d_in[19];
    const float* Afc2 = (const float*)d_in[20];
    const float* Bfc2 = (const float*)d_in[21];
    float* out = (float*)d_out;

    float *p_res2, *p_u;
    __half *p_Wh, *p_AS, *p_AL;
    cudaGetSymbolAddress((void**)&p_res2, g_res2);
    cudaGetSymbolAddress((void**)&p_u,    g_u);
    cudaGetSymbolAddress((void**)&p_Wh,   g_Wh);
    cudaGetSymbolAddress((void**)&p_AS,   g_AS);
    cudaGetSymbolAddress((void**)&p_AL,   g_AL);
    __half* p_qkvh = p_AL;   // fp16 qkv plane reuses the large activation plane

    cudaFuncSetAttribute(tc_gemm, cudaFuncAttributeMaxDynamicSharedMemorySize, SMEM_G);
    cudaFuncSetAttribute(attn6_kernel, cudaFuncAttributeMaxDynamicSharedMemorySize,
                         ATTN_SMEM);
    cudaFuncSetAttribute(lora_u_smem_h, cudaFuncAttributeMaxDynamicSharedMemorySize,
                         FFN_D * 4);

    // ---- all weights -> fp16 (one launch) ----
    cvt_all<<<8192, 256>>>(Wqkv, Wout, Wfc1, Wfc2, p_Wh);

    // ---- attention block ----
    ln_fused<<<NT, 256>>>(x, ln1g, ln1b, Aqkv, map, p_AS, p_u);
    tc_gemm<<<dim3(H3 / BN, NT / BM), 256, SMEM_G>>>(
        p_AS, p_Wh + WOFF_QKV, bqkv, p_u, Bqkv, map,
        nullptr, nullptr, p_qkvh, H3, DIM, 0);
    attn6_kernel<<<dim3(SEQ / TQ, NH, 2), 256, ATTN_SMEM>>>(p_qkvh, p_AS);
    lora_u_smem_h<<<NT, 256, DIM * 4>>>(p_AS, Aout, map, p_u, DIM);
    tc_gemm<<<dim3(DIM / BN, NT / BM), 256, SMEM_G>>>(
        p_AS, p_Wh + WOFF_OUT, bout, p_u, Bout, map,
        x, p_res2, nullptr, DIM, DIM, 0);
    // ---- FFN block ----
    ln_fused<<<NT, 256>>>(p_res2, ln2g, ln2b, Afc1, map, p_AS, p_u);
    tc_gemm<<<dim3(FFN_D / BN, NT / BM), 256, SMEM_G>>>(
        p_AS, p_Wh + WOFF_FC1, bfc1, p_u, Bfc1, map,
        nullptr, nullptr, p_AL, FFN_D, DIM, 1);
    lora_u_smem_h<<<NT, 256, FFN_D * 4>>>(p_AL, Afc2, map, p_u, FFN_D);
    tc_gemm<<<dim3(DIM / BN, NT / BM), 256, SMEM_G>>>(
        p_AL, p_Wh + WOFF_FC2, bfc2, p_u, Bfc2, map,
        p_res2, out, nullptr, DIM, FFN_D, 0);
}

// round 15
// speedup vs baseline: 5.4845x; 1.0097x over previous
#include <cuda_runtime.h>
#include <cuda_fp16.h>
#include <cstdint>
#include <cstddef>

#define DIM   4096
#define H3    12288
#define FFN_D 16384
#define NT    2048      // total tokens = 2*1024
#define LR    16        // lora rank
#define SEQ   1024
#define NH    32
#define HD    128

// ---------------- scratch (device globals; no allocations allowed) ----------
__device__ float g_res2[(size_t)NT * DIM];
__device__ float g_u   [(size_t)NT * LR];

// fp16 weight plane + fp16 activation planes
#define WOFF_QKV 0
#define WOFF_OUT 50331648u
#define WOFF_FC1 67108864u
#define WOFF_FC2 134217728u
#define W_TOTAL  201326592u
__device__ __half g_Wh [W_TOTAL];
__device__ __half g_AS [(size_t)NT * DIM];
__device__ __half g_AL [(size_t)NT * FFN_D];   // doubles as fp16 qkv plane

// ================= helpers ===================================================
__device__ __forceinline__ uint32_t smem_u32(const void* p) {
    uint32_t a;
    asm("{ .reg .u64 t; cvta.to.shared.u64 t, %1; cvt.u32.u64 %0, t; }"
        : "=r"(a) : "l"(p));
    return a;
}
__device__ __forceinline__ void ldmx4(uint32_t* r, uint32_t addr) {
    asm volatile("ldmatrix.sync.aligned.m8n8.x4.shared.b16 {%0,%1,%2,%3}, [%4];"
                 : "=r"(r[0]), "=r"(r[1]), "=r"(r[2]), "=r"(r[3]) : "r"(addr));
}
__device__ __forceinline__ void ldmx4t(uint32_t* r, uint32_t addr) {
    asm volatile("ldmatrix.sync.aligned.m8n8.x4.trans.shared.b16 {%0,%1,%2,%3}, [%4];"
                 : "=r"(r[0]), "=r"(r[1]), "=r"(r[2]), "=r"(r[3]) : "r"(addr));
}
__device__ __forceinline__ uint32_t lds32(uint32_t addr) {
    uint32_t v;
    asm volatile("ld.shared.b32 %0, [%1];" : "=r"(v) : "r"(addr));
    return v;
}
__device__ __forceinline__ void mmaf16(float* d, const uint32_t* a,
                                       uint32_t b0, uint32_t b1) {
    asm volatile("mma.sync.aligned.m16n8k16.row.col.f32.f16.f16.f32 "
                 "{%0,%1,%2,%3}, {%4,%5,%6,%7}, {%8,%9}, {%0,%1,%2,%3};"
                 : "+f"(d[0]), "+f"(d[1]), "+f"(d[2]), "+f"(d[3])
                 : "r"(a[0]), "r"(a[1]), "r"(a[2]), "r"(a[3]),
                   "r"(b0), "r"(b1));
}
__device__ __forceinline__ void cpa16(uint32_t d, const void* s) {
    asm volatile("cp.async.ca.shared.global [%0], [%1], 16;"
                 :: "r"(d), "l"(s) : "memory");
}
__device__ __forceinline__ void cpa_commit() {
    asm volatile("cp.async.commit_group;" ::: "memory");
}
__device__ __forceinline__ void pack2h(float a, float b, __half* dst) {
    *(__half2*)dst = __halves2half2(__float2half_rn(a), __float2half_rn(b));
}

// ================= fused weight fp32 -> fp16 (all 4 mats, 1 launch) ===========
__global__ void cvt_all(const float* __restrict__ s0, const float* __restrict__ s1,
                        const float* __restrict__ s2, const float* __restrict__ s3,
                        __half* __restrict__ dst) {
    const size_t e0 = 12582912, e1 = 16777216, e2 = 33554432, e3 = 50331648;
    size_t i = (size_t)blockIdx.x * blockDim.x + threadIdx.x;
    size_t stride = (size_t)gridDim.x * blockDim.x;
    for (; i < e3; i += stride) {
        const float* src; size_t j;
        if (i < e0)      { src = s0; j = i; }
        else if (i < e1) { src = s1; j = i - e0; }
        else if (i < e2) { src = s2; j = i - e1; }
        else             { src = s3; j = i - e2; }
        float4 v = ((const float4*)src)[j];
        ((__half2*)dst)[i * 2]     = __halves2half2(__float2half_rn(v.x),
                                                    __float2half_rn(v.y));
        ((__half2*)dst)[i * 2 + 1] = __halves2half2(__float2half_rn(v.z),
                                                    __float2half_rn(v.w));
    }
}

// ================= fused LayerNorm + fp16 plane + lora-u ======================
__global__ void ln_fused(const float* __restrict__ x, const float* __restrict__ g,
                         const float* __restrict__ b, const float* __restrict__ A,
                         const int* __restrict__ map,
                         __half* __restrict__ hp, float* __restrict__ u) {
    __shared__ float row[DIM];
    __shared__ float rs[8], rs2[8];
    int t = blockIdx.x;
    int tid = threadIdx.x, lane = tid & 31, warp = tid >> 5;
    const float4* x4 = (const float4*)(x + (size_t)t * DIM);
    float4* row4 = (float4*)row;
    float s = 0.f, s2 = 0.f;
    #pragma unroll
    for (int p = 0; p < 4; p++) {
        int i = tid + p * 256;
        float4 v = x4[i];
        row4[i] = v;
        s += v.x + v.y + v.z + v.w;
        s2 += v.x * v.x + v.y * v.y + v.z * v.z + v.w * v.w;
    }
    #pragma unroll
    for (int o = 16; o; o >>= 1) {
        s  += __shfl_xor_sync(0xffffffffu, s,  o);
        s2 += __shfl_xor_sync(0xffffffffu, s2, o);
    }
    if (!lane) { rs[warp] = s; rs2[warp] = s2; }
    __syncthreads();
    s = 0.f; s2 = 0.f;
    #pragma unroll
    for (int w = 0; w < 8; w++) { s += rs[w]; s2 += rs2[w]; }
    float mean = s * (1.f / DIM);
    float var  = s2 * (1.f / DIM) - mean * mean;
    float rstd = rsqrtf(var + 1e-5f);
    __half* hr = hp + (size_t)t * DIM;
    const float4* g4 = (const float4*)g;
    const float4* b4 = (const float4*)b;
    #pragma unroll
    for (int p = 0; p < 4; p++) {
        int i = tid + p * 256;
        float4 v = row4[i], gv = g4[i], bv = b4[i];
        float4 nv;
        nv.x = (v.x - mean) * rstd * gv.x + bv.x;
        nv.y = (v.y - mean) * rstd * gv.y + bv.y;
        nv.z = (v.z - mean) * rstd * gv.z + bv.z;
        nv.w = (v.w - mean) * rstd * gv.w + bv.w;
        pack2h(nv.x, nv.y, hr + i * 4);
        pack2h(nv.z, nv.w, hr + i * 4 + 2);
        row4[i] = nv;
    }
    __syncthreads();
    int a = map[t];
    #pragma unroll
    for (int rr = 0; rr < 2; rr++) {
        int r = warp * 2 + rr;
        const float4* ar = (const float4*)(A + ((size_t)a * LR + r) * DIM);
        float acc = 0.f;
        #pragma unroll
        for (int p = 0; p < 32; p++) {
            int i = lane + p * 32;
            float4 av = ar[i], xv = row4[i];
            acc += av.x * xv.x + av.y * xv.y + av.z * xv.z + av.w * xv.w;
        }
        #pragma unroll
        for (int o = 16; o; o >>= 1) acc += __shfl_xor_sync(0xffffffffu, acc, o);
        if (!lane) u[t * LR + r] = acc;
    }
}

// ================= lora-u from fp16 plane, smem-staged ========================
__global__ void lora_u_smem_h(const __half* __restrict__ x,
                              const float* __restrict__ A,
                              const int* __restrict__ map,
                              float* __restrict__ u, int K) {
    extern __shared__ float srow[];
    int t = blockIdx.x;
    int tid = threadIdx.x, lane = tid & 31, warp = tid >> 5;
    const __half2* x2 = (const __half2*)(x + (size_t)t * K);
    int n2 = K >> 1;
    for (int i = tid; i < n2; i += 256)
        ((float2*)srow)[i] = __half22float2(x2[i]);
    __syncthreads();
    int a = map[t];
    const float4* s4 = (const float4*)srow;
    int n4 = K >> 2;
    #pragma unroll
    for (int rr = 0; rr < 2; rr++) {
        int r = warp * 2 + rr;
        const float4* ar = (const float4*)(A + ((size_t)a * LR + r) * K);
        float acc = 0.f;
        for (int i = lane; i < n4; i += 32) {
            float4 av = ar[i], xv = s4[i];
            acc += av.x * xv.x + av.y * xv.y + av.z * xv.z + av.w * xv.w;
        }
        #pragma unroll
        for (int o = 16; o; o >>= 1) acc += __shfl_xor_sync(0xffffffffu, acc, o);
        if (!lane) u[t * LR + r] = acc;
    }
}

// ================= tensor-core GEMM (fp16 x fp16, k-chunk 64, 2-stage) ========
#define BM 128
#define BN 128
#define RSTR 72                       // smem row stride in halves (144 B)
#define PLANE (128 * RSTR * 2)        // 18432 B per plane
#define STAGE_B (2 * PLANE)           // A | W = 36864
#define SOFF_BIAS  128
#define SOFF_STAGE 1024
#define SMEM_G (SOFF_STAGE + 2 * STAGE_B)   // 74752

__device__ __forceinline__ float dot16(const float* u, const float* b) {
    float s = 0.f;
    #pragma unroll
    for (int r = 0; r < 16; r++) s = fmaf(u[r], b[r], s);
    return s;
}

__device__ __forceinline__ void issue_chunk(
        const __half* __restrict__ Ah, const __half* __restrict__ W,
        int m0, int n0, int K, int c, uint32_t sdst, int tid) {
    int k0 = c * 64;
    #pragma unroll
    for (int p = 0; p < 4; p++) {
        int idx = tid + p * 256;
        int row = idx >> 3, seg = idx & 7;
        uint32_t d = sdst + row * (RSTR * 2) + seg * 16;
        cpa16(d,         Ah + (size_t)(m0 + row) * K + k0 + seg * 8);
        cpa16(d + PLANE, W  + (size_t)(n0 + row) * K + k0 + seg * 8);
    }
    cpa_commit();
}

__global__ void __launch_bounds__(256, 2)
tc_gemm(const __half* __restrict__ Ah, const __half* __restrict__ W,
        const float* __restrict__ bias, const float* __restrict__ u,
        const float* __restrict__ Bl, const int* __restrict__ map,
        const float* __restrict__ resid, float* __restrict__ C,
        __half* __restrict__ hOut, int N, int K, int relu) {
    extern __shared__ __align__(1024) char smem[];
    uint32_t sbase = smem_u32(smem);
    int tid = threadIdx.x;
    int lane = tid & 31, warp = tid >> 5;
    int wm = warp >> 2, wn = warp & 3;
    int n0 = blockIdx.x * BN;
    int m0 = blockIdx.y * BM;

    if (tid < BN) ((float*)(smem + SOFF_BIAS))[tid] = bias[n0 + tid];

    float acc[4][4][4];
    #pragma unroll
    for (int f = 0; f < 4; f++)
        #pragma unroll
        for (int g = 0; g < 4; g++)
            #pragma unroll
            for (int e = 0; e < 4; e++) acc[f][g][e] = 0.f;

    int nCh = K >> 6;
    issue_chunk(Ah, W, m0, n0, K, 0, sbase + SOFF_STAGE, tid);
    if (nCh > 1)
        issue_chunk(Ah, W, m0, n0, K, 1, sbase + SOFF_STAGE + STAGE_B, tid);

    int lane15 = lane & 15, laneHalf = lane >> 4;
    int grp = lane >> 2, tig = lane & 3;

    int stage = 0;
    for (int c = 0; c < nCh; c++) {
        if (c + 1 < nCh)
            asm volatile("cp.async.wait_group 1;" ::: "memory");
        else
            asm volatile("cp.async.wait_group 0;" ::: "memory");
        __syncthreads();

        uint32_t base = sbase + SOFF_STAGE + stage * STAGE_B;
        #pragma unroll
        for (int ks = 0; ks < 4; ks++) {
            uint32_t af[4][4];
            int koffA = ks * 16 + laneHalf * 8;
            #pragma unroll
            for (int f = 0; f < 4; f++) {
                int row = wm * 64 + f * 16 + lane15;
                ldmx4(af[f], base + row * (RSTR * 2) + koffA * 2);
            }
            #pragma unroll
            for (int g = 0; g < 4; g++) {
                int n = wn * 32 + g * 8 + grp;
                uint32_t bd = base + PLANE + n * (RSTR * 2)
                            + (ks * 16 + tig * 2) * 2;
                uint32_t w0 = lds32(bd), w1 = lds32(bd + 16);
                #pragma unroll
                for (int f = 0; f < 4; f++)
                    mmaf16(acc[f][g], af[f], w0, w1);
            }
        }
        __syncthreads();
        if (c + 2 < nCh)
            issue_chunk(Ah, W, m0, n0, K, c + 2,
                        sbase + SOFF_STAGE + stage * STAGE_B, tid);
        stage ^= 1;
    }

    // ---- stage lora-B slice into SMEM (overlays stages) ----
    float* Bs = (float*)(smem + SOFF_STAGE);
    for (int i = tid; i < 4096; i += 256) {
        int a   = i >> 9;
        int rem = i & 511;
        int nl  = rem >> 2;
        int sg  = rem & 3;
        float4 v = *(const float4*)(Bl + ((size_t)a * N + n0 + nl) * LR + sg * 4);
        *(float4*)(Bs + ((size_t)((a << 7) + nl)) * LR + sg * 4) = v;
    }
    __syncthreads();

    const float* biasS = (const float*)(smem + SOFF_BIAS);
    #pragma unroll
    for (int f = 0; f < 4; f++) {
        int r0 = m0 + wm * 64 + f * 16 + grp;
        int r1 = r0 + 8;
        int a0 = map[r0], a1 = map[r1];
        float u0[16], u1[16];
        {
            const float4* p0 = (const float4*)(u + (size_t)r0 * LR);
            const float4* p1 = (const float4*)(u + (size_t)r1 * LR);
            #pragma unroll
            for (int q = 0; q < 4; q++) {
                float4 v0 = p0[q], v1 = p1[q];
                u0[q*4+0]=v0.x; u0[q*4+1]=v0.y; u0[q*4+2]=v0.z; u0[q*4+3]=v0.w;
                u1[q*4+0]=v1.x; u1[q*4+1]=v1.y; u1[q*4+2]=v1.z; u1[q*4+3]=v1.w;
            }
        }
        #pragma unroll
        for (int g = 0; g < 4; g++) {
            int nl = wn * 32 + g * 8 + tig * 2;
            float v00 = acc[f][g][0] + biasS[nl]
                      + dot16(u0, Bs + ((size_t)((a0 << 7) + nl)) * LR);
            float v01 = acc[f][g][1] + biasS[nl + 1]
                      + dot16(u0, Bs + ((size_t)((a0 << 7) + nl + 1)) * LR);
            float v10 = acc[f][g][2] + biasS[nl]
                      + dot16(u1, Bs + ((size_t)((a1 << 7) + nl)) * LR);
            float v11 = acc[f][g][3] + biasS[nl + 1]
                      + dot16(u1, Bs + ((size_t)((a1 << 7) + nl + 1)) * LR);
            size_t o0 = (size_t)r0 * N + n0 + nl;
            size_t o1 = (size_t)r1 * N + n0 + nl;
            if (resid) {
                float2 q0 = *(const float2*)(resid + o0);
                float2 q1 = *(const float2*)(resid + o1);
                v00 += q0.x; v01 += q0.y; v10 += q1.x; v11 += q1.y;
            }
            if (relu) {
                v00 = fmaxf(v00, 0.f); v01 = fmaxf(v01, 0.f);
                v10 = fmaxf(v10, 0.f); v11 = fmaxf(v11, 0.f);
            }
            if (C) {
                *(float2*)(C + o0) = make_float2(v00, v01);
                *(float2*)(C + o1) = make_float2(v10, v11);
            }
            if (hOut) {
                pack2h(v00, v01, hOut + o0);
                pack2h(v10, v11, hOut + o1);
            }
        }
    }
}

// ================= attention: flash online-softmax, TQ=32, all-MMA ============
#define TQ 32
// smem: qh 32x136h (8704) | kc 64x136h (17408) | vc 64x136h (17408)
//       scb 32x64 f (8192) | pt 64x40h (5120) | m/l/f 3x32 f (384)
#define ATT_QH  0
#define ATT_KC  8704
#define ATT_VC  26112
#define ATT_SCB 43520
#define ATT_PT  51712
#define ATT_M   56832
#define ATT_L   56960
#define ATT_F   57088
#define ATTN_SMEM 57216

__global__ void __launch_bounds__(256, 2)
attn7_kernel(const __half* __restrict__ qkvh, __half* __restrict__ hp) {
    extern __shared__ __align__(1024) char smemA[];
    __half* qh  = (__half*)(smemA + ATT_QH);
    float*  scb = (float*)(smemA + ATT_SCB);
    __half* pt  = (__half*)(smemA + ATT_PT);
    float*  mrow = (float*)(smemA + ATT_M);
    float*  lrow = (float*)(smemA + ATT_L);
    float*  frow = (float*)(smemA + ATT_F);
    int qt = blockIdx.x, h = blockIdx.y, bb = blockIdx.z;
    int q0 = qt * TQ;
    int tid = threadIdx.x, lane = tid & 31, warp = tid >> 5;
    int lane15 = lane & 15, laneHalf = lane >> 4;
    int grp = lane >> 2, tig = lane & 3;
    const size_t base = (size_t)bb * SEQ * H3;
    const float scale = 0.08838834764831845f;
    uint32_t qaddr = smem_u32(qh);
    uint32_t kcaddr = smem_u32(smemA + ATT_KC);
    uint32_t vcaddr = smem_u32(smemA + ATT_VC);
    uint32_t ptaddr = smem_u32(pt);

    if (tid < TQ) { mrow[tid] = -1e30f; lrow[tid] = 0.f; }

    // stage Q tile via cp.async (32 rows x 16 segs = 2 per thread)
    #pragma unroll
    for (int p = 0; p < 2; p++) {
        int idx = tid + p * 256;
        int r = idx >> 4, seg = idx & 15;
        cpa16(qaddr + r * 272 + seg * 16,
              qkvh + base + (size_t)(q0 + r) * H3 + h * HD + seg * 8);
    }
    cpa_commit();
    asm volatile("cp.async.wait_group 0;" ::: "memory");
    __syncthreads();

    float acc[2][2][4];
    #pragma unroll
    for (int mt = 0; mt < 2; mt++)
        #pragma unroll
        for (int hh = 0; hh < 2; hh++)
            #pragma unroll
            for (int e = 0; e < 4; e++) acc[mt][hh][e] = 0.f;
    int nkmax = q0 + TQ;

    for (int kb = 0; kb < nkmax; kb += 64) {
        __syncthreads();     // kc/vc/pt reuse: prior chunk's MMAs complete
        #pragma unroll
        for (int p = 0; p < 4; p++) {
            int idx = tid + p * 256;
            int r = idx >> 4, seg = idx & 15;
            uint32_t off = (uint32_t)(r * 272 + seg * 16);
            if (kb + r < nkmax) {
                const __half* src = qkvh + base + (size_t)(kb + r) * H3
                                  + h * HD + seg * 8;
                cpa16(kcaddr + off, src + DIM);
                cpa16(vcaddr + off, src + 2 * DIM);
            } else {
                *(uint4*)(smemA + ATT_VC + off) = make_uint4(0, 0, 0, 0);
            }
        }
        cpa_commit();
        asm volatile("cp.async.wait_group 0;" ::: "memory");
        __syncthreads();

        // scores: warp owns 8 keys; two q-tiles (mt)
        #pragma unroll
        for (int mt = 0; mt < 2; mt++) {
            float sacc[4] = {0.f, 0.f, 0.f, 0.f};
            #pragma unroll
            for (int ks = 0; ks < 8; ks++) {
                uint32_t qf[4];
                ldmx4(qf, qaddr + (mt * 16 + lane15) * 272
                          + (ks * 16 + laneHalf * 8) * 2);
                uint32_t bd = kcaddr + (warp * 8 + grp) * 272
                            + (ks * 16 + tig * 2) * 2;
                uint32_t w0 = lds32(bd), w1 = lds32(bd + 16);
                mmaf16(sacc, qf, w0, w1);
            }
            int kl = warp * 8 + tig * 2;
            int kcol = kb + kl;
            int r0 = mt * 16 + grp, r1 = r0 + 8;
            scb[r0 * 64 + kl]     = (kcol     <= q0 + r0) ? sacc[0] * scale : -1e30f;
            scb[r0 * 64 + kl + 1] = (kcol + 1 <= q0 + r0) ? sacc[1] * scale : -1e30f;
            scb[r1 * 64 + kl]     = (kcol     <= q0 + r1) ? sacc[2] * scale : -1e30f;
            scb[r1 * 64 + kl + 1] = (kcol + 1 <= q0 + r1) ? sacc[3] * scale : -1e30f;
        }
        __syncthreads();

        // online softmax: warp handles rows warp + 8*rr (4 rows)
        #pragma unroll
        for (int rr = 0; rr < 4; rr++) {
            int r = warp + rr * 8;
            float s0 = scb[r * 64 + lane], s1 = scb[r * 64 + lane + 32];
            float mc = fmaxf(s0, s1);
            #pragma unroll
            for (int o = 16; o; o >>= 1)
                mc = fmaxf(mc, __shfl_xor_sync(0xffffffffu, mc, o));
            float mold = mrow[r];
            float newm = fmaxf(mold, mc);
            float p0 = __expf(s0 - newm), p1 = __expf(s1 - newm);
            pt[lane * 40 + r]        = __float2half(p0);
            pt[(lane + 32) * 40 + r] = __float2half(p1);
            float ls = p0 + p1;
            #pragma unroll
            for (int o = 16; o; o >>= 1) ls += __shfl_xor_sync(0xffffffffu, ls, o);
            if (!lane) {
                float f = __expf(mold - newm);
                lrow[r] = lrow[r] * f + ls;
                mrow[r] = newm;
                frow[r] = f;
            }
        }
        __syncthreads();

        // rescale + PV MMAs: warp owns dims [warp*16, +16)
        #pragma unroll
        for (int mt = 0; mt < 2; mt++) {
            float f0 = frow[mt * 16 + grp], f1 = frow[mt * 16 + grp + 8];
            #pragma unroll
            for (int hh = 0; hh < 2; hh++) {
                acc[mt][hh][0] *= f0; acc[mt][hh][1] *= f0;
                acc[mt][hh][2] *= f1; acc[mt][hh][3] *= f1;
            }
        }
        #pragma unroll
        for (int ks = 0; ks < 4; ks++) {
            uint32_t tB[4];
            ldmx4t(tB, vcaddr + (ks * 16 + lane15) * 272
                       + (warp * 16 + laneHalf * 8) * 2);
            #pragma unroll
            for (int mt = 0; mt < 2; mt++) {
                uint32_t tA[4];
                ldmx4t(tA, ptaddr + (ks * 16 + lane15) * 80
                           + (mt * 16 + laneHalf * 8) * 2);
                uint32_t a[4] = { tA[0], tA[2], tA[1], tA[3] };
                mmaf16(acc[mt][0], a, tB[0], tB[1]);
                mmaf16(acc[mt][1], a, tB[2], tB[3]);
            }
        }
    }
    __syncthreads();

    // epilogue
    #pragma unroll
    for (int mt = 0; mt < 2; mt++) {
        float iv0 = 1.f / lrow[mt * 16 + grp];
        float iv1 = 1.f / lrow[mt * 16 + grp + 8];
        int dbase = warp * 16 + tig * 2;
        size_t o00 = ((size_t)bb * SEQ + q0 + mt * 16 + grp) * DIM + h * HD + dbase;
        size_t o10 = ((size_t)bb * SEQ + q0 + mt * 16 + grp + 8) * DIM + h * HD + dbase;
        pack2h(acc[mt][0][0] * iv0, acc[mt][0][1] * iv0, hp + o00);
        pack2h(acc[mt][0][2] * iv1, acc[mt][0][3] * iv1, hp + o10);
        pack2h(acc[mt][1][0] * iv0, acc[mt][1][1] * iv0, hp + o00 + 8);
        pack2h(acc[mt][1][2] * iv1, acc[mt][1][3] * iv1, hp + o10 + 8);
    }
}

// ---------------- launch ------------------------------------------------------
extern "C" void kernel_launch(void* const* d_in, const int* in_sizes, int n_in,
                              void* d_out, int out_size) {
    const float* x    = (const float*)d_in[0];
    const int*   map  = (const int*)  d_in[1];
    const float* Wqkv = (const float*)d_in[2];
    const float* bqkv = (const float*)d_in[3];
    const float* Wout = (const float*)d_in[4];
    const float* bout = (const float*)d_in[5];
    const float* Wfc1 = (const float*)d_in[6];
    const float* bfc1 = (const float*)d_in[7];
    const float* Wfc2 = (const float*)d_in[8];
    const float* bfc2 = (const float*)d_in[9];
    const float* ln1g = (const float*)d_in[10];
    const float* ln1b = (const float*)d_in[11];
    const float* ln2g = (const float*)d_in[12];
    const float* ln2b = (const float*)d_in[13];
    const float* Aqkv = (const float*)d_in[14];
    const float* Bqkv = (const float*)d_in[15];
    const float* Aout = (const float*)d_in[16];
    const float* Bout = (const float*)d_in[17];
    const float* Afc1 = (const float*)d_in[18];
    const float* Bfc1 = (const float*)d_in[19];
    const float* Afc2 = (const float*)d_in[20];
    const float* Bfc2 = (const float*)d_in[21];
    float* out = (float*)d_out;

    float *p_res2, *p_u;
    __half *p_Wh, *p_AS, *p_AL;
    cudaGetSymbolAddress((void**)&p_res2, g_res2);
    cudaGetSymbolAddress((void**)&p_u,    g_u);
    cudaGetSymbolAddress((void**)&p_Wh,   g_Wh);
    cudaGetSymbolAddress((void**)&p_AS,   g_AS);
    cudaGetSymbolAddress((void**)&p_AL,   g_AL);
    __half* p_qkvh = p_AL;   // fp16 qkv plane reuses the large activation plane

    cudaFuncSetAttribute(tc_gemm, cudaFuncAttributeMaxDynamicSharedMemorySize, SMEM_G);
    cudaFuncSetAttribute(attn7_kernel, cudaFuncAttributeMaxDynamicSharedMemorySize,
                         ATTN_SMEM);
    cudaFuncSetAttribute(lora_u_smem_h, cudaFuncAttributeMaxDynamicSharedMemorySize,
                         FFN_D * 4);

    // ---- all weights -> fp16 (one launch) ----
    cvt_all<<<8192, 256>>>(Wqkv, Wout, Wfc1, Wfc2, p_Wh);

    // ---- attention block ----
    ln_fused<<<NT, 256>>>(x, ln1g, ln1b, Aqkv, map, p_AS, p_u);
    tc_gemm<<<dim3(H3 / BN, NT / BM), 256, SMEM_G>>>(
        p_AS, p_Wh + WOFF_QKV, bqkv, p_u, Bqkv, map,
        nullptr, nullptr, p_qkvh, H3, DIM, 0);
    attn7_kernel<<<dim3(SEQ / TQ, NH, 2), 256, ATTN_SMEM>>>(p_qkvh, p_AS);
    lora_u_smem_h<<<NT, 256, DIM * 4>>>(p_AS, Aout, map, p_u, DIM);
    tc_gemm<<<dim3(DIM / BN, NT / BM), 256, SMEM_G>>>(
        p_AS, p_Wh + WOFF_OUT, bout, p_u, Bout, map,
        x, p_res2, nullptr, DIM, DIM, 0);
    // ---- FFN block ----
    ln_fused<<<NT, 256>>>(p_res2, ln2g, ln2b, Afc1, map, p_AS, p_u);
    tc_gemm<<<dim3(FFN_D / BN, NT / BM), 256, SMEM_G>>>(
        p_AS, p_Wh + WOFF_FC1, bfc1, p_u, Bfc1, map,
        nullptr, nullptr, p_AL, FFN_D, DIM, 1);
    lora_u_smem_h<<<NT, 256, FFN_D * 4>>>(p_AL, Afc2, map, p_u, FFN_D);
    tc_gemm<<<dim3(DIM / BN, NT / BM), 256, SMEM_G>>>(
        p_AL, p_Wh + WOFF_FC2, bfc2, p_u, Bfc2, map,
        p_res2, out, nullptr, DIM, FFN_D, 0);
}